// round 11
// baseline (speedup 1.0000x reference)
#include <cuda_runtime.h>
#include <cuda_fp16.h>
#include <math.h>
#include <stdint.h>

#define Bsz 8
#define Ssz 1024
#define Dsz 512
#define Hsz 8
#define DHsz 64
#define FFsz 1024
#define NPOS 64          // 2*SPAN
#define NROWS (Bsz*Ssz)  // 8192

// ---------------- scratch (device globals; no allocation allowed) ------------
__device__ float g_xn  [Bsz*Ssz*Dsz];
__device__ float g_conv[Bsz*Ssz*Dsz];
__device__ float g_x1  [Bsz*Ssz*Dsz];
__device__ float g_x2  [Bsz*Ssz*Dsz];
__device__ float g_q   [Bsz*Ssz*Dsz];
__device__ float g_k   [Bsz*Ssz*Dsz];
__device__ float g_v   [Bsz*Ssz*Dsz];
__device__ float g_vt  [Bsz*Ssz*Dsz];   // [B, D, S], S pre-permuted within 8-groups
__device__ float g_ctx [Bsz*Ssz*Dsz];
__device__ float g_posk[NPOS*Dsz];
__device__ float g_posq[NPOS*Dsz];
__device__ float g_c2p [Bsz*Hsz*Ssz*NPOS];
__device__ float g_p2c [Bsz*Hsz*Ssz*NPOS];
__device__ float g_ff  [Bsz*Ssz*FFsz];
__device__ int   g_lut [2*Ssz];

// ---------------- relative-position bucket LUT --------------------------------
__global__ void build_lut_kernel(int* __restrict__ lut) {
    int t = blockIdx.x * blockDim.x + threadIdx.x;
    if (t >= 2*Ssz - 1) return;
    int rel = t - (Ssz - 1);   // i - j
    const int mid = 16;        // BUCKETS/2
    int bucket;
    if (rel > -mid && rel < mid) {
        bucket = rel;
    } else {
        float absp = fabsf((float)rel);
        if (absp <= (float)mid) {
            bucket = rel;
        } else {
            float logp = ceilf(logf(absp / 16.0f) / logf(127.0f / 16.0f) * 15.0f) + 16.0f;
            bucket = (rel > 0 ? 1 : -1) * (int)logp;
        }
    }
    int idx = bucket + 32;
    idx = min(max(idx, 0), 63);
    lut[t] = idx;
}

// ---------------- LayerNorm (D=512, one block per row) ------------------------
__global__ void layernorm_kernel(const float* __restrict__ x,
                                 const float* __restrict__ g,
                                 const float* __restrict__ bb,
                                 float* __restrict__ out) {
    const float* xr = x + (size_t)blockIdx.x * Dsz;
    float* orow = out + (size_t)blockIdx.x * Dsz;
    int tid = threadIdx.x;  // 256
    float v0 = xr[tid], v1 = xr[tid + 256];
    float s = v0 + v1, ss = v0 * v0 + v1 * v1;
    __shared__ float r1[8], r2[8];
    #pragma unroll
    for (int o = 16; o; o >>= 1) {
        s  += __shfl_xor_sync(0xffffffffu, s, o);
        ss += __shfl_xor_sync(0xffffffffu, ss, o);
    }
    if ((tid & 31) == 0) { r1[tid >> 5] = s; r2[tid >> 5] = ss; }
    __syncthreads();
    float S1 = 0.f, S2 = 0.f;
    #pragma unroll
    for (int i = 0; i < 8; i++) { S1 += r1[i]; S2 += r2[i]; }
    float mean = S1 * (1.0f / Dsz);
    float var  = S2 * (1.0f / Dsz) - mean * mean;
    float rs = rsqrtf(var + 1e-5f);
    orow[tid]       = (v0 - mean) * rs * g[tid]       + bb[tid];
    orow[tid + 256] = (v1 - mean) * rs * g[tid + 256] + bb[tid + 256];
}

// ---------------- depthwise conv (K=3 along S) + bias + SiLU ------------------
__global__ void dwconv_silu_kernel(const float* __restrict__ xn,
                                   const float* __restrict__ w,
                                   const float* __restrict__ bias,
                                   float* __restrict__ out) {
    size_t idx = (size_t)blockIdx.x * blockDim.x + threadIdx.x;
    if (idx >= (size_t)Bsz * Ssz * Dsz) return;
    int d = (int)(idx % Dsz);
    int s = (int)((idx / Dsz) % Ssz);
    const float* base = xn + idx;
    float w0 = w[d * 3 + 0], w1 = w[d * 3 + 1], w2 = w[d * 3 + 2];
    float acc = bias[d] + base[0] * w1;
    if (s > 0)        acc += base[-Dsz] * w0;
    if (s < Ssz - 1)  acc += base[ Dsz] * w2;
    out[idx] = acc / (1.0f + expf(-acc));  // silu
}

// ---------------- V transpose: [B,S,D] -> [B,D,S] with j permutation -----------
__global__ void transpose_v_kernel(const float* __restrict__ v, float* __restrict__ vt) {
    __shared__ float tile[32][33];
    int b = blockIdx.z;
    int s0 = blockIdx.x * 32, d0 = blockIdx.y * 32;
    int tx = threadIdx.x, ty = threadIdx.y;  // 32 x 8
    #pragma unroll
    for (int j = 0; j < 32; j += 8)
        tile[ty + j][tx] = v[((size_t)b * Ssz + s0 + ty + j) * Dsz + d0 + tx];
    __syncthreads();
    int sl = tx & 7;
    int sp = (s0 + (tx & ~7)) | ((sl & 1) ? (4 + (sl >> 1)) : (sl >> 1));
    #pragma unroll
    for (int j = 0; j < 32; j += 8)
        vt[((size_t)b * Dsz + d0 + ty + j) * Ssz + sp] = tile[tx][ty + j];
}

// ---------------- mma.tf32 + ldmatrix helpers ----------------------------------
__device__ __forceinline__ void mma_tf32(float c[4], const uint32_t a[4], const uint32_t b[2]) {
    asm volatile(
        "mma.sync.aligned.m16n8k8.row.col.f32.tf32.tf32.f32 "
        "{%0,%1,%2,%3}, {%4,%5,%6,%7}, {%8,%9}, {%0,%1,%2,%3};"
        : "+f"(c[0]), "+f"(c[1]), "+f"(c[2]), "+f"(c[3])
        : "r"(a[0]), "r"(a[1]), "r"(a[2]), "r"(a[3]), "r"(b[0]), "r"(b[1]));
}

__device__ __forceinline__ void ldsm_x4(uint32_t r[4], uint32_t addr) {
    asm volatile("ldmatrix.sync.aligned.m8n8.x4.shared.b16 {%0,%1,%2,%3}, [%4];"
                 : "=r"(r[0]), "=r"(r[1]), "=r"(r[2]), "=r"(r[3]) : "r"(addr));
}

#define CP_ASYNC16(dst_u32, src_ptr) \
    asm volatile("cp.async.ca.shared.global [%0], [%1], 16;" :: "r"(dst_u32), "l"(src_ptr))
#define CP_COMMIT() asm volatile("cp.async.commit_group;")
#define CP_WAIT2()  asm volatile("cp.async.wait_group 2;")
#define CP_WAIT1()  asm volatile("cp.async.wait_group 1;")
#define CP_WAIT0()  asm volatile("cp.async.wait_group 0;")

// ---------------- tensor-core TN GEMM (128xCN tiles, 4-stage, 1 barrier/iter) --
// (R9 configuration — known best)
#define SSTRIDE 20
#define NSTAGE 4
#define GEMM_SMEM(CNv) (NSTAGE * (128 + (CNv)) * SSTRIDE * 4)

template<int CN, int EPI, int MODE>
__global__ void __launch_bounds__(256, 2) gemm_mma_kernel(
    const float* __restrict__ A0, int lda,
    const float* __restrict__ W0, int ldw,
    const float* __restrict__ bias0, const float* __restrict__ res,
    float* __restrict__ C0, int ldc, int K,
    const float* __restrict__ Aa, const float* __restrict__ Wa,
    const float* __restrict__ Wb2, const float* __restrict__ ba,
    const float* __restrict__ bb2, float* __restrict__ Ca, float* __restrict__ Cb)
{
    constexpr int NWN = CN / 32;     // warps along N
    constexpr int NWM = 8 / NWN;     // warps along M
    constexpr int MT  = 8 / NWM;     // m16 tiles per warp

    extern __shared__ float smem[];
    float* As = smem;
    float* Ws = smem + NSTAGE * 128 * SSTRIDE;

    const int tid  = threadIdx.x;
    const int wid  = tid >> 5, lane = tid & 31;
    const int g    = lane >> 2, tg = lane & 3;
    const int wm   = wid % NWM, wn = wid / NWM;

    const int z = blockIdx.z;
    const float* A = A0; const float* W = W0; float* C = C0;
    const float* bias = bias0;
    if (MODE == 4) {
        W    = (z == 0) ? W0 : (z == 1 ? Wa : Wb2);
        bias = (z == 0) ? bias0 : (z == 1 ? ba : bb2);
        C    = (z == 0) ? C0 : (z == 1 ? Ca : Cb);
    }

    const int m_cta = blockIdx.y * 128, n_cta = blockIdx.x * CN;

    const uint32_t sA = (uint32_t)__cvta_generic_to_shared(As);
    const uint32_t sW = (uint32_t)__cvta_generic_to_shared(Ws);

    const int qd = (tid & 3) * 4;
    const int rr = tid >> 2;

    auto fetch = [&](int t, int buf) {
        int k0 = t * 16;
        #pragma unroll
        for (int r = 0; r < 2; r++) {
            int row = rr + 64 * r;
            uint32_t d = sA + (uint32_t)(buf * 128 * SSTRIDE + row * SSTRIDE + qd) * 4u;
            CP_ASYNC16(d, A + (size_t)(m_cta + row) * lda + k0 + qd);
        }
        #pragma unroll
        for (int r = 0; r < CN / 64; r++) {
            int row = rr + 64 * r;
            uint32_t d = sW + (uint32_t)(buf * CN * SSTRIDE + row * SSTRIDE + qd) * 4u;
            CP_ASYNC16(d, W + (size_t)(n_cta + row) * ldw + k0 + qd);
        }
        CP_COMMIT();
    };

    const int lq = lane >> 3, lr = lane & 7;
    const int aoff = ((lq & 1) * 8 + lr) * SSTRIDE + (lq >> 1) * 4;
    const int boff = ((lq >> 1) * 8 + lr) * SSTRIDE + (lq & 1) * 4;

    float acc[MT][4][4] = {};

    const int T = K / 16;
    fetch(0, 0);
    fetch(1, 1);
    if (T > 2) fetch(2, 2);
    for (int it = 0; it < T; it++) {
        const int buf = it & (NSTAGE - 1);
        if (it < T - 2)       { CP_WAIT2(); }
        else if (it == T - 2) { CP_WAIT1(); }
        else                  { CP_WAIT0(); }
        __syncthreads();
        if (it + 3 < T) fetch(it + 3, (it + 3) & (NSTAGE - 1));

        const uint32_t bA = sA + (uint32_t)(buf * 128 * SSTRIDE) * 4u;
        const uint32_t bW = sW + (uint32_t)(buf * CN  * SSTRIDE) * 4u;
        #pragma unroll
        for (int ks = 0; ks < 2; ks++) {
            const int kk = ks * 8;
            uint32_t af[MT][4];
            #pragma unroll
            for (int im = 0; im < MT; im++)
                ldsm_x4(af[im], bA + (uint32_t)((wm * MT * 16 + im * 16) * SSTRIDE + aoff + kk) * 4u);
            uint32_t bf[2][4];
            #pragma unroll
            for (int ip = 0; ip < 2; ip++)
                ldsm_x4(bf[ip], bW + (uint32_t)((wn * 32 + ip * 16) * SSTRIDE + boff + kk) * 4u);
            #pragma unroll
            for (int im = 0; im < MT; im++)
                #pragma unroll
                for (int in = 0; in < 4; in++)
                    mma_tf32(acc[im][in], af[im], &bf[in >> 1][(in & 1) * 2]);
        }
    }

    #pragma unroll
    for (int im = 0; im < MT; im++) {
        int mrow0 = m_cta + wm * MT * 16 + im * 16 + g;
        #pragma unroll
        for (int in = 0; in < 4; in++) {
            int ncol0 = n_cta + wn * 32 + in * 8 + tg * 2;
            #pragma unroll
            for (int e = 0; e < 4; e++) {
                int m = mrow0 + ((e >= 2) ? 8 : 0);
                int n = ncol0 + (e & 1);
                float vv = acc[im][in][e];
                if (EPI == 1 || EPI == 2 || EPI == 3) vv += bias[n];
                if (EPI == 2) vv += res[(size_t)m * ldc + n];
                if (EPI == 3) vv = vv / (1.0f + expf(-vv));
                C[(size_t)m * ldc + n] = vv;
            }
        }
    }
}

// ---------------- mma GEMM for pos projections (small N=64, K=64) --------------
template<int CN>
__global__ void __launch_bounds__(256, 2) gemm_pos_kernel(
    const float* __restrict__ A0,
    const float* __restrict__ W0,
    float* __restrict__ C0,
    const float* __restrict__ Aa, const float* __restrict__ Wa,
    float* __restrict__ Ca)
{
    constexpr int NWN = CN / 32;
    constexpr int NWM = 8 / NWN;
    constexpr int MT  = 8 / NWM;
    const int K = DHsz;

    extern __shared__ float smem[];
    float* As = smem;
    float* Ws = smem + NSTAGE * 128 * SSTRIDE;

    const int tid  = threadIdx.x;
    const int wid  = tid >> 5, lane = tid & 31;
    const int g    = lane >> 2, tg = lane & 3;
    const int wm   = wid % NWM, wn = wid / NWM;

    int zz = blockIdx.z & 63, sel = blockIdx.z >> 6;
    int bb = zz >> 3, hh = zz & 7;
    const float* A = (sel ? Aa : A0) + (size_t)bb * Ssz * Dsz + hh * DHsz;
    const float* W = (sel ? Wa : W0) + hh * DHsz;
    float* C = (sel ? Ca : C0) + (size_t)zz * Ssz * NPOS;

    const int m_cta = blockIdx.y * 128;

    const uint32_t sA = (uint32_t)__cvta_generic_to_shared(As);
    const uint32_t sW = (uint32_t)__cvta_generic_to_shared(Ws);
    const int qd = (tid & 3) * 4;
    const int rr = tid >> 2;

    auto fetch = [&](int t, int buf) {
        int k0 = t * 16;
        #pragma unroll
        for (int r = 0; r < 2; r++) {
            int row = rr + 64 * r;
            CP_ASYNC16(sA + (uint32_t)(buf * 128 * SSTRIDE + row * SSTRIDE + qd) * 4u,
                       A + (size_t)(m_cta + row) * Dsz + k0 + qd);
        }
        if (rr < CN)
            CP_ASYNC16(sW + (uint32_t)(buf * CN * SSTRIDE + rr * SSTRIDE + qd) * 4u,
                       W + (size_t)rr * Dsz + k0 + qd);
        CP_COMMIT();
    };

    const int lq = lane >> 3, lr = lane & 7;
    const int aoff = ((lq & 1) * 8 + lr) * SSTRIDE + (lq >> 1) * 4;
    const int boff = ((lq >> 1) * 8 + lr) * SSTRIDE + (lq & 1) * 4;

    float acc[MT][4][4] = {};
    const int T = K / 16;   // 4
    fetch(0, 0); fetch(1, 1); if (T > 2) fetch(2, 2);
    for (int it = 0; it < T; it++) {
        const int buf = it & (NSTAGE - 1);
        if (it < T - 2)       { CP_WAIT2(); }
        else if (it == T - 2) { CP_WAIT1(); }
        else                  { CP_WAIT0(); }
        __syncthreads();
        if (it + 3 < T) fetch(it + 3, (it + 3) & (NSTAGE - 1));
        const uint32_t bA = sA + (uint32_t)(buf * 128 * SSTRIDE) * 4u;
        const uint32_t bW = sW + (uint32_t)(buf * CN  * SSTRIDE) * 4u;
        #pragma unroll
        for (int ks = 0; ks < 2; ks++) {
            const int kk = ks * 8;
            uint32_t af[MT][4];
            #pragma unroll
            for (int im = 0; im < MT; im++)
                ldsm_x4(af[im], bA + (uint32_t)((wm * MT * 16 + im * 16) * SSTRIDE + aoff + kk) * 4u);
            uint32_t bf[2][4];
            #pragma unroll
            for (int ip = 0; ip < 2; ip++)
                ldsm_x4(bf[ip], bW + (uint32_t)((wn * 32 + ip * 16) * SSTRIDE + boff + kk) * 4u);
            #pragma unroll
            for (int im = 0; im < MT; im++)
                #pragma unroll
                for (int in = 0; in < 4; in++)
                    mma_tf32(acc[im][in], af[im], &bf[in >> 1][(in & 1) * 2]);
        }
    }

    #pragma unroll
    for (int im = 0; im < MT; im++) {
        int mrow0 = m_cta + wm * MT * 16 + im * 16 + g;
        #pragma unroll
        for (int in = 0; in < 4; in++) {
            int ncol0 = wn * 32 + in * 8 + tg * 2;
            #pragma unroll
            for (int e = 0; e < 4; e++) {
                int m = mrow0 + ((e >= 2) ? 8 : 0);
                int nn = ncol0 + (e & 1);
                C[(size_t)m * NPOS + nn] = acc[im][in][e];
            }
        }
    }
}

// ---------------- small SIMT GEMM (pos-emb projections, M=64, merged) ----------
#define TK 16
#define TPAD 68
__global__ void gemm_tn_small_kernel(const float* __restrict__ A, int lda,
                                     const float* __restrict__ W0, int ldw,
                                     const float* __restrict__ b0,
                                     float* __restrict__ C0,
                                     const float* __restrict__ W1,
                                     const float* __restrict__ b1,
                                     float* __restrict__ C1, int ldc, int Kd) {
    const float* W   = blockIdx.z ? W1 : W0;
    const float* bias= blockIdx.z ? b1 : b0;
    float* C         = blockIdx.z ? C1 : C0;
    int m0 = blockIdx.y * 64, n0 = blockIdx.x * 64;
    __shared__ float As[TK][TPAD];
    __shared__ float Ws2[TK][TPAD];
    const int tid = threadIdx.x;
    const int tx = tid & 15, ty = tid >> 4;
    const int lk = tid & 15, lm = tid >> 4;
    float acc[4][4] = {};
    for (int k0 = 0; k0 < Kd; k0 += TK) {
        #pragma unroll
        for (int r = 0; r < 4; r++) {
            As[lk][lm + 16 * r]  = A[(size_t)(m0 + lm + 16 * r) * lda + k0 + lk];
            Ws2[lk][lm + 16 * r] = W[(size_t)(n0 + lm + 16 * r) * ldw + k0 + lk];
        }
        __syncthreads();
        #pragma unroll
        for (int kk = 0; kk < TK; kk++) {
            float4 a = *(const float4*)&As[kk][ty * 4];
            float4 b = *(const float4*)&Ws2[kk][tx * 4];
            float av[4] = {a.x, a.y, a.z, a.w};
            float bv[4] = {b.x, b.y, b.z, b.w};
            #pragma unroll
            for (int i = 0; i < 4; i++)
                #pragma unroll
                for (int j = 0; j < 4; j++)
                    acc[i][j] += av[i] * bv[j];
        }
        __syncthreads();
    }
    #pragma unroll
    for (int i = 0; i < 4; i++) {
        int m = m0 + ty * 4 + i;
        #pragma unroll
        for (int j = 0; j < 4; j++) {
            int n = n0 + tx * 4 + j;
            C[(size_t)m * ldc + n] = acc[i][j] + bias[n];
        }
    }
}

// =========================== fused flash attention =============================
// R9 structure (register P, fused KV double-buffer, 1 barrier/iter) with the
// softmax moved to log2 domain and exp computed as f16x2 h2exp2 (halves MUFU).
#define FST 68
#define FA_K(buf) ((buf) * 64 * FST)
#define FA_V(buf) (2 * 64 * FST + (buf) * 64 * FST)
#define FA_Q      (4 * 64 * FST)
#define FA_LUT    (4 * 64 * FST + 128 * FST)
#define FA_SMEM   ((4*64*FST + 128*FST + 2048) * 4)

__global__ void __launch_bounds__(256, 2) flash_attn_kernel(
    const float* __restrict__ qg, const float* __restrict__ kg,
    const float* __restrict__ vt,
    const float* __restrict__ c2p, const float* __restrict__ p2c,
    const int* __restrict__ lut, float* __restrict__ ctx)
{
    extern __shared__ float sm[];
    int* lut_s = (int*)(sm + FA_LUT);

    const int tid = threadIdx.x, w = tid >> 5, lane = tid & 31;
    const int g = lane >> 2, tg = lane & 3;
    const int z = blockIdx.z, bb = z >> 3, hh = z & 7;
    const int i0 = blockIdx.x * 128;

    const float* c2pz = c2p + (size_t)z * Ssz * NPOS;
    const float* p2cz = p2c + (size_t)z * Ssz * NPOS;

    const uint32_t sb = (uint32_t)__cvta_generic_to_shared(sm);

    #pragma unroll
    for (int t = 0; t < 8; t++) {
        int idx = tid + 256 * t;
        if (idx < 2 * Ssz - 1) lut_s[idx] = lut[idx];
    }

    auto loadKV = [&](int jt, int buf) {
        int j0 = jt * 64;
        #pragma unroll
        for (int c = 0; c < 4; c++) {
            int id = tid * 4 + c;
            int row = id >> 4, fcol = (id & 15) * 4;
            CP_ASYNC16(sb + (uint32_t)(FA_K(buf) + row * FST + fcol) * 4u,
                       kg + ((size_t)bb * Ssz + j0 + row) * Dsz + hh * DHsz + fcol);
        }
        #pragma unroll
        for (int c = 0; c < 4; c++) {
            int id = tid * 4 + c;
            int row = id >> 4, fcol = (id & 15) * 4;
            CP_ASYNC16(sb + (uint32_t)(FA_V(buf) + row * FST + fcol) * 4u,
                       vt + ((size_t)bb * Dsz + hh * DHsz + row) * Ssz + j0 + fcol);
        }
        CP_COMMIT();
    };

    #pragma unroll
    for (int c = 0; c < 8; c++) {
        int id = tid * 8 + c;
        int row = id >> 4, fcol = (id & 15) * 4;
        CP_ASYNC16(sb + (uint32_t)(FA_Q + row * FST + fcol) * 4u,
                   qg + ((size_t)bb * Ssz + i0 + row) * Dsz + hh * DHsz + fcol);
    }
    CP_COMMIT();
    loadKV(0, 0);

    CP_WAIT1();
    __syncthreads();

    const int lq = lane >> 3, lr = lane & 7;
    const int aoffA = ((lq & 1) * 8 + lr) * FST + (lq >> 1) * 4;
    const int boffB = ((lq >> 1) * 8 + lr) * FST + (lq & 1) * 4;

    uint32_t qf[8][4];
    #pragma unroll
    for (int kc = 0; kc < 8; kc++)
        ldsm_x4(qf[kc], sb + (uint32_t)(FA_Q + (w * 16) * FST + aoffA + kc * 8) * 4u);

    float acc_o[8][4] = {};
    float m_r[2] = {-1e30f, -1e30f};
    float l_r[2] = {0.f, 0.f};
    // log2-domain scale: 1/sqrt(64*3) * log2(e)
    const float SCALE2 = 0.07216878364870323f * 1.4426950408889634f;
    const int mg0 = i0 + w * 16 + g;

    for (int jt = 0; jt < 16; jt++) {
        const int buf = jt & 1;
        const int j0 = jt * 64;
        CP_WAIT0();
        __syncthreads();
        if (jt < 15) loadKV(jt + 1, buf ^ 1);

        // ---- S = Q K^T (64 cols) ----
        float acc_s[8][4] = {};
        #pragma unroll
        for (int kc = 0; kc < 8; kc++) {
            #pragma unroll
            for (int ip = 0; ip < 4; ip++) {
                uint32_t bf[4];
                ldsm_x4(bf, sb + (uint32_t)(FA_K(buf) + (ip * 16) * FST + boffB + kc * 8) * 4u);
                mma_tf32(acc_s[ip * 2],     qf[kc], &bf[0]);
                mma_tf32(acc_s[ip * 2 + 1], qf[kc], &bf[2]);
            }
        }

        // ---- bias + online softmax (log2 domain, f16x2 exp2) ----
        float mx0 = -1e30f, mx1 = -1e30f;
        #pragma unroll
        for (int in = 0; in < 8; in++) {
            int nbase = j0 + in * 8 + tg * 2;
            #pragma unroll
            for (int e = 0; e < 4; e++) {
                int m = mg0 + ((e >= 2) ? 8 : 0);
                int n = nbase + (e & 1);
                int idx = lut_s[m - n + (Ssz - 1)];
                float vv = (acc_s[in][e] + __ldg(&c2pz[(size_t)m * NPOS + idx])
                                         + __ldg(&p2cz[(size_t)n * NPOS + idx])) * SCALE2;
                acc_s[in][e] = vv;
                if (e < 2) mx0 = fmaxf(mx0, vv); else mx1 = fmaxf(mx1, vv);
            }
        }
        mx0 = fmaxf(mx0, __shfl_xor_sync(0xffffffffu, mx0, 1));
        mx0 = fmaxf(mx0, __shfl_xor_sync(0xffffffffu, mx0, 2));
        mx1 = fmaxf(mx1, __shfl_xor_sync(0xffffffffu, mx1, 1));
        mx1 = fmaxf(mx1, __shfl_xor_sync(0xffffffffu, mx1, 2));
        float mn0 = fmaxf(m_r[0], mx0), mn1 = fmaxf(m_r[1], mx1);
        float al0 = exp2f(m_r[0] - mn0), al1 = exp2f(m_r[1] - mn1);
        float s0 = 0.f, s1 = 0.f;
        #pragma unroll
        for (int in = 0; in < 8; in++) {
            float d0 = acc_s[in][0] - mn0;
            float d1 = acc_s[in][1] - mn0;
            float d2 = acc_s[in][2] - mn1;
            float d3 = acc_s[in][3] - mn1;
            __half2 e01 = h2exp2(__floats2half2_rn(d0, d1));
            __half2 e23 = h2exp2(__floats2half2_rn(d2, d3));
            float2 f01 = __half22float2(e01);
            float2 f23 = __half22float2(e23);
            acc_s[in][0] = f01.x; acc_s[in][1] = f01.y;
            acc_s[in][2] = f23.x; acc_s[in][3] = f23.y;
            s0 += f01.x + f01.y; s1 += f23.x + f23.y;
        }
        l_r[0] = l_r[0] * al0 + s0;
        l_r[1] = l_r[1] * al1 + s1;
        m_r[0] = mn0; m_r[1] = mn1;
        #pragma unroll
        for (int nf = 0; nf < 8; nf++) {
            acc_o[nf][0] *= al0; acc_o[nf][1] *= al0;
            acc_o[nf][2] *= al1; acc_o[nf][3] *= al1;
        }

        // ---- O += P V : P from registers (V columns pre-permuted) ----
        #pragma unroll
        for (int kc2 = 0; kc2 < 8; kc2++) {
            uint32_t af[4];
            af[0] = __float_as_uint(acc_s[kc2][0]);
            af[1] = __float_as_uint(acc_s[kc2][2]);
            af[2] = __float_as_uint(acc_s[kc2][1]);
            af[3] = __float_as_uint(acc_s[kc2][3]);
            #pragma unroll
            for (int ip = 0; ip < 4; ip++) {
                uint32_t bf[4];
                ldsm_x4(bf, sb + (uint32_t)(FA_V(buf) + (ip * 16) * FST + boffB + kc2 * 8) * 4u);
                mma_tf32(acc_o[ip * 2],     af, &bf[0]);
                mma_tf32(acc_o[ip * 2 + 1], af, &bf[2]);
            }
        }
    }

    float l0 = l_r[0];
    l0 += __shfl_xor_sync(0xffffffffu, l0, 1);
    l0 += __shfl_xor_sync(0xffffffffu, l0, 2);
    float l1 = l_r[1];
    l1 += __shfl_xor_sync(0xffffffffu, l1, 1);
    l1 += __shfl_xor_sync(0xffffffffu, l1, 2);
    float inv0 = 1.0f / l0, inv1 = 1.0f / l1;
    float* c0 = ctx + ((size_t)bb * Ssz + mg0)     * Dsz + hh * DHsz;
    float* c1 = ctx + ((size_t)bb * Ssz + mg0 + 8) * Dsz + hh * DHsz;
    #pragma unroll
    for (int nf = 0; nf < 8; nf++) {
        int col = nf * 8 + tg * 2;
        *(float2*)&c0[col] = make_float2(acc_o[nf][0] * inv0, acc_o[nf][1] * inv0);
        *(float2*)&c1[col] = make_float2(acc_o[nf][2] * inv1, acc_o[nf][3] * inv1);
    }
}

// =============================== launch ========================================
extern "C" void kernel_launch(void* const* d_in, const int* in_sizes, int n_in,
                              void* d_out, int out_size) {
    const float* x      = (const float*)d_in[0];
    const float* ln1g   = (const float*)d_in[1];
    const float* ln1b   = (const float*)d_in[2];
    const float* dww    = (const float*)d_in[3];
    const float* dwb    = (const float*)d_in[4];
    const float* pww    = (const float*)d_in[5];
    const float* pwb    = (const float*)d_in[6];
    const float* ln2g   = (const float*)d_in[7];
    const float* ln2b   = (const float*)d_in[8];
    const float* qw     = (const float*)d_in[9];
    const float* qb     = (const float*)d_in[10];
    const float* kw     = (const float*)d_in[11];
    const float* kb     = (const float*)d_in[12];
    const float* vw     = (const float*)d_in[13];
    const float* vb     = (const float*)d_in[14];
    const float* ow     = (const float*)d_in[15];
    const float* ob     = (const float*)d_in[16];
    const float* relemb = (const float*)d_in[17];
    const float* ln3g   = (const float*)d_in[18];
    const float* ln3b   = (const float*)d_in[19];
    const float* w1     = (const float*)d_in[20];
    const float* b1     = (const float*)d_in[21];
    const float* w2     = (const float*)d_in[22];
    const float* b2     = (const float*)d_in[23];
    float* out = (float*)d_out;

    float *xn, *conv, *x1, *x2, *q, *k, *v, *vt, *ctx, *posk, *posq, *c2p, *p2c, *ff;
    int* lut;
    cudaGetSymbolAddress((void**)&xn,   g_xn);
    cudaGetSymbolAddress((void**)&conv, g_conv);
    cudaGetSymbolAddress((void**)&x1,   g_x1);
    cudaGetSymbolAddress((void**)&x2,   g_x2);
    cudaGetSymbolAddress((void**)&q,    g_q);
    cudaGetSymbolAddress((void**)&k,    g_k);
    cudaGetSymbolAddress((void**)&v,    g_v);
    cudaGetSymbolAddress((void**)&vt,   g_vt);
    cudaGetSymbolAddress((void**)&ctx,  g_ctx);
    cudaGetSymbolAddress((void**)&posk, g_posk);
    cudaGetSymbolAddress((void**)&posq, g_posq);
    cudaGetSymbolAddress((void**)&c2p,  g_c2p);
    cudaGetSymbolAddress((void**)&p2c,  g_p2c);
    cudaGetSymbolAddress((void**)&ff,   g_ff);
    cudaGetSymbolAddress((void**)&lut,  g_lut);

    static int attr_set = 0;
    if (!attr_set) {
        cudaFuncSetAttribute(flash_attn_kernel,
                             cudaFuncAttributeMaxDynamicSharedMemorySize, FA_SMEM);
        cudaFuncSetAttribute(gemm_mma_kernel<128,2,0>,
                             cudaFuncAttributeMaxDynamicSharedMemorySize, GEMM_SMEM(128));
        cudaFuncSetAttribute(gemm_mma_kernel<128,1,4>,
                             cudaFuncAttributeMaxDynamicSharedMemorySize, GEMM_SMEM(128));
        cudaFuncSetAttribute(gemm_mma_kernel<128,3,0>,
                             cudaFuncAttributeMaxDynamicSharedMemorySize, GEMM_SMEM(128));
        cudaFuncSetAttribute(gemm_pos_kernel<64>,
                             cudaFuncAttributeMaxDynamicSharedMemorySize, GEMM_SMEM(64));
        attr_set = 1;
    }

    build_lut_kernel<<<8, 256>>>(lut);

    // ---- conv block ----
    layernorm_kernel<<<NROWS, 256>>>(x, ln1g, ln1b, xn);
    dwconv_silu_kernel<<<(Bsz*Ssz*Dsz + 255) / 256, 256>>>(xn, dww, dwb, conv);
    gemm_mma_kernel<128,2,0><<<dim3(Dsz/128, NROWS/128, 1), 256, GEMM_SMEM(128)>>>(
        conv, Dsz, pww, Dsz, pwb, x, x1, Dsz, Dsz,
        nullptr, nullptr, nullptr, nullptr, nullptr, nullptr, nullptr);

    // ---- attention block ----
    layernorm_kernel<<<NROWS, 256>>>(x1, ln2g, ln2b, xn);
    gemm_mma_kernel<128,1,4><<<dim3(Dsz/128, NROWS/128, 3), 256, GEMM_SMEM(128)>>>(
        xn, Dsz, qw, Dsz, qb, nullptr, q, Dsz, Dsz,
        nullptr, kw, vw, kb, vb, k, v);
    transpose_v_kernel<<<dim3(Ssz/32, Dsz/32, Bsz), dim3(32, 8)>>>(v, vt);

    gemm_tn_small_kernel<<<dim3(Dsz/64, 1, 2), 256>>>(
        relemb, Dsz, kw, Dsz, kb, posk, qw, qb, posq, Dsz, Dsz);

    gemm_pos_kernel<64><<<dim3(1, Ssz/128, 2*Bsz*Hsz), 256, GEMM_SMEM(64)>>>(
        q, posk, c2p, k, posq, p2c);

    flash_attn_kernel<<<dim3(Ssz/128, 1, Bsz*Hsz), 256, FA_SMEM>>>(
        q, k, vt, c2p, p2c, lut, ctx);

    gemm_mma_kernel<128,2,0><<<dim3(Dsz/128, NROWS/128, 1), 256, GEMM_SMEM(128)>>>(
        ctx, Dsz, ow, Dsz, ob, x1, x2, Dsz, Dsz,
        nullptr, nullptr, nullptr, nullptr, nullptr, nullptr, nullptr);

    // ---- FFN block ----
    layernorm_kernel<<<NROWS, 256>>>(x2, ln3g, ln3b, xn);
    gemm_mma_kernel<128,3,0><<<dim3(FFsz/128, NROWS/128, 1), 256, GEMM_SMEM(128)>>>(
        xn, Dsz, w1, Dsz, b1, nullptr, ff, FFsz, Dsz,
        nullptr, nullptr, nullptr, nullptr, nullptr, nullptr, nullptr);
    gemm_mma_kernel<128,2,0><<<dim3(Dsz/128, NROWS/128, 1), 256, GEMM_SMEM(128)>>>(
        ff, FFsz, w2, FFsz, b2, x2, out, Dsz, FFsz,
        nullptr, nullptr, nullptr, nullptr, nullptr, nullptr, nullptr);
}

// round 12
// speedup vs baseline: 1.3826x; 1.3826x over previous
#include <cuda_runtime.h>
#include <cuda_fp16.h>
#include <math.h>
#include <stdint.h>

#define Bsz 8
#define Ssz 1024
#define Dsz 512
#define Hsz 8
#define DHsz 64
#define FFsz 1024
#define NPOS 64          // 2*SPAN
#define NROWS (Bsz*Ssz)  // 8192

// ---------------- scratch (device globals; no allocation allowed) ------------
// fp32 residual stream + bias-like data
__device__ float  g_x1  [Bsz*Ssz*Dsz];
__device__ float  g_x2  [Bsz*Ssz*Dsz];
__device__ float  g_c2p [Bsz*Hsz*Ssz*NPOS];
__device__ float  g_p2c [Bsz*Hsz*Ssz*NPOS];
__device__ int    g_lut [2*Ssz];
// half activations (GEMM inputs)
__device__ __half g_xnh  [Bsz*Ssz*Dsz];
__device__ __half g_convh[Bsz*Ssz*Dsz];
__device__ __half g_qh   [Bsz*Ssz*Dsz];
__device__ __half g_kh   [Bsz*Ssz*Dsz];
__device__ __half g_vh   [Bsz*Ssz*Dsz];
__device__ __half g_vth  [Bsz*Ssz*Dsz];   // [B, D, S]
__device__ __half g_ctxh [Bsz*Ssz*Dsz];
__device__ __half g_ffh  [Bsz*Ssz*FFsz];
__device__ __half g_poskh[NPOS*Dsz];
__device__ __half g_posqh[NPOS*Dsz];
// half weights
__device__ __half g_pwwh[Dsz*Dsz];
__device__ __half g_qwh [Dsz*Dsz];
__device__ __half g_kwh [Dsz*Dsz];
__device__ __half g_vwh [Dsz*Dsz];
__device__ __half g_owh [Dsz*Dsz];
__device__ __half g_w1h [FFsz*Dsz];
__device__ __half g_w2h [FFsz*Dsz];

// ---------------- weight fp32 -> fp16 ------------------------------------------
__global__ void f2h_kernel(const float* __restrict__ s0, const float* __restrict__ s1,
                           const float* __restrict__ s2, const float* __restrict__ s3,
                           const float* __restrict__ s4, const float* __restrict__ s5,
                           const float* __restrict__ s6,
                           __half* d0, __half* d1, __half* d2, __half* d3,
                           __half* d4, __half* d5, __half* d6) {
    int z = blockIdx.z;
    const float* s; __half* d; int n;
    switch (z) {
        case 0: s = s0; d = d0; n = Dsz*Dsz;  break;
        case 1: s = s1; d = d1; n = Dsz*Dsz;  break;
        case 2: s = s2; d = d2; n = Dsz*Dsz;  break;
        case 3: s = s3; d = d3; n = Dsz*Dsz;  break;
        case 4: s = s4; d = d4; n = Dsz*Dsz;  break;
        case 5: s = s5; d = d5; n = FFsz*Dsz; break;
        default:s = s6; d = d6; n = FFsz*Dsz; break;
    }
    for (int i = blockIdx.x * blockDim.x + threadIdx.x; i < n; i += gridDim.x * blockDim.x)
        d[i] = __float2half(s[i]);
}

// ---------------- relative-position bucket LUT --------------------------------
__global__ void build_lut_kernel(int* __restrict__ lut) {
    int t = blockIdx.x * blockDim.x + threadIdx.x;
    if (t >= 2*Ssz - 1) return;
    int rel = t - (Ssz - 1);   // i - j
    const int mid = 16;        // BUCKETS/2
    int bucket;
    if (rel > -mid && rel < mid) {
        bucket = rel;
    } else {
        float absp = fabsf((float)rel);
        if (absp <= (float)mid) {
            bucket = rel;
        } else {
            float logp = ceilf(logf(absp / 16.0f) / logf(127.0f / 16.0f) * 15.0f) + 16.0f;
            bucket = (rel > 0 ? 1 : -1) * (int)logp;
        }
    }
    int idx = bucket + 32;
    idx = min(max(idx, 0), 63);
    lut[t] = idx;
}

// ---------------- LayerNorm (D=512, one block per row) -> half -----------------
__global__ void layernorm_kernel(const float* __restrict__ x,
                                 const float* __restrict__ g,
                                 const float* __restrict__ bb,
                                 __half* __restrict__ out) {
    const float* xr = x + (size_t)blockIdx.x * Dsz;
    __half* orow = out + (size_t)blockIdx.x * Dsz;
    int tid = threadIdx.x;  // 256
    float v0 = xr[tid], v1 = xr[tid + 256];
    float s = v0 + v1, ss = v0 * v0 + v1 * v1;
    __shared__ float r1[8], r2[8];
    #pragma unroll
    for (int o = 16; o; o >>= 1) {
        s  += __shfl_xor_sync(0xffffffffu, s, o);
        ss += __shfl_xor_sync(0xffffffffu, ss, o);
    }
    if ((tid & 31) == 0) { r1[tid >> 5] = s; r2[tid >> 5] = ss; }
    __syncthreads();
    float S1 = 0.f, S2 = 0.f;
    #pragma unroll
    for (int i = 0; i < 8; i++) { S1 += r1[i]; S2 += r2[i]; }
    float mean = S1 * (1.0f / Dsz);
    float var  = S2 * (1.0f / Dsz) - mean * mean;
    float rs = rsqrtf(var + 1e-5f);
    orow[tid]       = __float2half((v0 - mean) * rs * g[tid]       + bb[tid]);
    orow[tid + 256] = __float2half((v1 - mean) * rs * g[tid + 256] + bb[tid + 256]);
}

// ---------------- depthwise conv (K=3 along S) + bias + SiLU (half->half) ------
__global__ void dwconv_silu_kernel(const __half* __restrict__ xn,
                                   const float* __restrict__ w,
                                   const float* __restrict__ bias,
                                   __half* __restrict__ out) {
    size_t idx = (size_t)blockIdx.x * blockDim.x + threadIdx.x;
    if (idx >= (size_t)Bsz * Ssz * Dsz) return;
    int d = (int)(idx % Dsz);
    int s = (int)((idx / Dsz) % Ssz);
    const __half* base = xn + idx;
    float w0 = w[d * 3 + 0], w1 = w[d * 3 + 1], w2 = w[d * 3 + 2];
    float acc = bias[d] + __half2float(base[0]) * w1;
    if (s > 0)        acc += __half2float(base[-Dsz]) * w0;
    if (s < Ssz - 1)  acc += __half2float(base[ Dsz]) * w2;
    out[idx] = __float2half(acc / (1.0f + expf(-acc)));  // silu
}

// ---------------- V transpose: [B,S,D] -> [B,D,S] (half) -----------------------
__global__ void transpose_v_kernel(const __half* __restrict__ v, __half* __restrict__ vt) {
    __shared__ __half tile[32][34];
    int b = blockIdx.z;
    int s0 = blockIdx.x * 32, d0 = blockIdx.y * 32;
    int tx = threadIdx.x, ty = threadIdx.y;  // 32 x 8
    #pragma unroll
    for (int j = 0; j < 32; j += 8)
        tile[ty + j][tx] = v[((size_t)b * Ssz + s0 + ty + j) * Dsz + d0 + tx];
    __syncthreads();
    #pragma unroll
    for (int j = 0; j < 32; j += 8)
        vt[((size_t)b * Dsz + d0 + ty + j) * Ssz + s0 + tx] = tile[tx][ty + j];
}

// ---------------- mma.f16 + ldmatrix helpers -----------------------------------
__device__ __forceinline__ void mma_f16(float c[4], const uint32_t a[4], const uint32_t b[2]) {
    asm volatile(
        "mma.sync.aligned.m16n8k16.row.col.f32.f16.f16.f32 "
        "{%0,%1,%2,%3}, {%4,%5,%6,%7}, {%8,%9}, {%0,%1,%2,%3};"
        : "+f"(c[0]), "+f"(c[1]), "+f"(c[2]), "+f"(c[3])
        : "r"(a[0]), "r"(a[1]), "r"(a[2]), "r"(a[3]), "r"(b[0]), "r"(b[1]));
}

__device__ __forceinline__ void ldsm_x4(uint32_t r[4], uint32_t addr) {
    asm volatile("ldmatrix.sync.aligned.m8n8.x4.shared.b16 {%0,%1,%2,%3}, [%4];"
                 : "=r"(r[0]), "=r"(r[1]), "=r"(r[2]), "=r"(r[3]) : "r"(addr));
}

#define CP_ASYNC16(dst_u32, src_ptr) \
    asm volatile("cp.async.ca.shared.global [%0], [%1], 16;" :: "r"(dst_u32), "l"(src_ptr))
#define CP_COMMIT() asm volatile("cp.async.commit_group;")
#define CP_WAIT2()  asm volatile("cp.async.wait_group 2;")
#define CP_WAIT1()  asm volatile("cp.async.wait_group 1;")
#define CP_WAIT0()  asm volatile("cp.async.wait_group 0;")

// ---------------- fp16 tensor-core TN GEMM (128xCN tiles, K32 chunks) ----------
// C[m,n] = sum_k A[m,k]*W[n,k], A/W half, accum fp32.
// EPI: 0 none, 1 +bias, 2 +bias+res, 3 silu(+bias). OUTH: 1 -> write half.
// MODE: 0 plain, 4 qkv-merged (z selects weights/bias/out).
#define STRB 80                      // bytes per 32-half row (64B data + 16B pad)
#define NSTAGE 4
#define GEMM_SMEMH(CNv) (NSTAGE * (128 + (CNv)) * STRB)

template<int CN, int EPI, int MODE, int OUTH>
__global__ void __launch_bounds__(256, 2) gemm_mma_kernel(
    const __half* __restrict__ A0, int lda,
    const __half* __restrict__ W0, int ldw,
    const float* __restrict__ bias0, const float* __restrict__ res,
    void* __restrict__ C0v, int ldc, int K,
    const __half* __restrict__ Wa, const __half* __restrict__ Wb2,
    const float* __restrict__ ba, const float* __restrict__ bb2,
    void* __restrict__ Cav, void* __restrict__ Cbv)
{
    constexpr int NWN = CN / 32;     // warps along N
    constexpr int NWM = 8 / NWN;     // warps along M
    constexpr int MT  = 8 / NWM;     // m16 tiles per warp

    extern __shared__ char smem[];
    const uint32_t sb = (uint32_t)__cvta_generic_to_shared(smem);
    const uint32_t sA = sb;                              // NSTAGE * 128 * STRB
    const uint32_t sW = sb + NSTAGE * 128 * STRB;        // NSTAGE * CN * STRB

    const int tid  = threadIdx.x;
    const int wid  = tid >> 5, lane = tid & 31;
    const int g    = lane >> 2, tg = lane & 3;
    const int wm   = wid % NWM, wn = wid / NWM;

    const int z = blockIdx.z;
    const __half* A = A0; const __half* W = W0; void* Cv = C0v;
    const float* bias = bias0;
    if (MODE == 4) {
        W    = (z == 0) ? W0 : (z == 1 ? Wa : Wb2);
        bias = (z == 0) ? bias0 : (z == 1 ? ba : bb2);
        Cv   = (z == 0) ? C0v : (z == 1 ? Cav : Cbv);
    }

    const int m_cta = blockIdx.y * 128, n_cta = blockIdx.x * CN;

    auto fetch = [&](int t, int buf) {
        int k0 = t * 32;
        #pragma unroll
        for (int r = 0; r < 2; r++) {               // A: 128 rows x 4 chunks
            int id = tid + 256 * r;                 // 0..511
            int row = id >> 2, ch = id & 3;
            CP_ASYNC16(sA + (uint32_t)(buf * 128 * STRB + row * STRB + ch * 16),
                       A + (size_t)(m_cta + row) * lda + k0 + ch * 8);
        }
        #pragma unroll
        for (int r = 0; r < CN / 64; r++) {         // W: CN rows x 4 chunks
            int id = tid + 256 * r;
            int row = id >> 2, ch = id & 3;
            CP_ASYNC16(sW + (uint32_t)(buf * CN * STRB + row * STRB + ch * 16),
                       W + (size_t)(n_cta + row) * ldw + k0 + ch * 8);
        }
        CP_COMMIT();
    };

    const int lq = lane >> 3, lr = lane & 7;
    const int aoff = ((lq & 1) * 8 + lr) * STRB + (lq >> 1) * 16;  // A frag (bytes)
    const int boff = ((lq >> 1) * 8 + lr) * STRB + (lq & 1) * 16;  // B frag (bytes)

    float acc[MT][4][4] = {};

    const int T = K / 32;
    fetch(0, 0);
    fetch(1, 1);
    if (T > 2) fetch(2, 2);
    for (int it = 0; it < T; it++) {
        const int buf = it & (NSTAGE - 1);
        if (it < T - 2)       { CP_WAIT2(); }
        else if (it == T - 2) { CP_WAIT1(); }
        else                  { CP_WAIT0(); }
        __syncthreads();
        if (it + 3 < T) fetch(it + 3, (it + 3) & (NSTAGE - 1));

        const uint32_t bA = sA + (uint32_t)(buf * 128 * STRB);
        const uint32_t bW = sW + (uint32_t)(buf * CN  * STRB);
        #pragma unroll
        for (int ks = 0; ks < 2; ks++) {            // two k16 steps per K32
            const int kb = ks * 32;                 // byte offset of k16 chunk
            uint32_t af[MT][4];
            #pragma unroll
            for (int im = 0; im < MT; im++)
                ldsm_x4(af[im], bA + (uint32_t)((wm * MT * 16 + im * 16) * STRB + aoff + kb));
            uint32_t bf[2][4];                       // each x4 covers 2 n8 tiles
            #pragma unroll
            for (int ip = 0; ip < 2; ip++)
                ldsm_x4(bf[ip], bW + (uint32_t)((wn * 32 + ip * 16) * STRB + boff + kb));
            #pragma unroll
            for (int im = 0; im < MT; im++)
                #pragma unroll
                for (int in = 0; in < 4; in++)
                    mma_f16(acc[im][in], af[im], &bf[in >> 1][(in & 1) * 2]);
        }
    }

    #pragma unroll
    for (int im = 0; im < MT; im++) {
        int mrow0 = m_cta + wm * MT * 16 + im * 16 + g;
        #pragma unroll
        for (int in = 0; in < 4; in++) {
            int ncol0 = n_cta + wn * 32 + in * 8 + tg * 2;
            #pragma unroll
            for (int e = 0; e < 4; e++) {
                int m = mrow0 + ((e >= 2) ? 8 : 0);
                int n = ncol0 + (e & 1);
                float vv = acc[im][in][e];
                if (EPI == 1 || EPI == 2 || EPI == 3) vv += bias[n];
                if (EPI == 2) vv += res[(size_t)m * ldc + n];
                if (EPI == 3) vv = vv / (1.0f + expf(-vv));
                if (OUTH) ((__half*)Cv)[(size_t)m * ldc + n] = __float2half(vv);
                else      ((float*) Cv)[(size_t)m * ldc + n] = vv;
            }
        }
    }
}

// ---------------- fp16 mma GEMM for pos projections (N=64, K=64) ---------------
__global__ void __launch_bounds__(256, 2) gemm_pos_kernel(
    const __half* __restrict__ A0,
    const __half* __restrict__ W0,
    float* __restrict__ C0,
    const __half* __restrict__ Aa, const __half* __restrict__ Wa,
    float* __restrict__ Ca)
{
    // CN=64: NWN=2, NWM=4, MT=2
    extern __shared__ char smem[];
    const uint32_t sb = (uint32_t)__cvta_generic_to_shared(smem);
    const uint32_t sA = sb;
    const uint32_t sW = sb + NSTAGE * 128 * STRB;

    const int tid  = threadIdx.x;
    const int wid  = tid >> 5, lane = tid & 31;
    const int g    = lane >> 2, tg = lane & 3;
    const int wm   = wid & 3, wn = wid >> 2;

    int zz = blockIdx.z & 63, sel = blockIdx.z >> 6;
    int bb = zz >> 3, hh = zz & 7;
    const __half* A = (sel ? Aa : A0) + (size_t)bb * Ssz * Dsz + hh * DHsz;
    const __half* W = (sel ? Wa : W0) + hh * DHsz;
    float* C = (sel ? Ca : C0) + (size_t)zz * Ssz * NPOS;

    const int m_cta = blockIdx.y * 128;

    auto fetch = [&](int t, int buf) {
        int k0 = t * 32;
        #pragma unroll
        for (int r = 0; r < 2; r++) {
            int id = tid + 256 * r;
            int row = id >> 2, ch = id & 3;
            CP_ASYNC16(sA + (uint32_t)(buf * 128 * STRB + row * STRB + ch * 16),
                       A + (size_t)(m_cta + row) * Dsz + k0 + ch * 8);
        }
        {   // W: 64 rows x 4 chunks = 256
            int row = tid >> 2, ch = tid & 3;
            if (row < 64)
                CP_ASYNC16(sW + (uint32_t)(buf * 64 * STRB + row * STRB + ch * 16),
                           W + (size_t)row * Dsz + k0 + ch * 8);
        }
        CP_COMMIT();
    };

    const int lq = lane >> 3, lr = lane & 7;
    const int aoff = ((lq & 1) * 8 + lr) * STRB + (lq >> 1) * 16;
    const int boff = ((lq >> 1) * 8 + lr) * STRB + (lq & 1) * 16;

    float acc[2][4][4] = {};
    const int T = 2;   // K=64
    fetch(0, 0); fetch(1, 1);
    for (int it = 0; it < T; it++) {
        const int buf = it & (NSTAGE - 1);
        if (it == T - 2) { CP_WAIT1(); } else { CP_WAIT0(); }
        __syncthreads();

        const uint32_t bA = sA + (uint32_t)(buf * 128 * STRB);
        const uint32_t bW = sW + (uint32_t)(buf * 64  * STRB);
        #pragma unroll
        for (int ks = 0; ks < 2; ks++) {
            const int kb = ks * 32;
            uint32_t af[2][4];
            #pragma unroll
            for (int im = 0; im < 2; im++)
                ldsm_x4(af[im], bA + (uint32_t)((wm * 32 + im * 16) * STRB + aoff + kb));
            uint32_t bf[2][4];
            #pragma unroll
            for (int ip = 0; ip < 2; ip++)
                ldsm_x4(bf[ip], bW + (uint32_t)((wn * 32 + ip * 16) * STRB + boff + kb));
            #pragma unroll
            for (int im = 0; im < 2; im++)
                #pragma unroll
                for (int in = 0; in < 4; in++)
                    mma_f16(acc[im][in], af[im], &bf[in >> 1][(in & 1) * 2]);
        }
    }

    #pragma unroll
    for (int im = 0; im < 2; im++) {
        int mrow0 = m_cta + wm * 32 + im * 16 + g;
        #pragma unroll
        for (int in = 0; in < 4; in++) {
            int ncol0 = wn * 32 + in * 8 + tg * 2;
            #pragma unroll
            for (int e = 0; e < 4; e++) {
                int m = mrow0 + ((e >= 2) ? 8 : 0);
                int nn = ncol0 + (e & 1);
                C[(size_t)m * NPOS + nn] = acc[im][in][e];
            }
        }
    }
}

// ---------------- small SIMT GEMM (pos-emb projections, fp32 in, half out) -----
#define TK 16
#define TPAD 68
__global__ void gemm_tn_small_kernel(const float* __restrict__ A, int lda,
                                     const float* __restrict__ W0, int ldw,
                                     const float* __restrict__ b0,
                                     __half* __restrict__ C0,
                                     const float* __restrict__ W1,
                                     const float* __restrict__ b1,
                                     __half* __restrict__ C1, int ldc, int Kd) {
    const float* W   = blockIdx.z ? W1 : W0;
    const float* bias= blockIdx.z ? b1 : b0;
    __half* C        = blockIdx.z ? C1 : C0;
    int m0 = blockIdx.y * 64, n0 = blockIdx.x * 64;
    __shared__ float As[TK][TPAD];
    __shared__ float Ws2[TK][TPAD];
    const int tid = threadIdx.x;
    const int tx = tid & 15, ty = tid >> 4;
    const int lk = tid & 15, lm = tid >> 4;
    float acc[4][4] = {};
    for (int k0 = 0; k0 < Kd; k0 += TK) {
        #pragma unroll
        for (int r = 0; r < 4; r++) {
            As[lk][lm + 16 * r]  = A[(size_t)(m0 + lm + 16 * r) * lda + k0 + lk];
            Ws2[lk][lm + 16 * r] = W[(size_t)(n0 + lm + 16 * r) * ldw + k0 + lk];
        }
        __syncthreads();
        #pragma unroll
        for (int kk = 0; kk < TK; kk++) {
            float4 a = *(const float4*)&As[kk][ty * 4];
            float4 b = *(const float4*)&Ws2[kk][tx * 4];
            float av[4] = {a.x, a.y, a.z, a.w};
            float bv[4] = {b.x, b.y, b.z, b.w};
            #pragma unroll
            for (int i = 0; i < 4; i++)
                #pragma unroll
                for (int j = 0; j < 4; j++)
                    acc[i][j] += av[i] * bv[j];
        }
        __syncthreads();
    }
    #pragma unroll
    for (int i = 0; i < 4; i++) {
        int m = m0 + ty * 4 + i;
        #pragma unroll
        for (int j = 0; j < 4; j++) {
            int n = n0 + tx * 4 + j;
            C[(size_t)m * ldc + n] = __float2half(acc[i][j] + bias[n]);
        }
    }
}

// =========================== fused flash attention (fp16 mma) ==================
// Register P (half2 from h2exp2 feeds P.V A-frags directly), KV double-buffer,
// 1 cp.async group + 1 barrier per j-tile of 64.
#define STRF 144                      // bytes per 64-half row (128B data + 16B pad)
#define FA_K(buf) ((buf) * 64 * STRF)
#define FA_V(buf) (2 * 64 * STRF + (buf) * 64 * STRF)
#define FA_Q      (4 * 64 * STRF)
#define FA_LUT    (4 * 64 * STRF + 128 * STRF)
#define FA_SMEM   (FA_LUT + 2048 * 4)

__global__ void __launch_bounds__(256, 2) flash_attn_kernel(
    const __half* __restrict__ qg, const __half* __restrict__ kg,
    const __half* __restrict__ vt,
    const float* __restrict__ c2p, const float* __restrict__ p2c,
    const int* __restrict__ lut, __half* __restrict__ ctx)
{
    extern __shared__ char smc[];
    int* lut_s = (int*)(smc + FA_LUT);

    const int tid = threadIdx.x, w = tid >> 5, lane = tid & 31;
    const int g = lane >> 2, tg = lane & 3;
    const int z = blockIdx.z, bb = z >> 3, hh = z & 7;
    const int i0 = blockIdx.x * 128;

    const float* c2pz = c2p + (size_t)z * Ssz * NPOS;
    const float* p2cz = p2c + (size_t)z * Ssz * NPOS;

    const uint32_t sb = (uint32_t)__cvta_generic_to_shared(smc);

    #pragma unroll
    for (int t = 0; t < 8; t++) {
        int idx = tid + 256 * t;
        if (idx < 2 * Ssz - 1) lut_s[idx] = lut[idx];
    }

    auto loadKV = [&](int jt, int buf) {
        int j0 = jt * 64;
        #pragma unroll
        for (int c = 0; c < 2; c++) {       // K: 64 rows x 8 chunks = 512
            int id = tid * 2 + c;
            int row = id >> 3, ch = id & 7;
            CP_ASYNC16(sb + (uint32_t)(FA_K(buf) + row * STRF + ch * 16),
                       kg + ((size_t)bb * Ssz + j0 + row) * Dsz + hh * DHsz + ch * 8);
        }
        #pragma unroll
        for (int c = 0; c < 2; c++) {       // V: 64 d-rows x 8 chunks (j contig)
            int id = tid * 2 + c;
            int row = id >> 3, ch = id & 7;
            CP_ASYNC16(sb + (uint32_t)(FA_V(buf) + row * STRF + ch * 16),
                       vt + ((size_t)bb * Dsz + hh * DHsz + row) * Ssz + j0 + ch * 8);
        }
        CP_COMMIT();
    };

    #pragma unroll
    for (int c = 0; c < 4; c++) {           // Q: 128 rows x 8 chunks = 1024
        int id = tid * 4 + c;
        int row = id >> 3, ch = id & 7;
        CP_ASYNC16(sb + (uint32_t)(FA_Q + row * STRF + ch * 16),
                   qg + ((size_t)bb * Ssz + i0 + row) * Dsz + hh * DHsz + ch * 8);
    }
    CP_COMMIT();
    loadKV(0, 0);

    CP_WAIT1();
    __syncthreads();

    const int lq = lane >> 3, lr = lane & 7;
    const int aoffF = ((lq & 1) * 8 + lr) * STRF + (lq >> 1) * 16;
    const int boffF = ((lq >> 1) * 8 + lr) * STRF + (lq & 1) * 16;

    uint32_t qf[4][4];                       // 4 k16 chunks over d=64
    #pragma unroll
    for (int kc = 0; kc < 4; kc++)
        ldsm_x4(qf[kc], sb + (uint32_t)(FA_Q + (w * 16) * STRF + aoffF + kc * 32));

    float acc_o[8][4] = {};
    float m_r[2] = {-1e30f, -1e30f};
    float l_r[2] = {0.f, 0.f};
    const float SCALE2 = 0.07216878364870323f * 1.4426950408889634f;  // log2 domain
    const int mg0 = i0 + w * 16 + g;

    for (int jt = 0; jt < 16; jt++) {
        const int buf = jt & 1;
        const int j0 = jt * 64;
        CP_WAIT0();
        __syncthreads();
        if (jt < 15) loadKV(jt + 1, buf ^ 1);

        // ---- S = Q K^T (64 cols) ----
        float acc_s[8][4] = {};
        #pragma unroll
        for (int kc = 0; kc < 4; kc++) {
            #pragma unroll
            for (int ip = 0; ip < 4; ip++) {
                uint32_t bf[4];
                ldsm_x4(bf, sb + (uint32_t)(FA_K(buf) + (ip * 16) * STRF + boffF + kc * 32));
                mma_f16(acc_s[ip * 2],     qf[kc], &bf[0]);
                mma_f16(acc_s[ip * 2 + 1], qf[kc], &bf[2]);
            }
        }

        // ---- bias + online softmax (log2 domain, half2 exp2) ----
        float mx0 = -1e30f, mx1 = -1e30f;
        #pragma unroll
        for (int in = 0; in < 8; in++) {
            int nbase = j0 + in * 8 + tg * 2;
            #pragma unroll
            for (int e = 0; e < 4; e++) {
                int m = mg0 + ((e >= 2) ? 8 : 0);
                int n = nbase + (e & 1);
                int idx = lut_s[m - n + (Ssz - 1)];
                float vv = (acc_s[in][e] + __ldg(&c2pz[(size_t)m * NPOS + idx])
                                         + __ldg(&p2cz[(size_t)n * NPOS + idx])) * SCALE2;
                acc_s[in][e] = vv;
                if (e < 2) mx0 = fmaxf(mx0, vv); else mx1 = fmaxf(mx1, vv);
            }
        }
        mx0 = fmaxf(mx0, __shfl_xor_sync(0xffffffffu, mx0, 1));
        mx0 = fmaxf(mx0, __shfl_xor_sync(0xffffffffu, mx0, 2));
        mx1 = fmaxf(mx1, __shfl_xor_sync(0xffffffffu, mx1, 1));
        mx1 = fmaxf(mx1, __shfl_xor_sync(0xffffffffu, mx1, 2));
        float mn0 = fmaxf(m_r[0], mx0), mn1 = fmaxf(m_r[1], mx1);
        float al0 = exp2f(m_r[0] - mn0), al1 = exp2f(m_r[1] - mn1);
        float s0 = 0.f, s1 = 0.f;
        uint32_t u01[8], u23[8];             // P as half2: rows g / g+8
        #pragma unroll
        for (int in = 0; in < 8; in++) {
            __half2 e01 = h2exp2(__floats2half2_rn(acc_s[in][0] - mn0, acc_s[in][1] - mn0));
            __half2 e23 = h2exp2(__floats2half2_rn(acc_s[in][2] - mn1, acc_s[in][3] - mn1));
            u01[in] = *(uint32_t*)&e01;
            u23[in] = *(uint32_t*)&e23;
            float2 f01 = __half22float2(e01);
            float2 f23 = __half22float2(e23);
            s0 += f01.x + f01.y; s1 += f23.x + f23.y;
        }
        l_r[0] = l_r[0] * al0 + s0;
        l_r[1] = l_r[1] * al1 + s1;
        m_r[0] = mn0; m_r[1] = mn1;
        #pragma unroll
        for (int nf = 0; nf < 8; nf++) {
            acc_o[nf][0] *= al0; acc_o[nf][1] *= al0;
            acc_o[nf][2] *= al1; acc_o[nf][3] *= al1;
        }

        // ---- O += P V : P half2 fragments direct from registers ----
        #pragma unroll
        for (int kc2 = 0; kc2 < 4; kc2++) {
            uint32_t af[4];
            af[0] = u01[kc2 * 2];
            af[1] = u23[kc2 * 2];
            af[2] = u01[kc2 * 2 + 1];
            af[3] = u23[kc2 * 2 + 1];
            #pragma unroll
            for (int ip = 0; ip < 4; ip++) {
                uint32_t bf[4];
                ldsm_x4(bf, sb + (uint32_t)(FA_V(buf) + (ip * 16) * STRF + boffF + kc2 * 32));
                mma_f16(acc_o[ip * 2],     af, &bf[0]);
                mma_f16(acc_o[ip * 2 + 1], af, &bf[2]);
            }
        }
    }

    float l0 = l_r[0];
    l0 += __shfl_xor_sync(0xffffffffu, l0, 1);
    l0 += __shfl_xor_sync(0xffffffffu, l0, 2);
    float l1 = l_r[1];
    l1 += __shfl_xor_sync(0xffffffffu, l1, 1);
    l1 += __shfl_xor_sync(0xffffffffu, l1, 2);
    float inv0 = 1.0f / l0, inv1 = 1.0f / l1;
    __half* c0 = ctx + ((size_t)bb * Ssz + mg0)     * Dsz + hh * DHsz;
    __half* c1 = ctx + ((size_t)bb * Ssz + mg0 + 8) * Dsz + hh * DHsz;
    #pragma unroll
    for (int nf = 0; nf < 8; nf++) {
        int col = nf * 8 + tg * 2;
        *(__half2*)&c0[col] = __floats2half2_rn(acc_o[nf][0] * inv0, acc_o[nf][1] * inv0);
        *(__half2*)&c1[col] = __floats2half2_rn(acc_o[nf][2] * inv1, acc_o[nf][3] * inv1);
    }
}

// =============================== launch ========================================
extern "C" void kernel_launch(void* const* d_in, const int* in_sizes, int n_in,
                              void* d_out, int out_size) {
    const float* x      = (const float*)d_in[0];
    const float* ln1g   = (const float*)d_in[1];
    const float* ln1b   = (const float*)d_in[2];
    const float* dww    = (const float*)d_in[3];
    const float* dwb    = (const float*)d_in[4];
    const float* pww    = (const float*)d_in[5];
    const float* pwb    = (const float*)d_in[6];
    const float* ln2g   = (const float*)d_in[7];
    const float* ln2b   = (const float*)d_in[8];
    const float* qw     = (const float*)d_in[9];
    const float* qb     = (const float*)d_in[10];
    const float* kw     = (const float*)d_in[11];
    const float* kb     = (const float*)d_in[12];
    const float* vw     = (const float*)d_in[13];
    const float* vb     = (const float*)d_in[14];
    const float* ow     = (const float*)d_in[15];
    const float* ob     = (const float*)d_in[16];
    const float* relemb = (const float*)d_in[17];
    const float* ln3g   = (const float*)d_in[18];
    const float* ln3b   = (const float*)d_in[19];
    const float* w1     = (const float*)d_in[20];
    const float* b1     = (const float*)d_in[21];
    const float* w2     = (const float*)d_in[22];
    const float* b2     = (const float*)d_in[23];
    float* out = (float*)d_out;

    float *x1, *x2, *c2p, *p2c; int* lut;
    __half *xnh, *convh, *qh, *kh, *vh, *vth, *ctxh, *ffh, *poskh, *posqh;
    __half *pwwh, *qwh, *kwh, *vwh, *owh, *w1h, *w2h;
    cudaGetSymbolAddress((void**)&x1,    g_x1);
    cudaGetSymbolAddress((void**)&x2,    g_x2);
    cudaGetSymbolAddress((void**)&c2p,   g_c2p);
    cudaGetSymbolAddress((void**)&p2c,   g_p2c);
    cudaGetSymbolAddress((void**)&lut,   g_lut);
    cudaGetSymbolAddress((void**)&xnh,   g_xnh);
    cudaGetSymbolAddress((void**)&convh, g_convh);
    cudaGetSymbolAddress((void**)&qh,    g_qh);
    cudaGetSymbolAddress((void**)&kh,    g_kh);
    cudaGetSymbolAddress((void**)&vh,    g_vh);
    cudaGetSymbolAddress((void**)&vth,   g_vth);
    cudaGetSymbolAddress((void**)&ctxh,  g_ctxh);
    cudaGetSymbolAddress((void**)&ffh,   g_ffh);
    cudaGetSymbolAddress((void**)&poskh, g_poskh);
    cudaGetSymbolAddress((void**)&posqh, g_posqh);
    cudaGetSymbolAddress((void**)&pwwh,  g_pwwh);
    cudaGetSymbolAddress((void**)&qwh,   g_qwh);
    cudaGetSymbolAddress((void**)&kwh,   g_kwh);
    cudaGetSymbolAddress((void**)&vwh,   g_vwh);
    cudaGetSymbolAddress((void**)&owh,   g_owh);
    cudaGetSymbolAddress((void**)&w1h,   g_w1h);
    cudaGetSymbolAddress((void**)&w2h,   g_w2h);

    static int attr_set = 0;
    if (!attr_set) {
        cudaFuncSetAttribute(flash_attn_kernel,
                             cudaFuncAttributeMaxDynamicSharedMemorySize, FA_SMEM);
        cudaFuncSetAttribute(gemm_mma_kernel<128,2,0,0>,
                             cudaFuncAttributeMaxDynamicSharedMemorySize, GEMM_SMEMH(128));
        cudaFuncSetAttribute(gemm_mma_kernel<128,1,4,1>,
                             cudaFuncAttributeMaxDynamicSharedMemorySize, GEMM_SMEMH(128));
        cudaFuncSetAttribute(gemm_mma_kernel<128,3,0,1>,
                             cudaFuncAttributeMaxDynamicSharedMemorySize, GEMM_SMEMH(128));
        cudaFuncSetAttribute(gemm_pos_kernel,
                             cudaFuncAttributeMaxDynamicSharedMemorySize, GEMM_SMEMH(64));
        attr_set = 1;
    }

    build_lut_kernel<<<8, 256>>>(lut);
    f2h_kernel<<<dim3(512, 1, 7), 256>>>(pww, qw, kw, vw, ow, w1, w2,
                                         pwwh, qwh, kwh, vwh, owh, w1h, w2h);

    // ---- conv block ----
    layernorm_kernel<<<NROWS, 256>>>(x, ln1g, ln1b, xnh);
    dwconv_silu_kernel<<<(Bsz*Ssz*Dsz + 255) / 256, 256>>>(xnh, dww, dwb, convh);
    gemm_mma_kernel<128,2,0,0><<<dim3(Dsz/128, NROWS/128, 1), 256, GEMM_SMEMH(128)>>>(
        convh, Dsz, pwwh, Dsz, pwb, x, x1, Dsz, Dsz,
        nullptr, nullptr, nullptr, nullptr, nullptr, nullptr);

    // ---- attention block ----
    layernorm_kernel<<<NROWS, 256>>>(x1, ln2g, ln2b, xnh);
    gemm_mma_kernel<128,1,4,1><<<dim3(Dsz/128, NROWS/128, 3), 256, GEMM_SMEMH(128)>>>(
        xnh, Dsz, qwh, Dsz, qb, nullptr, qh, Dsz, Dsz,
        kwh, vwh, kb, vb, kh, vh);
    transpose_v_kernel<<<dim3(Ssz/32, Dsz/32, Bsz), dim3(32, 8)>>>(vh, vth);

    gemm_tn_small_kernel<<<dim3(Dsz/64, 1, 2), 256>>>(
        relemb, Dsz, kw, Dsz, kb, poskh, qw, qb, posqh, Dsz, Dsz);

    gemm_pos_kernel<<<dim3(1, Ssz/128, 2*Bsz*Hsz), 256, GEMM_SMEMH(64)>>>(
        qh, poskh, c2p, kh, posqh, p2c);

    flash_attn_kernel<<<dim3(Ssz/128, 1, Bsz*Hsz), 256, FA_SMEM>>>(
        qh, kh, vth, c2p, p2c, lut, ctxh);

    gemm_mma_kernel<128,2,0,0><<<dim3(Dsz/128, NROWS/128, 1), 256, GEMM_SMEMH(128)>>>(
        ctxh, Dsz, owh, Dsz, ob, x1, x2, Dsz, Dsz,
        nullptr, nullptr, nullptr, nullptr, nullptr, nullptr);

    // ---- FFN block ----
    layernorm_kernel<<<NROWS, 256>>>(x2, ln3g, ln3b, xnh);
    gemm_mma_kernel<128,3,0,1><<<dim3(FFsz/128, NROWS/128, 1), 256, GEMM_SMEMH(128)>>>(
        xnh, Dsz, w1h, Dsz, b1, nullptr, ffh, FFsz, Dsz,
        nullptr, nullptr, nullptr, nullptr, nullptr, nullptr);
    gemm_mma_kernel<128,2,0,0><<<dim3(Dsz/128, NROWS/128, 1), 256, GEMM_SMEMH(128)>>>(
        ffh, FFsz, w2h, FFsz, b2, x2, out, Dsz, FFsz,
        nullptr, nullptr, nullptr, nullptr, nullptr, nullptr);
}

// round 13
// speedup vs baseline: 1.5365x; 1.1113x over previous
#include <cuda_runtime.h>
#include <cuda_fp16.h>
#include <math.h>
#include <stdint.h>

#define Bsz 8
#define Ssz 1024
#define Dsz 512
#define Hsz 8
#define DHsz 64
#define FFsz 1024
#define NPOS 64          // 2*SPAN
#define NROWS (Bsz*Ssz)  // 8192

// ---------------- scratch (device globals; no allocation allowed) ------------
__device__ float  g_x1  [Bsz*Ssz*Dsz];
__device__ float  g_x2  [Bsz*Ssz*Dsz];
__device__ float  g_c2p [Bsz*Hsz*Ssz*NPOS];
__device__ float  g_p2c [Bsz*Hsz*Ssz*NPOS];
__device__ int    g_lut [2*Ssz];
__device__ __half g_xnh  [Bsz*Ssz*Dsz];
__device__ __half g_convh[Bsz*Ssz*Dsz];
__device__ __half g_qh   [Bsz*Ssz*Dsz];
__device__ __half g_kh   [Bsz*Ssz*Dsz];
__device__ __half g_vh   [Bsz*Ssz*Dsz];
__device__ __half g_vth  [Bsz*Ssz*Dsz];   // [B, D, S]
__device__ __half g_ctxh [Bsz*Ssz*Dsz];
__device__ __half g_ffh  [Bsz*Ssz*FFsz];
__device__ __half g_poskh[NPOS*Dsz];
__device__ __half g_posqh[NPOS*Dsz];
__device__ __half g_pwwh[Dsz*Dsz];
__device__ __half g_qwh [Dsz*Dsz];
__device__ __half g_kwh [Dsz*Dsz];
__device__ __half g_vwh [Dsz*Dsz];
__device__ __half g_owh [Dsz*Dsz];
__device__ __half g_w1h [FFsz*Dsz];
__device__ __half g_w2h [FFsz*Dsz];

// ---------------- half2 silu helper ---------------------------------------------
__device__ __forceinline__ __half2 silu_h2(__half2 hv) {
    const __half2 nl2e = __floats2half2_rn(-1.4426950408889634f, -1.4426950408889634f);
    const __half2 one2 = __floats2half2_rn(1.0f, 1.0f);
    return __hmul2(hv, h2rcp(__hadd2(one2, h2exp2(__hmul2(hv, nl2e)))));
}

// ---------------- weight fp32 -> fp16 ------------------------------------------
__global__ void f2h_kernel(const float* __restrict__ s0, const float* __restrict__ s1,
                           const float* __restrict__ s2, const float* __restrict__ s3,
                           const float* __restrict__ s4, const float* __restrict__ s5,
                           const float* __restrict__ s6,
                           __half* d0, __half* d1, __half* d2, __half* d3,
                           __half* d4, __half* d5, __half* d6) {
    int z = blockIdx.z;
    const float* s; __half* d; int n;
    switch (z) {
        case 0: s = s0; d = d0; n = Dsz*Dsz;  break;
        case 1: s = s1; d = d1; n = Dsz*Dsz;  break;
        case 2: s = s2; d = d2; n = Dsz*Dsz;  break;
        case 3: s = s3; d = d3; n = Dsz*Dsz;  break;
        case 4: s = s4; d = d4; n = Dsz*Dsz;  break;
        case 5: s = s5; d = d5; n = FFsz*Dsz; break;
        default:s = s6; d = d6; n = FFsz*Dsz; break;
    }
    for (int i = blockIdx.x * blockDim.x + threadIdx.x; i * 2 < n; i += gridDim.x * blockDim.x) {
        float2 f = *(const float2*)&s[i * 2];
        *(__half2*)&d[i * 2] = __floats2half2_rn(f.x, f.y);
    }
}

// ---------------- relative-position bucket LUT --------------------------------
__global__ void build_lut_kernel(int* __restrict__ lut) {
    int t = blockIdx.x * blockDim.x + threadIdx.x;
    if (t >= 2*Ssz - 1) return;
    int rel = t - (Ssz - 1);   // i - j
    const int mid = 16;        // BUCKETS/2
    int bucket;
    if (rel > -mid && rel < mid) {
        bucket = rel;
    } else {
        float absp = fabsf((float)rel);
        if (absp <= (float)mid) {
            bucket = rel;
        } else {
            float logp = ceilf(logf(absp / 16.0f) / logf(127.0f / 16.0f) * 15.0f) + 16.0f;
            bucket = (rel > 0 ? 1 : -1) * (int)logp;
        }
    }
    int idx = bucket + 32;
    idx = min(max(idx, 0), 63);
    lut[t] = idx;
}

// ---------------- LayerNorm (D=512, one block per row) -> half -----------------
__global__ void layernorm_kernel(const float* __restrict__ x,
                                 const float* __restrict__ g,
                                 const float* __restrict__ bb,
                                 __half* __restrict__ out) {
    const float* xr = x + (size_t)blockIdx.x * Dsz;
    __half* orow = out + (size_t)blockIdx.x * Dsz;
    int tid = threadIdx.x;  // 256
    float2 v = *(const float2*)&xr[tid * 2];
    float s = v.x + v.y, ss = v.x * v.x + v.y * v.y;
    __shared__ float r1[8], r2[8];
    #pragma unroll
    for (int o = 16; o; o >>= 1) {
        s  += __shfl_xor_sync(0xffffffffu, s, o);
        ss += __shfl_xor_sync(0xffffffffu, ss, o);
    }
    if ((tid & 31) == 0) { r1[tid >> 5] = s; r2[tid >> 5] = ss; }
    __syncthreads();
    float S1 = 0.f, S2 = 0.f;
    #pragma unroll
    for (int i = 0; i < 8; i++) { S1 += r1[i]; S2 += r2[i]; }
    float mean = S1 * (1.0f / Dsz);
    float var  = S2 * (1.0f / Dsz) - mean * mean;
    float rs = rsqrtf(var + 1e-5f);
    float2 gg = *(const float2*)&g[tid * 2];
    float2 bv = *(const float2*)&bb[tid * 2];
    *(__half2*)&orow[tid * 2] = __floats2half2_rn(
        (v.x - mean) * rs * gg.x + bv.x,
        (v.y - mean) * rs * gg.y + bv.y);
}

// ---------------- depthwise conv (K=3 along S) + bias + SiLU (half2) -----------
__global__ void dwconv_silu_kernel(const __half* __restrict__ xn,
                                   const float* __restrict__ w,
                                   const float* __restrict__ bias,
                                   __half* __restrict__ out) {
    size_t idx = (size_t)blockIdx.x * blockDim.x + threadIdx.x;   // half2 index
    if (idx >= (size_t)Bsz * Ssz * Dsz / 2) return;
    int d2 = (int)(idx % (Dsz / 2));
    int s  = (int)((idx / (Dsz / 2)) % Ssz);
    int d  = d2 * 2;
    const __half2* base = (const __half2*)xn + idx;
    float w00 = w[d*3+0], w01 = w[d*3+1], w02 = w[d*3+2];
    float w10 = w[d*3+3], w11 = w[d*3+4], w12 = w[d*3+5];
    float2 c = __half22float2(base[0]);
    float a0 = bias[d]   + c.x * w01;
    float a1 = bias[d+1] + c.y * w11;
    if (s > 0)       { float2 p = __half22float2(base[-(Dsz/2)]); a0 += p.x * w00; a1 += p.y * w10; }
    if (s < Ssz - 1) { float2 q = __half22float2(base[  Dsz/2 ]); a0 += q.x * w02; a1 += q.y * w12; }
    ((__half2*)out)[idx] = silu_h2(__floats2half2_rn(a0, a1));
}

// ---------------- V transpose: [B,S,D] -> [B,D,S] (half2 both sides) -----------
__global__ void transpose_v_kernel(const __half* __restrict__ v, __half* __restrict__ vt) {
    __shared__ __half tile[64][66];
    int b = blockIdx.z;
    int s0 = blockIdx.x * 64, d0 = blockIdx.y * 64;
    int tx = threadIdx.x & 31, ty = threadIdx.x >> 5;   // 32 x 8
    #pragma unroll
    for (int j = 0; j < 64; j += 8) {
        __half2 hv = *(const __half2*)&v[((size_t)b * Ssz + s0 + ty + j) * Dsz + d0 + tx * 2];
        tile[ty + j][tx * 2]     = __low2half(hv);
        tile[ty + j][tx * 2 + 1] = __high2half(hv);
    }
    __syncthreads();
    #pragma unroll
    for (int j = 0; j < 64; j += 8) {
        int d = ty + j;
        __half2 hv = __halves2half2(tile[tx * 2][d], tile[tx * 2 + 1][d]);
        *(__half2*)&vt[((size_t)b * Dsz + d0 + d) * Ssz + s0 + tx * 2] = hv;
    }
}

// ---------------- mma.f16 + ldmatrix helpers -----------------------------------
__device__ __forceinline__ void mma_f16(float c[4], const uint32_t a[4], const uint32_t b[2]) {
    asm volatile(
        "mma.sync.aligned.m16n8k16.row.col.f32.f16.f16.f32 "
        "{%0,%1,%2,%3}, {%4,%5,%6,%7}, {%8,%9}, {%0,%1,%2,%3};"
        : "+f"(c[0]), "+f"(c[1]), "+f"(c[2]), "+f"(c[3])
        : "r"(a[0]), "r"(a[1]), "r"(a[2]), "r"(a[3]), "r"(b[0]), "r"(b[1]));
}

__device__ __forceinline__ void ldsm_x4(uint32_t r[4], uint32_t addr) {
    asm volatile("ldmatrix.sync.aligned.m8n8.x4.shared.b16 {%0,%1,%2,%3}, [%4];"
                 : "=r"(r[0]), "=r"(r[1]), "=r"(r[2]), "=r"(r[3]) : "r"(addr));
}

#define CP_ASYNC16(dst_u32, src_ptr) \
    asm volatile("cp.async.ca.shared.global [%0], [%1], 16;" :: "r"(dst_u32), "l"(src_ptr))
#define CP_COMMIT() asm volatile("cp.async.commit_group;")
#define CP_WAIT2()  asm volatile("cp.async.wait_group 2;")
#define CP_WAIT1()  asm volatile("cp.async.wait_group 1;")
#define CP_WAIT0()  asm volatile("cp.async.wait_group 0;")

// ---------------- fp16 tensor-core TN GEMM (128xCN tiles, K32 chunks) ----------
#define STRB 80                      // bytes per 32-half row (64B data + 16B pad)
#define NSTAGE 4
#define GEMM_SMEMH(CNv) (NSTAGE * (128 + (CNv)) * STRB)

template<int CN, int EPI, int MODE, int OUTH>
__global__ void __launch_bounds__(256, 2) gemm_mma_kernel(
    const __half* __restrict__ A0, int lda,
    const __half* __restrict__ W0, int ldw,
    const float* __restrict__ bias0, const float* __restrict__ res,
    void* __restrict__ C0v, int ldc, int K,
    const __half* __restrict__ Wa, const __half* __restrict__ Wb2,
    const float* __restrict__ ba, const float* __restrict__ bb2,
    void* __restrict__ Cav, void* __restrict__ Cbv)
{
    constexpr int NWN = CN / 32;
    constexpr int NWM = 8 / NWN;
    constexpr int MT  = 8 / NWM;

    extern __shared__ char smem[];
    const uint32_t sb = (uint32_t)__cvta_generic_to_shared(smem);
    const uint32_t sA = sb;
    const uint32_t sW = sb + NSTAGE * 128 * STRB;

    const int tid  = threadIdx.x;
    const int wid  = tid >> 5, lane = tid & 31;
    const int g    = lane >> 2, tg = lane & 3;
    const int wm   = wid % NWM, wn = wid / NWM;

    const int z = blockIdx.z;
    const __half* A = A0; const __half* W = W0; void* Cv = C0v;
    const float* bias = bias0;
    if (MODE == 4) {
        W    = (z == 0) ? W0 : (z == 1 ? Wa : Wb2);
        bias = (z == 0) ? bias0 : (z == 1 ? ba : bb2);
        Cv   = (z == 0) ? C0v : (z == 1 ? Cav : Cbv);
    }

    const int m_cta = blockIdx.y * 128, n_cta = blockIdx.x * CN;

    auto fetch = [&](int t, int buf) {
        int k0 = t * 32;
        #pragma unroll
        for (int r = 0; r < 2; r++) {
            int id = tid + 256 * r;
            int row = id >> 2, ch = id & 3;
            CP_ASYNC16(sA + (uint32_t)(buf * 128 * STRB + row * STRB + ch * 16),
                       A + (size_t)(m_cta + row) * lda + k0 + ch * 8);
        }
        #pragma unroll
        for (int r = 0; r < CN / 64; r++) {
            int id = tid + 256 * r;
            int row = id >> 2, ch = id & 3;
            CP_ASYNC16(sW + (uint32_t)(buf * CN * STRB + row * STRB + ch * 16),
                       W + (size_t)(n_cta + row) * ldw + k0 + ch * 8);
        }
        CP_COMMIT();
    };

    const int lq = lane >> 3, lr = lane & 7;
    const int aoff = ((lq & 1) * 8 + lr) * STRB + (lq >> 1) * 16;
    const int boff = ((lq >> 1) * 8 + lr) * STRB + (lq & 1) * 16;

    float acc[MT][4][4] = {};

    const int T = K / 32;
    fetch(0, 0);
    fetch(1, 1);
    if (T > 2) fetch(2, 2);
    for (int it = 0; it < T; it++) {
        const int buf = it & (NSTAGE - 1);
        if (it < T - 2)       { CP_WAIT2(); }
        else if (it == T - 2) { CP_WAIT1(); }
        else                  { CP_WAIT0(); }
        __syncthreads();
        if (it + 3 < T) fetch(it + 3, (it + 3) & (NSTAGE - 1));

        const uint32_t bA = sA + (uint32_t)(buf * 128 * STRB);
        const uint32_t bW = sW + (uint32_t)(buf * CN  * STRB);
        #pragma unroll
        for (int ks = 0; ks < 2; ks++) {
            const int kb = ks * 32;
            uint32_t af[MT][4];
            #pragma unroll
            for (int im = 0; im < MT; im++)
                ldsm_x4(af[im], bA + (uint32_t)((wm * MT * 16 + im * 16) * STRB + aoff + kb));
            uint32_t bf[2][4];
            #pragma unroll
            for (int ip = 0; ip < 2; ip++)
                ldsm_x4(bf[ip], bW + (uint32_t)((wn * 32 + ip * 16) * STRB + boff + kb));
            #pragma unroll
            for (int im = 0; im < MT; im++)
                #pragma unroll
                for (int in = 0; in < 4; in++)
                    mma_f16(acc[im][in], af[im], &bf[in >> 1][(in & 1) * 2]);
        }
    }

    // vectorized epilogue (float2 / half2 pairs)
    #pragma unroll
    for (int im = 0; im < MT; im++) {
        int mrow0 = m_cta + wm * MT * 16 + im * 16 + g;
        #pragma unroll
        for (int in = 0; in < 4; in++) {
            int ncol0 = n_cta + wn * 32 + in * 8 + tg * 2;
            float2 bv = make_float2(0.f, 0.f);
            if (EPI >= 1) bv = *(const float2*)&bias[ncol0];
            #pragma unroll
            for (int h = 0; h < 2; h++) {
                int m = mrow0 + h * 8;
                float v0 = acc[im][in][h * 2 + 0];
                float v1 = acc[im][in][h * 2 + 1];
                if (EPI >= 1) { v0 += bv.x; v1 += bv.y; }
                if (EPI == 2) {
                    float2 rv = *(const float2*)&res[(size_t)m * ldc + ncol0];
                    v0 += rv.x; v1 += rv.y;
                }
                if (OUTH) {
                    __half2 hv = __floats2half2_rn(v0, v1);
                    if (EPI == 3) hv = silu_h2(hv);
                    *(__half2*)&((__half*)Cv)[(size_t)m * ldc + ncol0] = hv;
                } else {
                    *(float2*)&((float*)Cv)[(size_t)m * ldc + ncol0] = make_float2(v0, v1);
                }
            }
        }
    }
}

// ---------------- fp16 mma GEMM for pos projections (N=64, K=64) ---------------
__global__ void __launch_bounds__(256, 2) gemm_pos_kernel(
    const __half* __restrict__ A0,
    const __half* __restrict__ W0,
    float* __restrict__ C0,
    const __half* __restrict__ Aa, const __half* __restrict__ Wa,
    float* __restrict__ Ca)
{
    extern __shared__ char smem[];
    const uint32_t sb = (uint32_t)__cvta_generic_to_shared(smem);
    const uint32_t sA = sb;
    const uint32_t sW = sb + NSTAGE * 128 * STRB;

    const int tid  = threadIdx.x;
    const int wid  = tid >> 5, lane = tid & 31;
    const int g    = lane >> 2, tg = lane & 3;
    const int wm   = wid & 3, wn = wid >> 2;

    int zz = blockIdx.z & 63, sel = blockIdx.z >> 6;
    int bb = zz >> 3, hh = zz & 7;
    const __half* A = (sel ? Aa : A0) + (size_t)bb * Ssz * Dsz + hh * DHsz;
    const __half* W = (sel ? Wa : W0) + hh * DHsz;
    float* C = (sel ? Ca : C0) + (size_t)zz * Ssz * NPOS;

    const int m_cta = blockIdx.y * 128;

    auto fetch = [&](int t, int buf) {
        int k0 = t * 32;
        #pragma unroll
        for (int r = 0; r < 2; r++) {
            int id = tid + 256 * r;
            int row = id >> 2, ch = id & 3;
            CP_ASYNC16(sA + (uint32_t)(buf * 128 * STRB + row * STRB + ch * 16),
                       A + (size_t)(m_cta + row) * Dsz + k0 + ch * 8);
        }
        {
            int row = tid >> 2, ch = tid & 3;
            if (row < 64)
                CP_ASYNC16(sW + (uint32_t)(buf * 64 * STRB + row * STRB + ch * 16),
                           W + (size_t)row * Dsz + k0 + ch * 8);
        }
        CP_COMMIT();
    };

    const int lq = lane >> 3, lr = lane & 7;
    const int aoff = ((lq & 1) * 8 + lr) * STRB + (lq >> 1) * 16;
    const int boff = ((lq >> 1) * 8 + lr) * STRB + (lq & 1) * 16;

    float acc[2][4][4] = {};
    const int T = 2;   // K=64
    fetch(0, 0); fetch(1, 1);
    for (int it = 0; it < T; it++) {
        const int buf = it & (NSTAGE - 1);
        if (it == T - 2) { CP_WAIT1(); } else { CP_WAIT0(); }
        __syncthreads();

        const uint32_t bA = sA + (uint32_t)(buf * 128 * STRB);
        const uint32_t bW = sW + (uint32_t)(buf * 64  * STRB);
        #pragma unroll
        for (int ks = 0; ks < 2; ks++) {
            const int kb = ks * 32;
            uint32_t af[2][4];
            #pragma unroll
            for (int im = 0; im < 2; im++)
                ldsm_x4(af[im], bA + (uint32_t)((wm * 32 + im * 16) * STRB + aoff + kb));
            uint32_t bf[2][4];
            #pragma unroll
            for (int ip = 0; ip < 2; ip++)
                ldsm_x4(bf[ip], bW + (uint32_t)((wn * 32 + ip * 16) * STRB + boff + kb));
            #pragma unroll
            for (int im = 0; im < 2; im++)
                #pragma unroll
                for (int in = 0; in < 4; in++)
                    mma_f16(acc[im][in], af[im], &bf[in >> 1][(in & 1) * 2]);
        }
    }

    #pragma unroll
    for (int im = 0; im < 2; im++) {
        int mrow0 = m_cta + wm * 32 + im * 16 + g;
        #pragma unroll
        for (int in = 0; in < 4; in++) {
            int ncol0 = wn * 32 + in * 8 + tg * 2;
            #pragma unroll
            for (int h = 0; h < 2; h++) {
                int m = mrow0 + h * 8;
                *(float2*)&C[(size_t)m * NPOS + ncol0] =
                    make_float2(acc[im][in][h * 2], acc[im][in][h * 2 + 1]);
            }
        }
    }
}

// ---------------- small SIMT GEMM (pos-emb projections, fp32 in, half out) -----
#define TK 16
#define TPAD 68
__global__ void gemm_tn_small_kernel(const float* __restrict__ A, int lda,
                                     const float* __restrict__ W0, int ldw,
                                     const float* __restrict__ b0,
                                     __half* __restrict__ C0,
                                     const float* __restrict__ W1,
                                     const float* __restrict__ b1,
                                     __half* __restrict__ C1, int ldc, int Kd) {
    const float* W   = blockIdx.z ? W1 : W0;
    const float* bias= blockIdx.z ? b1 : b0;
    __half* C        = blockIdx.z ? C1 : C0;
    int m0 = blockIdx.y * 64, n0 = blockIdx.x * 64;
    __shared__ float As[TK][TPAD];
    __shared__ float Ws2[TK][TPAD];
    const int tid = threadIdx.x;
    const int tx = tid & 15, ty = tid >> 4;
    const int lk = tid & 15, lm = tid >> 4;
    float acc[4][4] = {};
    for (int k0 = 0; k0 < Kd; k0 += TK) {
        #pragma unroll
        for (int r = 0; r < 4; r++) {
            As[lk][lm + 16 * r]  = A[(size_t)(m0 + lm + 16 * r) * lda + k0 + lk];
            Ws2[lk][lm + 16 * r] = W[(size_t)(n0 + lm + 16 * r) * ldw + k0 + lk];
        }
        __syncthreads();
        #pragma unroll
        for (int kk = 0; kk < TK; kk++) {
            float4 a = *(const float4*)&As[kk][ty * 4];
            float4 b = *(const float4*)&Ws2[kk][tx * 4];
            float av[4] = {a.x, a.y, a.z, a.w};
            float bv[4] = {b.x, b.y, b.z, b.w};
            #pragma unroll
            for (int i = 0; i < 4; i++)
                #pragma unroll
                for (int j = 0; j < 4; j++)
                    acc[i][j] += av[i] * bv[j];
        }
        __syncthreads();
    }
    #pragma unroll
    for (int i = 0; i < 4; i++) {
        int m = m0 + ty * 4 + i;
        #pragma unroll
        for (int j = 0; j < 4; j += 2) {
            int n = n0 + tx * 4 + j;
            *(__half2*)&C[(size_t)m * ldc + n] =
                __floats2half2_rn(acc[i][j] + bias[n], acc[i][j+1] + bias[n+1]);
        }
    }
}

// =========================== fused flash attention (fp16 mma) ==================
#define STRF 144                      // bytes per 64-half row (128B data + 16B pad)
#define FA_K(buf) ((buf) * 64 * STRF)
#define FA_V(buf) (2 * 64 * STRF + (buf) * 64 * STRF)
#define FA_Q      (4 * 64 * STRF)
#define FA_LUT    (4 * 64 * STRF + 128 * STRF)
#define FA_SMEM   (FA_LUT + 2048 * 4)

__global__ void __launch_bounds__(256, 2) flash_attn_kernel(
    const __half* __restrict__ qg, const __half* __restrict__ kg,
    const __half* __restrict__ vt,
    const float* __restrict__ c2p, const float* __restrict__ p2c,
    const int* __restrict__ lut, __half* __restrict__ ctx)
{
    extern __shared__ char smc[];
    int* lut_s = (int*)(smc + FA_LUT);

    const int tid = threadIdx.x, w = tid >> 5, lane = tid & 31;
    const int g = lane >> 2, tg = lane & 3;
    const int z = blockIdx.z, bb = z >> 3, hh = z & 7;
    const int i0 = blockIdx.x * 128;

    const float* c2pz = c2p + (size_t)z * Ssz * NPOS;
    const float* p2cz = p2c + (size_t)z * Ssz * NPOS;

    const uint32_t sb = (uint32_t)__cvta_generic_to_shared(smc);

    #pragma unroll
    for (int t = 0; t < 8; t++) {
        int idx = tid + 256 * t;
        if (idx < 2 * Ssz - 1) lut_s[idx] = lut[idx];
    }

    auto loadKV = [&](int jt, int buf) {
        int j0 = jt * 64;
        #pragma unroll
        for (int c = 0; c < 2; c++) {
            int id = tid * 2 + c;
            int row = id >> 3, ch = id & 7;
            CP_ASYNC16(sb + (uint32_t)(FA_K(buf) + row * STRF + ch * 16),
                       kg + ((size_t)bb * Ssz + j0 + row) * Dsz + hh * DHsz + ch * 8);
        }
        #pragma unroll
        for (int c = 0; c < 2; c++) {
            int id = tid * 2 + c;
            int row = id >> 3, ch = id & 7;
            CP_ASYNC16(sb + (uint32_t)(FA_V(buf) + row * STRF + ch * 16),
                       vt + ((size_t)bb * Dsz + hh * DHsz + row) * Ssz + j0 + ch * 8);
        }
        CP_COMMIT();
    };

    #pragma unroll
    for (int c = 0; c < 4; c++) {
        int id = tid * 4 + c;
        int row = id >> 3, ch = id & 7;
        CP_ASYNC16(sb + (uint32_t)(FA_Q + row * STRF + ch * 16),
                   qg + ((size_t)bb * Ssz + i0 + row) * Dsz + hh * DHsz + ch * 8);
    }
    CP_COMMIT();
    loadKV(0, 0);

    CP_WAIT1();
    __syncthreads();

    const int lq = lane >> 3, lr = lane & 7;
    const int aoffF = ((lq & 1) * 8 + lr) * STRF + (lq >> 1) * 16;
    const int boffF = ((lq >> 1) * 8 + lr) * STRF + (lq & 1) * 16;

    uint32_t qf[4][4];
    #pragma unroll
    for (int kc = 0; kc < 4; kc++)
        ldsm_x4(qf[kc], sb + (uint32_t)(FA_Q + (w * 16) * STRF + aoffF + kc * 32));

    float acc_o[8][4] = {};
    float m_r[2] = {-1e30f, -1e30f};
    float l_r[2] = {0.f, 0.f};
    const float SCALE2 = 0.07216878364870323f * 1.4426950408889634f;  // log2 domain
    const int mg0 = i0 + w * 16 + g;

    for (int jt = 0; jt < 16; jt++) {
        const int buf = jt & 1;
        const int j0 = jt * 64;
        CP_WAIT0();
        __syncthreads();
        if (jt < 15) loadKV(jt + 1, buf ^ 1);

        float acc_s[8][4] = {};
        #pragma unroll
        for (int kc = 0; kc < 4; kc++) {
            #pragma unroll
            for (int ip = 0; ip < 4; ip++) {
                uint32_t bf[4];
                ldsm_x4(bf, sb + (uint32_t)(FA_K(buf) + (ip * 16) * STRF + boffF + kc * 32));
                mma_f16(acc_s[ip * 2],     qf[kc], &bf[0]);
                mma_f16(acc_s[ip * 2 + 1], qf[kc], &bf[2]);
            }
        }

        float mx0 = -1e30f, mx1 = -1e30f;
        #pragma unroll
        for (int in = 0; in < 8; in++) {
            int nbase = j0 + in * 8 + tg * 2;
            #pragma unroll
            for (int e = 0; e < 4; e++) {
                int m = mg0 + ((e >= 2) ? 8 : 0);
                int n = nbase + (e & 1);
                int idx = lut_s[m - n + (Ssz - 1)];
                float vv = (acc_s[in][e] + __ldg(&c2pz[(size_t)m * NPOS + idx])
                                         + __ldg(&p2cz[(size_t)n * NPOS + idx])) * SCALE2;
                acc_s[in][e] = vv;
                if (e < 2) mx0 = fmaxf(mx0, vv); else mx1 = fmaxf(mx1, vv);
            }
        }
        mx0 = fmaxf(mx0, __shfl_xor_sync(0xffffffffu, mx0, 1));
        mx0 = fmaxf(mx0, __shfl_xor_sync(0xffffffffu, mx0, 2));
        mx1 = fmaxf(mx1, __shfl_xor_sync(0xffffffffu, mx1, 1));
        mx1 = fmaxf(mx1, __shfl_xor_sync(0xffffffffu, mx1, 2));
        float mn0 = fmaxf(m_r[0], mx0), mn1 = fmaxf(m_r[1], mx1);
        float al0 = exp2f(m_r[0] - mn0), al1 = exp2f(m_r[1] - mn1);
        float s0 = 0.f, s1 = 0.f;
        uint32_t u01[8], u23[8];
        #pragma unroll
        for (int in = 0; in < 8; in++) {
            __half2 e01 = h2exp2(__floats2half2_rn(acc_s[in][0] - mn0, acc_s[in][1] - mn0));
            __half2 e23 = h2exp2(__floats2half2_rn(acc_s[in][2] - mn1, acc_s[in][3] - mn1));
            u01[in] = *(uint32_t*)&e01;
            u23[in] = *(uint32_t*)&e23;
            float2 f01 = __half22float2(e01);
            float2 f23 = __half22float2(e23);
            s0 += f01.x + f01.y; s1 += f23.x + f23.y;
        }
        l_r[0] = l_r[0] * al0 + s0;
        l_r[1] = l_r[1] * al1 + s1;
        m_r[0] = mn0; m_r[1] = mn1;
        #pragma unroll
        for (int nf = 0; nf < 8; nf++) {
            acc_o[nf][0] *= al0; acc_o[nf][1] *= al0;
            acc_o[nf][2] *= al1; acc_o[nf][3] *= al1;
        }

        #pragma unroll
        for (int kc2 = 0; kc2 < 4; kc2++) {
            uint32_t af[4];
            af[0] = u01[kc2 * 2];
            af[1] = u23[kc2 * 2];
            af[2] = u01[kc2 * 2 + 1];
            af[3] = u23[kc2 * 2 + 1];
            #pragma unroll
            for (int ip = 0; ip < 4; ip++) {
                uint32_t bf[4];
                ldsm_x4(bf, sb + (uint32_t)(FA_V(buf) + (ip * 16) * STRF + boffF + kc2 * 32));
                mma_f16(acc_o[ip * 2],     af, &bf[0]);
                mma_f16(acc_o[ip * 2 + 1], af, &bf[2]);
            }
        }
    }

    float l0 = l_r[0];
    l0 += __shfl_xor_sync(0xffffffffu, l0, 1);
    l0 += __shfl_xor_sync(0xffffffffu, l0, 2);
    float l1 = l_r[1];
    l1 += __shfl_xor_sync(0xffffffffu, l1, 1);
    l1 += __shfl_xor_sync(0xffffffffu, l1, 2);
    float inv0 = 1.0f / l0, inv1 = 1.0f / l1;
    __half* c0 = ctx + ((size_t)bb * Ssz + mg0)     * Dsz + hh * DHsz;
    __half* c1 = ctx + ((size_t)bb * Ssz + mg0 + 8) * Dsz + hh * DHsz;
    #pragma unroll
    for (int nf = 0; nf < 8; nf++) {
        int col = nf * 8 + tg * 2;
        *(__half2*)&c0[col] = __floats2half2_rn(acc_o[nf][0] * inv0, acc_o[nf][1] * inv0);
        *(__half2*)&c1[col] = __floats2half2_rn(acc_o[nf][2] * inv1, acc_o[nf][3] * inv1);
    }
}

// =============================== launch ========================================
extern "C" void kernel_launch(void* const* d_in, const int* in_sizes, int n_in,
                              void* d_out, int out_size) {
    const float* x      = (const float*)d_in[0];
    const float* ln1g   = (const float*)d_in[1];
    const float* ln1b   = (const float*)d_in[2];
    const float* dww    = (const float*)d_in[3];
    const float* dwb    = (const float*)d_in[4];
    const float* pww    = (const float*)d_in[5];
    const float* pwb    = (const float*)d_in[6];
    const float* ln2g   = (const float*)d_in[7];
    const float* ln2b   = (const float*)d_in[8];
    const float* qw     = (const float*)d_in[9];
    const float* qb     = (const float*)d_in[10];
    const float* kw     = (const float*)d_in[11];
    const float* kb     = (const float*)d_in[12];
    const float* vw     = (const float*)d_in[13];
    const float* vb     = (const float*)d_in[14];
    const float* ow     = (const float*)d_in[15];
    const float* ob     = (const float*)d_in[16];
    const float* relemb = (const float*)d_in[17];
    const float* ln3g   = (const float*)d_in[18];
    const float* ln3b   = (const float*)d_in[19];
    const float* w1     = (const float*)d_in[20];
    const float* b1     = (const float*)d_in[21];
    const float* w2     = (const float*)d_in[22];
    const float* b2     = (const float*)d_in[23];
    float* out = (float*)d_out;

    float *x1, *x2, *c2p, *p2c; int* lut;
    __half *xnh, *convh, *qh, *kh, *vh, *vth, *ctxh, *ffh, *poskh, *posqh;
    __half *pwwh, *qwh, *kwh, *vwh, *owh, *w1h, *w2h;
    cudaGetSymbolAddress((void**)&x1,    g_x1);
    cudaGetSymbolAddress((void**)&x2,    g_x2);
    cudaGetSymbolAddress((void**)&c2p,   g_c2p);
    cudaGetSymbolAddress((void**)&p2c,   g_p2c);
    cudaGetSymbolAddress((void**)&lut,   g_lut);
    cudaGetSymbolAddress((void**)&xnh,   g_xnh);
    cudaGetSymbolAddress((void**)&convh, g_convh);
    cudaGetSymbolAddress((void**)&qh,    g_qh);
    cudaGetSymbolAddress((void**)&kh,    g_kh);
    cudaGetSymbolAddress((void**)&vh,    g_vh);
    cudaGetSymbolAddress((void**)&vth,   g_vth);
    cudaGetSymbolAddress((void**)&ctxh,  g_ctxh);
    cudaGetSymbolAddress((void**)&ffh,   g_ffh);
    cudaGetSymbolAddress((void**)&poskh, g_poskh);
    cudaGetSymbolAddress((void**)&posqh, g_posqh);
    cudaGetSymbolAddress((void**)&pwwh,  g_pwwh);
    cudaGetSymbolAddress((void**)&qwh,   g_qwh);
    cudaGetSymbolAddress((void**)&kwh,   g_kwh);
    cudaGetSymbolAddress((void**)&vwh,   g_vwh);
    cudaGetSymbolAddress((void**)&owh,   g_owh);
    cudaGetSymbolAddress((void**)&w1h,   g_w1h);
    cudaGetSymbolAddress((void**)&w2h,   g_w2h);

    static int attr_set = 0;
    if (!attr_set) {
        cudaFuncSetAttribute(flash_attn_kernel,
                             cudaFuncAttributeMaxDynamicSharedMemorySize, FA_SMEM);
        cudaFuncSetAttribute(gemm_mma_kernel<128,2,0,0>,
                             cudaFuncAttributeMaxDynamicSharedMemorySize, GEMM_SMEMH(128));
        cudaFuncSetAttribute(gemm_mma_kernel<128,1,4,1>,
                             cudaFuncAttributeMaxDynamicSharedMemorySize, GEMM_SMEMH(128));
        cudaFuncSetAttribute(gemm_mma_kernel<128,3,0,1>,
                             cudaFuncAttributeMaxDynamicSharedMemorySize, GEMM_SMEMH(128));
        cudaFuncSetAttribute(gemm_pos_kernel,
                             cudaFuncAttributeMaxDynamicSharedMemorySize, GEMM_SMEMH(64));
        attr_set = 1;
    }

    build_lut_kernel<<<8, 256>>>(lut);
    f2h_kernel<<<dim3(256, 1, 7), 256>>>(pww, qw, kw, vw, ow, w1, w2,
                                         pwwh, qwh, kwh, vwh, owh, w1h, w2h);

    // ---- conv block ----
    layernorm_kernel<<<NROWS, 256>>>(x, ln1g, ln1b, xnh);
    dwconv_silu_kernel<<<(Bsz*Ssz*Dsz/2 + 255) / 256, 256>>>(xnh, dww, dwb, convh);
    gemm_mma_kernel<128,2,0,0><<<dim3(Dsz/128, NROWS/128, 1), 256, GEMM_SMEMH(128)>>>(
        convh, Dsz, pwwh, Dsz, pwb, x, x1, Dsz, Dsz,
        nullptr, nullptr, nullptr, nullptr, nullptr, nullptr);

    // ---- attention block ----
    layernorm_kernel<<<NROWS, 256>>>(x1, ln2g, ln2b, xnh);
    gemm_mma_kernel<128,1,4,1><<<dim3(Dsz/128, NROWS/128, 3), 256, GEMM_SMEMH(128)>>>(
        xnh, Dsz, qwh, Dsz, qb, nullptr, qh, Dsz, Dsz,
        kwh, vwh, kb, vb, kh, vh);
    transpose_v_kernel<<<dim3(Ssz/64, Dsz/64, Bsz), 256>>>(vh, vth);

    gemm_tn_small_kernel<<<dim3(Dsz/64, 1, 2), 256>>>(
        relemb, Dsz, kw, Dsz, kb, poskh, qw, qb, posqh, Dsz, Dsz);

    gemm_pos_kernel<<<dim3(1, Ssz/128, 2*Bsz*Hsz), 256, GEMM_SMEMH(64)>>>(
        qh, poskh, c2p, kh, posqh, p2c);

    flash_attn_kernel<<<dim3(Ssz/128, 1, Bsz*Hsz), 256, FA_SMEM>>>(
        qh, kh, vth, c2p, p2c, lut, ctxh);

    gemm_mma_kernel<128,2,0,0><<<dim3(Dsz/128, NROWS/128, 1), 256, GEMM_SMEMH(128)>>>(
        ctxh, Dsz, owh, Dsz, ob, x1, x2, Dsz, Dsz,
        nullptr, nullptr, nullptr, nullptr, nullptr, nullptr);

    // ---- FFN block ----
    layernorm_kernel<<<NROWS, 256>>>(x2, ln3g, ln3b, xnh);
    gemm_mma_kernel<128,3,0,1><<<dim3(FFsz/128, NROWS/128, 1), 256, GEMM_SMEMH(128)>>>(
        xnh, Dsz, w1h, Dsz, b1, nullptr, ffh, FFsz, Dsz,
        nullptr, nullptr, nullptr, nullptr, nullptr, nullptr);
    gemm_mma_kernel<128,2,0,0><<<dim3(Dsz/128, NROWS/128, 1), 256, GEMM_SMEMH(128)>>>(
        ffh, FFsz, w2h, FFsz, b2, x2, out, Dsz, FFsz,
        nullptr, nullptr, nullptr, nullptr, nullptr, nullptr);
}

// round 14
// speedup vs baseline: 1.6141x; 1.0505x over previous
#include <cuda_runtime.h>
#include <cuda_fp16.h>
#include <math.h>
#include <stdint.h>

#define Bsz 8
#define Ssz 1024
#define Dsz 512
#define Hsz 8
#define DHsz 64
#define FFsz 1024
#define NPOS 64          // 2*SPAN
#define NROWS (Bsz*Ssz)  // 8192

// ---------------- scratch (device globals; no allocation allowed) ------------
__device__ float  g_x1  [Bsz*Ssz*Dsz];
__device__ float  g_x2  [Bsz*Ssz*Dsz];
__device__ __half g_c2p [Bsz*Hsz*Ssz*NPOS];
__device__ __half g_p2c [Bsz*Hsz*Ssz*NPOS];
__device__ int    g_lut [2*Ssz];
__device__ __half g_xnh  [Bsz*Ssz*Dsz];
__device__ __half g_convh[Bsz*Ssz*Dsz];
__device__ __half g_qh   [Bsz*Ssz*Dsz];
__device__ __half g_kh   [Bsz*Ssz*Dsz];
__device__ __half g_vh   [Bsz*Ssz*Dsz];
__device__ __half g_vth  [Bsz*Ssz*Dsz];   // [B, D, S]
__device__ __half g_ctxh [Bsz*Ssz*Dsz];
__device__ __half g_ffh  [Bsz*Ssz*FFsz];
__device__ __half g_poskh[NPOS*Dsz];
__device__ __half g_posqh[NPOS*Dsz];
__device__ __half g_pwwh[Dsz*Dsz];
__device__ __half g_qwh [Dsz*Dsz];
__device__ __half g_kwh [Dsz*Dsz];
__device__ __half g_vwh [Dsz*Dsz];
__device__ __half g_owh [Dsz*Dsz];
__device__ __half g_w1h [FFsz*Dsz];
__device__ __half g_w2h [FFsz*Dsz];

// ---------------- half2 silu helper ---------------------------------------------
__device__ __forceinline__ __half2 silu_h2(__half2 hv) {
    const __half2 nl2e = __floats2half2_rn(-1.4426950408889634f, -1.4426950408889634f);
    const __half2 one2 = __floats2half2_rn(1.0f, 1.0f);
    return __hmul2(hv, h2rcp(__hadd2(one2, h2exp2(__hmul2(hv, nl2e)))));
}

// ---------------- setup: weights fp32->fp16 + rel-pos LUT (merged) -------------
__global__ void setup_kernel(const float* __restrict__ s0, const float* __restrict__ s1,
                             const float* __restrict__ s2, const float* __restrict__ s3,
                             const float* __restrict__ s4, const float* __restrict__ s5,
                             const float* __restrict__ s6,
                             __half* d0, __half* d1, __half* d2, __half* d3,
                             __half* d4, __half* d5, __half* d6, int* __restrict__ lut) {
    int z = blockIdx.z;
    if (z == 7) {   // LUT
        int t = blockIdx.x * blockDim.x + threadIdx.x;
        if (t >= 2*Ssz - 1) return;
        int rel = t - (Ssz - 1);
        const int mid = 16;
        int bucket;
        if (rel > -mid && rel < mid) {
            bucket = rel;
        } else {
            float absp = fabsf((float)rel);
            if (absp <= (float)mid) {
                bucket = rel;
            } else {
                float logp = ceilf(logf(absp / 16.0f) / logf(127.0f / 16.0f) * 15.0f) + 16.0f;
                bucket = (rel > 0 ? 1 : -1) * (int)logp;
            }
        }
        int idx = bucket + 32;
        lut[t] = min(max(idx, 0), 63);
        return;
    }
    const float* s; __half* d; int n;
    switch (z) {
        case 0: s = s0; d = d0; n = Dsz*Dsz;  break;
        case 1: s = s1; d = d1; n = Dsz*Dsz;  break;
        case 2: s = s2; d = d2; n = Dsz*Dsz;  break;
        case 3: s = s3; d = d3; n = Dsz*Dsz;  break;
        case 4: s = s4; d = d4; n = Dsz*Dsz;  break;
        case 5: s = s5; d = d5; n = FFsz*Dsz; break;
        default:s = s6; d = d6; n = FFsz*Dsz; break;
    }
    for (int i = blockIdx.x * blockDim.x + threadIdx.x; i * 2 < n; i += gridDim.x * blockDim.x) {
        float2 f = *(const float2*)&s[i * 2];
        *(__half2*)&d[i * 2] = __floats2half2_rn(f.x, f.y);
    }
}

// ---------------- LayerNorm (D=512, one block per row) -> half -----------------
__global__ void layernorm_kernel(const float* __restrict__ x,
                                 const float* __restrict__ g,
                                 const float* __restrict__ bb,
                                 __half* __restrict__ out) {
    const float* xr = x + (size_t)blockIdx.x * Dsz;
    __half* orow = out + (size_t)blockIdx.x * Dsz;
    int tid = threadIdx.x;  // 256
    float2 v = *(const float2*)&xr[tid * 2];
    float s = v.x + v.y, ss = v.x * v.x + v.y * v.y;
    __shared__ float r1[8], r2[8];
    #pragma unroll
    for (int o = 16; o; o >>= 1) {
        s  += __shfl_xor_sync(0xffffffffu, s, o);
        ss += __shfl_xor_sync(0xffffffffu, ss, o);
    }
    if ((tid & 31) == 0) { r1[tid >> 5] = s; r2[tid >> 5] = ss; }
    __syncthreads();
    float S1 = 0.f, S2 = 0.f;
    #pragma unroll
    for (int i = 0; i < 8; i++) { S1 += r1[i]; S2 += r2[i]; }
    float mean = S1 * (1.0f / Dsz);
    float var  = S2 * (1.0f / Dsz) - mean * mean;
    float rs = rsqrtf(var + 1e-5f);
    float2 gg = *(const float2*)&g[tid * 2];
    float2 bv = *(const float2*)&bb[tid * 2];
    *(__half2*)&orow[tid * 2] = __floats2half2_rn(
        (v.x - mean) * rs * gg.x + bv.x,
        (v.y - mean) * rs * gg.y + bv.y);
}

// ---------------- depthwise conv: 4 s-positions per thread ---------------------
__global__ void dwconv_silu_kernel(const __half* __restrict__ xn,
                                   const float* __restrict__ w,
                                   const float* __restrict__ bias,
                                   __half* __restrict__ out) {
    int idx = blockIdx.x * blockDim.x + threadIdx.x;
    if (idx >= Bsz * Ssz * Dsz / 8) return;
    int d2 = idx & (Dsz/2 - 1);
    int rs = idx >> 8;                 // / (Dsz/2)
    int s4 = (rs & (Ssz/4 - 1)) * 4;
    int b  = rs >> 8;                  // / (Ssz/4)
    int d  = d2 * 2;

    float2 wc0 = *(const float2*)&w[d*3];       // w[d][0], w[d][1]
    float  wc2 = w[d*3+2];
    float2 wc3 = *(const float2*)&w[d*3+4];     // w[d+1][1], w[d+1][2]  (w[d*3+4],w[d*3+5])
    float  w10 = w[d*3+3];
    float2 bv  = *(const float2*)&bias[d];

    const __half2* col = (const __half2*)xn + ((size_t)b * Ssz + s4) * (Dsz/2) + d2;
    const int st = Dsz / 2;

    float2 xv[6];
    xv[0] = (s4 > 0) ? __half22float2(col[-st]) : make_float2(0.f, 0.f);
    #pragma unroll
    for (int t = 0; t < 4; t++) xv[t + 1] = __half22float2(col[t * st]);
    xv[5] = (s4 + 4 < Ssz) ? __half22float2(col[4 * st]) : make_float2(0.f, 0.f);

    __half2* orow = (__half2*)out + ((size_t)b * Ssz + s4) * (Dsz/2) + d2;
    #pragma unroll
    for (int t = 0; t < 4; t++) {
        float a0 = bv.x + xv[t].x * wc0.x + xv[t+1].x * wc0.y + xv[t+2].x * wc2;
        float a1 = bv.y + xv[t].y * w10   + xv[t+1].y * wc3.x + xv[t+2].y * wc3.y;
        orow[t * st] = silu_h2(__floats2half2_rn(a0, a1));
    }
}

// ---------------- V transpose: [B,S,D] -> [B,D,S] (half2 both sides) -----------
__global__ void transpose_v_kernel(const __half* __restrict__ v, __half* __restrict__ vt) {
    __shared__ __half tile[64][66];
    int b = blockIdx.z;
    int s0 = blockIdx.x * 64, d0 = blockIdx.y * 64;
    int tx = threadIdx.x & 31, ty = threadIdx.x >> 5;   // 32 x 8
    #pragma unroll
    for (int j = 0; j < 64; j += 8) {
        __half2 hv = *(const __half2*)&v[((size_t)b * Ssz + s0 + ty + j) * Dsz + d0 + tx * 2];
        tile[ty + j][tx * 2]     = __low2half(hv);
        tile[ty + j][tx * 2 + 1] = __high2half(hv);
    }
    __syncthreads();
    #pragma unroll
    for (int j = 0; j < 64; j += 8) {
        int d = ty + j;
        __half2 hv = __halves2half2(tile[tx * 2][d], tile[tx * 2 + 1][d]);
        *(__half2*)&vt[((size_t)b * Dsz + d0 + d) * Ssz + s0 + tx * 2] = hv;
    }
}

// ---------------- mma.f16 + ldmatrix helpers -----------------------------------
__device__ __forceinline__ void mma_f16(float c[4], const uint32_t a[4], const uint32_t b[2]) {
    asm volatile(
        "mma.sync.aligned.m16n8k16.row.col.f32.f16.f16.f32 "
        "{%0,%1,%2,%3}, {%4,%5,%6,%7}, {%8,%9}, {%0,%1,%2,%3};"
        : "+f"(c[0]), "+f"(c[1]), "+f"(c[2]), "+f"(c[3])
        : "r"(a[0]), "r"(a[1]), "r"(a[2]), "r"(a[3]), "r"(b[0]), "r"(b[1]));
}

__device__ __forceinline__ void ldsm_x4(uint32_t r[4], uint32_t addr) {
    asm volatile("ldmatrix.sync.aligned.m8n8.x4.shared.b16 {%0,%1,%2,%3}, [%4];"
                 : "=r"(r[0]), "=r"(r[1]), "=r"(r[2]), "=r"(r[3]) : "r"(addr));
}

#define CP_ASYNC16(dst_u32, src_ptr) \
    asm volatile("cp.async.ca.shared.global [%0], [%1], 16;" :: "r"(dst_u32), "l"(src_ptr))
#define CP_COMMIT() asm volatile("cp.async.commit_group;")
#define CP_WAIT2()  asm volatile("cp.async.wait_group 2;")
#define CP_WAIT1()  asm volatile("cp.async.wait_group 1;")
#define CP_WAIT0()  asm volatile("cp.async.wait_group 0;")

// ---------------- fp16 tensor-core TN GEMM (128xCN tiles, K32 chunks) ----------
#define STRB 80
#define NSTAGE 4
#define GEMM_SMEMH(CNv) (NSTAGE * (128 + (CNv)) * STRB)

template<int CN, int EPI, int MODE, int OUTH>
__global__ void __launch_bounds__(256, 2) gemm_mma_kernel(
    const __half* __restrict__ A0, int lda,
    const __half* __restrict__ W0, int ldw,
    const float* __restrict__ bias0, const float* __restrict__ res,
    void* __restrict__ C0v, int ldc, int K,
    const __half* __restrict__ Wa, const __half* __restrict__ Wb2,
    const float* __restrict__ ba, const float* __restrict__ bb2,
    void* __restrict__ Cav, void* __restrict__ Cbv)
{
    constexpr int NWN = CN / 32;
    constexpr int NWM = 8 / NWN;
    constexpr int MT  = 8 / NWM;

    extern __shared__ char smem[];
    const uint32_t sb = (uint32_t)__cvta_generic_to_shared(smem);
    const uint32_t sA = sb;
    const uint32_t sW = sb + NSTAGE * 128 * STRB;

    const int tid  = threadIdx.x;
    const int wid  = tid >> 5, lane = tid & 31;
    const int g    = lane >> 2, tg = lane & 3;
    const int wm   = wid % NWM, wn = wid / NWM;

    const int z = blockIdx.z;
    const __half* A = A0; const __half* W = W0; void* Cv = C0v;
    const float* bias = bias0;
    if (MODE == 4) {
        W    = (z == 0) ? W0 : (z == 1 ? Wa : Wb2);
        bias = (z == 0) ? bias0 : (z == 1 ? ba : bb2);
        Cv   = (z == 0) ? C0v : (z == 1 ? Cav : Cbv);
    }

    const int m_cta = blockIdx.y * 128, n_cta = blockIdx.x * CN;

    auto fetch = [&](int t, int buf) {
        int k0 = t * 32;
        #pragma unroll
        for (int r = 0; r < 2; r++) {
            int id = tid + 256 * r;
            int row = id >> 2, ch = id & 3;
            CP_ASYNC16(sA + (uint32_t)(buf * 128 * STRB + row * STRB + ch * 16),
                       A + (size_t)(m_cta + row) * lda + k0 + ch * 8);
        }
        #pragma unroll
        for (int r = 0; r < CN / 64; r++) {
            int id = tid + 256 * r;
            int row = id >> 2, ch = id & 3;
            CP_ASYNC16(sW + (uint32_t)(buf * CN * STRB + row * STRB + ch * 16),
                       W + (size_t)(n_cta + row) * ldw + k0 + ch * 8);
        }
        CP_COMMIT();
    };

    const int lq = lane >> 3, lr = lane & 7;
    const int aoff = ((lq & 1) * 8 + lr) * STRB + (lq >> 1) * 16;
    const int boff = ((lq >> 1) * 8 + lr) * STRB + (lq & 1) * 16;

    float acc[MT][4][4] = {};

    const int T = K / 32;
    fetch(0, 0);
    fetch(1, 1);
    if (T > 2) fetch(2, 2);
    for (int it = 0; it < T; it++) {
        const int buf = it & (NSTAGE - 1);
        if (it < T - 2)       { CP_WAIT2(); }
        else if (it == T - 2) { CP_WAIT1(); }
        else                  { CP_WAIT0(); }
        __syncthreads();
        if (it + 3 < T) fetch(it + 3, (it + 3) & (NSTAGE - 1));

        const uint32_t bA = sA + (uint32_t)(buf * 128 * STRB);
        const uint32_t bW = sW + (uint32_t)(buf * CN  * STRB);
        #pragma unroll
        for (int ks = 0; ks < 2; ks++) {
            const int kb = ks * 32;
            uint32_t af[MT][4];
            #pragma unroll
            for (int im = 0; im < MT; im++)
                ldsm_x4(af[im], bA + (uint32_t)((wm * MT * 16 + im * 16) * STRB + aoff + kb));
            uint32_t bf[2][4];
            #pragma unroll
            for (int ip = 0; ip < 2; ip++)
                ldsm_x4(bf[ip], bW + (uint32_t)((wn * 32 + ip * 16) * STRB + boff + kb));
            #pragma unroll
            for (int im = 0; im < MT; im++)
                #pragma unroll
                for (int in = 0; in < 4; in++)
                    mma_f16(acc[im][in], af[im], &bf[in >> 1][(in & 1) * 2]);
        }
    }

    #pragma unroll
    for (int im = 0; im < MT; im++) {
        int mrow0 = m_cta + wm * MT * 16 + im * 16 + g;
        #pragma unroll
        for (int in = 0; in < 4; in++) {
            int ncol0 = n_cta + wn * 32 + in * 8 + tg * 2;
            float2 bv = make_float2(0.f, 0.f);
            if (EPI >= 1) bv = *(const float2*)&bias[ncol0];
            #pragma unroll
            for (int h = 0; h < 2; h++) {
                int m = mrow0 + h * 8;
                float v0 = acc[im][in][h * 2 + 0];
                float v1 = acc[im][in][h * 2 + 1];
                if (EPI >= 1) { v0 += bv.x; v1 += bv.y; }
                if (EPI == 2) {
                    float2 rv = *(const float2*)&res[(size_t)m * ldc + ncol0];
                    v0 += rv.x; v1 += rv.y;
                }
                if (OUTH) {
                    __half2 hv = __floats2half2_rn(v0, v1);
                    if (EPI == 3) hv = silu_h2(hv);
                    *(__half2*)&((__half*)Cv)[(size_t)m * ldc + ncol0] = hv;
                } else {
                    *(float2*)&((float*)Cv)[(size_t)m * ldc + ncol0] = make_float2(v0, v1);
                }
            }
        }
    }
}

// ---------------- fp16 mma GEMM for pos projections (N=64, K=64, half out) -----
__global__ void __launch_bounds__(256, 2) gemm_pos_kernel(
    const __half* __restrict__ A0,
    const __half* __restrict__ W0,
    __half* __restrict__ C0,
    const __half* __restrict__ Aa, const __half* __restrict__ Wa,
    __half* __restrict__ Ca)
{
    extern __shared__ char smem[];
    const uint32_t sb = (uint32_t)__cvta_generic_to_shared(smem);
    const uint32_t sA = sb;
    const uint32_t sW = sb + NSTAGE * 128 * STRB;

    const int tid  = threadIdx.x;
    const int wid  = tid >> 5, lane = tid & 31;
    const int g    = lane >> 2, tg = lane & 3;
    const int wm   = wid & 3, wn = wid >> 2;

    int zz = blockIdx.z & 63, sel = blockIdx.z >> 6;
    int bb = zz >> 3, hh = zz & 7;
    const __half* A = (sel ? Aa : A0) + (size_t)bb * Ssz * Dsz + hh * DHsz;
    const __half* W = (sel ? Wa : W0) + hh * DHsz;
    __half* C = (sel ? Ca : C0) + (size_t)zz * Ssz * NPOS;

    const int m_cta = blockIdx.y * 128;

    auto fetch = [&](int t, int buf) {
        int k0 = t * 32;
        #pragma unroll
        for (int r = 0; r < 2; r++) {
            int id = tid + 256 * r;
            int row = id >> 2, ch = id & 3;
            CP_ASYNC16(sA + (uint32_t)(buf * 128 * STRB + row * STRB + ch * 16),
                       A + (size_t)(m_cta + row) * Dsz + k0 + ch * 8);
        }
        {
            int row = tid >> 2, ch = tid & 3;
            if (row < 64)
                CP_ASYNC16(sW + (uint32_t)(buf * 64 * STRB + row * STRB + ch * 16),
                           W + (size_t)row * Dsz + k0 + ch * 8);
        }
        CP_COMMIT();
    };

    const int lq = lane >> 3, lr = lane & 7;
    const int aoff = ((lq & 1) * 8 + lr) * STRB + (lq >> 1) * 16;
    const int boff = ((lq >> 1) * 8 + lr) * STRB + (lq & 1) * 16;

    float acc[2][4][4] = {};
    const int T = 2;   // K=64
    fetch(0, 0); fetch(1, 1);
    for (int it = 0; it < T; it++) {
        const int buf = it & (NSTAGE - 1);
        if (it == T - 2) { CP_WAIT1(); } else { CP_WAIT0(); }
        __syncthreads();

        const uint32_t bA = sA + (uint32_t)(buf * 128 * STRB);
        const uint32_t bW = sW + (uint32_t)(buf * 64  * STRB);
        #pragma unroll
        for (int ks = 0; ks < 2; ks++) {
            const int kb = ks * 32;
            uint32_t af[2][4];
            #pragma unroll
            for (int im = 0; im < 2; im++)
                ldsm_x4(af[im], bA + (uint32_t)((wm * 32 + im * 16) * STRB + aoff + kb));
            uint32_t bf[2][4];
            #pragma unroll
            for (int ip = 0; ip < 2; ip++)
                ldsm_x4(bf[ip], bW + (uint32_t)((wn * 32 + ip * 16) * STRB + boff + kb));
            #pragma unroll
            for (int im = 0; im < 2; im++)
                #pragma unroll
                for (int in = 0; in < 4; in++)
                    mma_f16(acc[im][in], af[im], &bf[in >> 1][(in & 1) * 2]);
        }
    }

    #pragma unroll
    for (int im = 0; im < 2; im++) {
        int mrow0 = m_cta + wm * 32 + im * 16 + g;
        #pragma unroll
        for (int in = 0; in < 4; in++) {
            int ncol0 = wn * 32 + in * 8 + tg * 2;
            #pragma unroll
            for (int h = 0; h < 2; h++) {
                int m = mrow0 + h * 8;
                *(__half2*)&C[(size_t)m * NPOS + ncol0] =
                    __floats2half2_rn(acc[im][in][h * 2], acc[im][in][h * 2 + 1]);
            }
        }
    }
}

// ---------------- small SIMT GEMM (pos-emb projections, fp32 in, half out) -----
#define TK 16
#define TPAD 68
__global__ void gemm_tn_small_kernel(const float* __restrict__ A, int lda,
                                     const float* __restrict__ W0, int ldw,
                                     const float* __restrict__ b0,
                                     __half* __restrict__ C0,
                                     const float* __restrict__ W1,
                                     const float* __restrict__ b1,
                                     __half* __restrict__ C1, int ldc, int Kd) {
    const float* W   = blockIdx.z ? W1 : W0;
    const float* bias= blockIdx.z ? b1 : b0;
    __half* C        = blockIdx.z ? C1 : C0;
    int m0 = blockIdx.y * 64, n0 = blockIdx.x * 64;
    __shared__ float As[TK][TPAD];
    __shared__ float Ws2[TK][TPAD];
    const int tid = threadIdx.x;
    const int tx = tid & 15, ty = tid >> 4;
    const int lk = tid & 15, lm = tid >> 4;
    float acc[4][4] = {};
    for (int k0 = 0; k0 < Kd; k0 += TK) {
        #pragma unroll
        for (int r = 0; r < 4; r++) {
            As[lk][lm + 16 * r]  = A[(size_t)(m0 + lm + 16 * r) * lda + k0 + lk];
            Ws2[lk][lm + 16 * r] = W[(size_t)(n0 + lm + 16 * r) * ldw + k0 + lk];
        }
        __syncthreads();
        #pragma unroll
        for (int kk = 0; kk < TK; kk++) {
            float4 a = *(const float4*)&As[kk][ty * 4];
            float4 b = *(const float4*)&Ws2[kk][tx * 4];
            float av[4] = {a.x, a.y, a.z, a.w};
            float bv[4] = {b.x, b.y, b.z, b.w};
            #pragma unroll
            for (int i = 0; i < 4; i++)
                #pragma unroll
                for (int j = 0; j < 4; j++)
                    acc[i][j] += av[i] * bv[j];
        }
        __syncthreads();
    }
    #pragma unroll
    for (int i = 0; i < 4; i++) {
        int m = m0 + ty * 4 + i;
        #pragma unroll
        for (int j = 0; j < 4; j += 2) {
            int n = n0 + tx * 4 + j;
            *(__half2*)&C[(size_t)m * ldc + n] =
                __floats2half2_rn(acc[i][j] + bias[n], acc[i][j+1] + bias[n+1]);
        }
    }
}

// =========================== fused flash attention (fp16 mma) ==================
// All bias gathers from smem: c2p rows staged once per CTA, p2c rows double-
// buffered with KV. Register P from h2exp2 feeds P.V A-frags directly.
#define STRF 144                      // bytes per 64-half row (128B + 16B pad)
#define FA_K(buf)   ((buf) * 64 * STRF)
#define FA_V(buf)   (2 * 64 * STRF + (buf) * 64 * STRF)
#define FA_Q        (4 * 64 * STRF)                 // 128 x STRF
#define FA_C2P      (FA_Q + 128 * STRF)             // 128 x 128B = 16384
#define FA_P2C(buf) (FA_C2P + 16384 + (buf) * 8192) // 2 x 64 x 128B
#define FA_LUT      (FA_C2P + 16384 + 16384)
#define FA_SMEM     (FA_LUT + 2048 * 4)

__global__ void __launch_bounds__(256, 2) flash_attn_kernel(
    const __half* __restrict__ qg, const __half* __restrict__ kg,
    const __half* __restrict__ vt,
    const __half* __restrict__ c2p, const __half* __restrict__ p2c,
    const int* __restrict__ lut, __half* __restrict__ ctx)
{
    extern __shared__ char smc[];
    int* lut_s = (int*)(smc + FA_LUT);

    const int tid = threadIdx.x, w = tid >> 5, lane = tid & 31;
    const int g = lane >> 2, tg = lane & 3;
    const int z = blockIdx.z, bb = z >> 3, hh = z & 7;
    const int i0 = blockIdx.x * 128;

    const __half* c2pz = c2p + (size_t)z * Ssz * NPOS;
    const __half* p2cz = p2c + (size_t)z * Ssz * NPOS;

    const uint32_t sb = (uint32_t)__cvta_generic_to_shared(smc);

    #pragma unroll
    for (int t = 0; t < 8; t++) {
        int idx = tid + 256 * t;
        if (idx < 2 * Ssz - 1) lut_s[idx] = lut[idx];
    }

    auto loadKV = [&](int jt, int buf) {
        int j0 = jt * 64;
        #pragma unroll
        for (int c = 0; c < 2; c++) {       // K
            int id = tid * 2 + c;
            int row = id >> 3, ch = id & 7;
            CP_ASYNC16(sb + (uint32_t)(FA_K(buf) + row * STRF + ch * 16),
                       kg + ((size_t)bb * Ssz + j0 + row) * Dsz + hh * DHsz + ch * 8);
        }
        #pragma unroll
        for (int c = 0; c < 2; c++) {       // V
            int id = tid * 2 + c;
            int row = id >> 3, ch = id & 7;
            CP_ASYNC16(sb + (uint32_t)(FA_V(buf) + row * STRF + ch * 16),
                       vt + ((size_t)bb * Dsz + hh * DHsz + row) * Ssz + j0 + ch * 8);
        }
        #pragma unroll
        for (int c = 0; c < 2; c++) {       // p2c rows for this j-tile (64 x 128B)
            int id = tid * 2 + c;
            int row = id >> 3, ch = id & 7;
            CP_ASYNC16(sb + (uint32_t)(FA_P2C(buf) + row * 128 + ch * 16),
                       p2cz + (size_t)(j0 + row) * NPOS + ch * 8);
        }
        CP_COMMIT();
    };

    // prologue: Q + c2p rows (group A), KV0 (group B)
    #pragma unroll
    for (int c = 0; c < 4; c++) {           // Q
        int id = tid * 4 + c;
        int row = id >> 3, ch = id & 7;
        CP_ASYNC16(sb + (uint32_t)(FA_Q + row * STRF + ch * 16),
                   qg + ((size_t)bb * Ssz + i0 + row) * Dsz + hh * DHsz + ch * 8);
    }
    #pragma unroll
    for (int c = 0; c < 4; c++) {           // c2p rows (128 x 128B)
        int id = tid * 4 + c;
        int row = id >> 3, ch = id & 7;
        CP_ASYNC16(sb + (uint32_t)(FA_C2P + row * 128 + ch * 16),
                   c2pz + (size_t)(i0 + row) * NPOS + ch * 8);
    }
    CP_COMMIT();
    loadKV(0, 0);

    CP_WAIT1();
    __syncthreads();

    const int lq = lane >> 3, lr = lane & 7;
    const int aoffF = ((lq & 1) * 8 + lr) * STRF + (lq >> 1) * 16;
    const int boffF = ((lq >> 1) * 8 + lr) * STRF + (lq & 1) * 16;

    uint32_t qf[4][4];
    #pragma unroll
    for (int kc = 0; kc < 4; kc++)
        ldsm_x4(qf[kc], sb + (uint32_t)(FA_Q + (w * 16) * STRF + aoffF + kc * 32));

    const __half* c2ps = (const __half*)(smc + FA_C2P);
    const int crow0 = (w * 16 + g) * 64;        // c2p smem row offsets
    const int crow1 = crow0 + 8 * 64;

    float acc_o[8][4] = {};
    float m_r[2] = {-1e30f, -1e30f};
    float l_r[2] = {0.f, 0.f};
    const float SCALE2 = 0.07216878364870323f * 1.4426950408889634f;  // log2 domain
    const int mg0 = i0 + w * 16 + g;

    for (int jt = 0; jt < 16; jt++) {
        const int buf = jt & 1;
        const int j0 = jt * 64;
        CP_WAIT0();
        __syncthreads();
        if (jt < 15) loadKV(jt + 1, buf ^ 1);

        // ---- S = Q K^T (64 cols) ----
        float acc_s[8][4] = {};
        #pragma unroll
        for (int kc = 0; kc < 4; kc++) {
            #pragma unroll
            for (int ip = 0; ip < 4; ip++) {
                uint32_t bf[4];
                ldsm_x4(bf, sb + (uint32_t)(FA_K(buf) + (ip * 16) * STRF + boffF + kc * 32));
                mma_f16(acc_s[ip * 2],     qf[kc], &bf[0]);
                mma_f16(acc_s[ip * 2 + 1], qf[kc], &bf[2]);
            }
        }

        // ---- bias (smem gathers) + online softmax ----
        const __half* p2cs = (const __half*)(smc + FA_P2C(buf));
        float mx0 = -1e30f, mx1 = -1e30f;
        #pragma unroll
        for (int in = 0; in < 8; in++) {
            int nloc = in * 8 + tg * 2;             // n - j0
            int dbase = mg0 - j0 - nloc + (Ssz - 1);
            #pragma unroll
            for (int e = 0; e < 4; e++) {
                int crow = (e >= 2) ? crow1 : crow0;
                int dd   = dbase + ((e >= 2) ? 8 : 0) - (e & 1);
                int nl   = nloc + (e & 1);
                int idx  = lut_s[dd];
                float vv = (acc_s[in][e] + __half2float(c2ps[crow + idx])
                                         + __half2float(p2cs[nl * 64 + idx])) * SCALE2;
                acc_s[in][e] = vv;
                if (e < 2) mx0 = fmaxf(mx0, vv); else mx1 = fmaxf(mx1, vv);
            }
        }
        mx0 = fmaxf(mx0, __shfl_xor_sync(0xffffffffu, mx0, 1));
        mx0 = fmaxf(mx0, __shfl_xor_sync(0xffffffffu, mx0, 2));
        mx1 = fmaxf(mx1, __shfl_xor_sync(0xffffffffu, mx1, 1));
        mx1 = fmaxf(mx1, __shfl_xor_sync(0xffffffffu, mx1, 2));
        float mn0 = fmaxf(m_r[0], mx0), mn1 = fmaxf(m_r[1], mx1);
        float al0 = exp2f(m_r[0] - mn0), al1 = exp2f(m_r[1] - mn1);
        float s0 = 0.f, s1 = 0.f;
        uint32_t u01[8], u23[8];
        #pragma unroll
        for (int in = 0; in < 8; in++) {
            __half2 e01 = h2exp2(__floats2half2_rn(acc_s[in][0] - mn0, acc_s[in][1] - mn0));
            __half2 e23 = h2exp2(__floats2half2_rn(acc_s[in][2] - mn1, acc_s[in][3] - mn1));
            u01[in] = *(uint32_t*)&e01;
            u23[in] = *(uint32_t*)&e23;
            float2 f01 = __half22float2(e01);
            float2 f23 = __half22float2(e23);
            s0 += f01.x + f01.y; s1 += f23.x + f23.y;
        }
        l_r[0] = l_r[0] * al0 + s0;
        l_r[1] = l_r[1] * al1 + s1;
        m_r[0] = mn0; m_r[1] = mn1;
        #pragma unroll
        for (int nf = 0; nf < 8; nf++) {
            acc_o[nf][0] *= al0; acc_o[nf][1] *= al0;
            acc_o[nf][2] *= al1; acc_o[nf][3] *= al1;
        }

        // ---- O += P V ----
        #pragma unroll
        for (int kc2 = 0; kc2 < 4; kc2++) {
            uint32_t af[4];
            af[0] = u01[kc2 * 2];
            af[1] = u23[kc2 * 2];
            af[2] = u01[kc2 * 2 + 1];
            af[3] = u23[kc2 * 2 + 1];
            #pragma unroll
            for (int ip = 0; ip < 4; ip++) {
                uint32_t bf[4];
                ldsm_x4(bf, sb + (uint32_t)(FA_V(buf) + (ip * 16) * STRF + boffF + kc2 * 32));
                mma_f16(acc_o[ip * 2],     af, &bf[0]);
                mma_f16(acc_o[ip * 2 + 1], af, &bf[2]);
            }
        }
    }

    float l0 = l_r[0];
    l0 += __shfl_xor_sync(0xffffffffu, l0, 1);
    l0 += __shfl_xor_sync(0xffffffffu, l0, 2);
    float l1 = l_r[1];
    l1 += __shfl_xor_sync(0xffffffffu, l1, 1);
    l1 += __shfl_xor_sync(0xffffffffu, l1, 2);
    float inv0 = 1.0f / l0, inv1 = 1.0f / l1;
    __half* c0 = ctx + ((size_t)bb * Ssz + mg0)     * Dsz + hh * DHsz;
    __half* c1 = ctx + ((size_t)bb * Ssz + mg0 + 8) * Dsz + hh * DHsz;
    #pragma unroll
    for (int nf = 0; nf < 8; nf++) {
        int col = nf * 8 + tg * 2;
        *(__half2*)&c0[col] = __floats2half2_rn(acc_o[nf][0] * inv0, acc_o[nf][1] * inv0);
        *(__half2*)&c1[col] = __floats2half2_rn(acc_o[nf][2] * inv1, acc_o[nf][3] * inv1);
    }
}

// =============================== launch ========================================
extern "C" void kernel_launch(void* const* d_in, const int* in_sizes, int n_in,
                              void* d_out, int out_size) {
    const float* x      = (const float*)d_in[0];
    const float* ln1g   = (const float*)d_in[1];
    const float* ln1b   = (const float*)d_in[2];
    const float* dww    = (const float*)d_in[3];
    const float* dwb    = (const float*)d_in[4];
    const float* pww    = (const float*)d_in[5];
    const float* pwb    = (const float*)d_in[6];
    const float* ln2g   = (const float*)d_in[7];
    const float* ln2b   = (const float*)d_in[8];
    const float* qw     = (const float*)d_in[9];
    const float* qb     = (const float*)d_in[10];
    const float* kw     = (const float*)d_in[11];
    const float* kb     = (const float*)d_in[12];
    const float* vw     = (const float*)d_in[13];
    const float* vb     = (const float*)d_in[14];
    const float* ow     = (const float*)d_in[15];
    const float* ob     = (const float*)d_in[16];
    const float* relemb = (const float*)d_in[17];
    const float* ln3g   = (const float*)d_in[18];
    const float* ln3b   = (const float*)d_in[19];
    const float* w1     = (const float*)d_in[20];
    const float* b1     = (const float*)d_in[21];
    const float* w2     = (const float*)d_in[22];
    const float* b2     = (const float*)d_in[23];
    float* out = (float*)d_out;

    float *x1, *x2; int* lut;
    __half *c2p, *p2c;
    __half *xnh, *convh, *qh, *kh, *vh, *vth, *ctxh, *ffh, *poskh, *posqh;
    __half *pwwh, *qwh, *kwh, *vwh, *owh, *w1h, *w2h;
    cudaGetSymbolAddress((void**)&x1,    g_x1);
    cudaGetSymbolAddress((void**)&x2,    g_x2);
    cudaGetSymbolAddress((void**)&c2p,   g_c2p);
    cudaGetSymbolAddress((void**)&p2c,   g_p2c);
    cudaGetSymbolAddress((void**)&lut,   g_lut);
    cudaGetSymbolAddress((void**)&xnh,   g_xnh);
    cudaGetSymbolAddress((void**)&convh, g_convh);
    cudaGetSymbolAddress((void**)&qh,    g_qh);
    cudaGetSymbolAddress((void**)&kh,    g_kh);
    cudaGetSymbolAddress((void**)&vh,    g_vh);
    cudaGetSymbolAddress((void**)&vth,   g_vth);
    cudaGetSymbolAddress((void**)&ctxh,  g_ctxh);
    cudaGetSymbolAddress((void**)&ffh,   g_ffh);
    cudaGetSymbolAddress((void**)&poskh, g_poskh);
    cudaGetSymbolAddress((void**)&posqh, g_posqh);
    cudaGetSymbolAddress((void**)&pwwh,  g_pwwh);
    cudaGetSymbolAddress((void**)&qwh,   g_qwh);
    cudaGetSymbolAddress((void**)&kwh,   g_kwh);
    cudaGetSymbolAddress((void**)&vwh,   g_vwh);
    cudaGetSymbolAddress((void**)&owh,   g_owh);
    cudaGetSymbolAddress((void**)&w1h,   g_w1h);
    cudaGetSymbolAddress((void**)&w2h,   g_w2h);

    static int attr_set = 0;
    if (!attr_set) {
        cudaFuncSetAttribute(flash_attn_kernel,
                             cudaFuncAttributeMaxDynamicSharedMemorySize, FA_SMEM);
        cudaFuncSetAttribute(gemm_mma_kernel<128,2,0,0>,
                             cudaFuncAttributeMaxDynamicSharedMemorySize, GEMM_SMEMH(128));
        cudaFuncSetAttribute(gemm_mma_kernel<128,1,4,1>,
                             cudaFuncAttributeMaxDynamicSharedMemorySize, GEMM_SMEMH(128));
        cudaFuncSetAttribute(gemm_mma_kernel<128,3,0,1>,
                             cudaFuncAttributeMaxDynamicSharedMemorySize, GEMM_SMEMH(128));
        cudaFuncSetAttribute(gemm_pos_kernel,
                             cudaFuncAttributeMaxDynamicSharedMemorySize, GEMM_SMEMH(64));
        attr_set = 1;
    }

    setup_kernel<<<dim3(256, 1, 8), 256>>>(pww, qw, kw, vw, ow, w1, w2,
                                           pwwh, qwh, kwh, vwh, owh, w1h, w2h, lut);

    // ---- conv block ----
    layernorm_kernel<<<NROWS, 256>>>(x, ln1g, ln1b, xnh);
    dwconv_silu_kernel<<<(Bsz*Ssz*Dsz/8 + 255) / 256, 256>>>(xnh, dww, dwb, convh);
    gemm_mma_kernel<128,2,0,0><<<dim3(Dsz/128, NROWS/128, 1), 256, GEMM_SMEMH(128)>>>(
        convh, Dsz, pwwh, Dsz, pwb, x, x1, Dsz, Dsz,
        nullptr, nullptr, nullptr, nullptr, nullptr, nullptr);

    // ---- attention block ----
    layernorm_kernel<<<NROWS, 256>>>(x1, ln2g, ln2b, xnh);
    gemm_mma_kernel<128,1,4,1><<<dim3(Dsz/128, NROWS/128, 3), 256, GEMM_SMEMH(128)>>>(
        xnh, Dsz, qwh, Dsz, qb, nullptr, qh, Dsz, Dsz,
        kwh, vwh, kb, vb, kh, vh);
    transpose_v_kernel<<<dim3(Ssz/64, Dsz/64, Bsz), 256>>>(vh, vth);

    gemm_tn_small_kernel<<<dim3(Dsz/64, 1, 2), 256>>>(
        relemb, Dsz, kw, Dsz, kb, poskh, qw, qb, posqh, Dsz, Dsz);

    gemm_pos_kernel<<<dim3(1, Ssz/128, 2*Bsz*Hsz), 256, GEMM_SMEMH(64)>>>(
        qh, poskh, c2p, kh, posqh, p2c);

    flash_attn_kernel<<<dim3(Ssz/128, 1, Bsz*Hsz), 256, FA_SMEM>>>(
        qh, kh, vth, c2p, p2c, lut, ctxh);

    gemm_mma_kernel<128,2,0,0><<<dim3(Dsz/128, NROWS/128, 1), 256, GEMM_SMEMH(128)>>>(
        ctxh, Dsz, owh, Dsz, ob, x1, x2, Dsz, Dsz,
        nullptr, nullptr, nullptr, nullptr, nullptr, nullptr);

    // ---- FFN block ----
    layernorm_kernel<<<NROWS, 256>>>(x2, ln3g, ln3b, xnh);
    gemm_mma_kernel<128,3,0,1><<<dim3(FFsz/128, NROWS/128, 1), 256, GEMM_SMEMH(128)>>>(
        xnh, Dsz, w1h, Dsz, b1, nullptr, ffh, FFsz, Dsz,
        nullptr, nullptr, nullptr, nullptr, nullptr, nullptr);
    gemm_mma_kernel<128,2,0,0><<<dim3(Dsz/128, NROWS/128, 1), 256, GEMM_SMEMH(128)>>>(
        ffh, FFsz, w2h, FFsz, b2, x2, out, Dsz, FFsz,
        nullptr, nullptr, nullptr, nullptr, nullptr, nullptr);
}

// round 15
// speedup vs baseline: 1.6292x; 1.0094x over previous
#include <cuda_runtime.h>
#include <cuda_fp16.h>
#include <math.h>
#include <stdint.h>

#define Bsz 8
#define Ssz 1024
#define Dsz 512
#define Hsz 8
#define DHsz 64
#define FFsz 1024
#define NPOS 64          // 2*SPAN
#define NROWS (Bsz*Ssz)  // 8192

// ---------------- scratch (device globals; no allocation allowed) ------------
__device__ float  g_x1  [Bsz*Ssz*Dsz];
__device__ float  g_x2  [Bsz*Ssz*Dsz];
__device__ __half g_c2p [Bsz*Hsz*Ssz*NPOS];   // pre-scaled by SCALE*log2(e)
__device__ __half g_p2c [Bsz*Hsz*Ssz*NPOS];   // pre-scaled
__device__ int    g_lut [2*Ssz];
__device__ __half g_xnh  [Bsz*Ssz*Dsz];
__device__ __half g_convh[Bsz*Ssz*Dsz];
__device__ __half g_qh   [Bsz*Ssz*Dsz];
__device__ __half g_kh   [Bsz*Ssz*Dsz];
__device__ __half g_vh   [Bsz*Ssz*Dsz];
__device__ __half g_vth  [Bsz*Ssz*Dsz];   // [B, D, S]
__device__ __half g_ctxh [Bsz*Ssz*Dsz];
__device__ __half g_ffh  [Bsz*Ssz*FFsz];
__device__ __half g_poskh[NPOS*Dsz];
__device__ __half g_posqh[NPOS*Dsz];
__device__ __half g_pwwh[Dsz*Dsz];
__device__ __half g_qwh [Dsz*Dsz];
__device__ __half g_kwh [Dsz*Dsz];
__device__ __half g_vwh [Dsz*Dsz];
__device__ __half g_owh [Dsz*Dsz];
__device__ __half g_w1h [FFsz*Dsz];
__device__ __half g_w2h [FFsz*Dsz];

#define SCALE2F (0.07216878364870323f * 1.4426950408889634f)  // 1/sqrt(192)*log2(e)

// ---------------- half2 silu helper ---------------------------------------------
__device__ __forceinline__ __half2 silu_h2(__half2 hv) {
    const __half2 nl2e = __floats2half2_rn(-1.4426950408889634f, -1.4426950408889634f);
    const __half2 one2 = __floats2half2_rn(1.0f, 1.0f);
    return __hmul2(hv, h2rcp(__hadd2(one2, h2exp2(__hmul2(hv, nl2e)))));
}

// ---------------- setup: weights fp32->fp16 + rel-pos LUT (merged) -------------
__global__ void setup_kernel(const float* __restrict__ s0, const float* __restrict__ s1,
                             const float* __restrict__ s2, const float* __restrict__ s3,
                             const float* __restrict__ s4, const float* __restrict__ s5,
                             const float* __restrict__ s6,
                             __half* d0, __half* d1, __half* d2, __half* d3,
                             __half* d4, __half* d5, __half* d6, int* __restrict__ lut) {
    int z = blockIdx.z;
    if (z == 7) {   // LUT
        int t = blockIdx.x * blockDim.x + threadIdx.x;
        if (t >= 2*Ssz - 1) return;
        int rel = t - (Ssz - 1);
        const int mid = 16;
        int bucket;
        if (rel > -mid && rel < mid) {
            bucket = rel;
        } else {
            float absp = fabsf((float)rel);
            if (absp <= (float)mid) {
                bucket = rel;
            } else {
                float logp = ceilf(logf(absp / 16.0f) / logf(127.0f / 16.0f) * 15.0f) + 16.0f;
                bucket = (rel > 0 ? 1 : -1) * (int)logp;
            }
        }
        int idx = bucket + 32;
        lut[t] = min(max(idx, 0), 63);
        return;
    }
    const float* s; __half* d; int n;
    switch (z) {
        case 0: s = s0; d = d0; n = Dsz*Dsz;  break;
        case 1: s = s1; d = d1; n = Dsz*Dsz;  break;
        case 2: s = s2; d = d2; n = Dsz*Dsz;  break;
        case 3: s = s3; d = d3; n = Dsz*Dsz;  break;
        case 4: s = s4; d = d4; n = Dsz*Dsz;  break;
        case 5: s = s5; d = d5; n = FFsz*Dsz; break;
        default:s = s6; d = d6; n = FFsz*Dsz; break;
    }
    for (int i = blockIdx.x * blockDim.x + threadIdx.x; i * 2 < n; i += gridDim.x * blockDim.x) {
        float2 f = *(const float2*)&s[i * 2];
        *(__half2*)&d[i * 2] = __floats2half2_rn(f.x, f.y);
    }
}

// ---------------- LayerNorm (D=512, one block per row) -> half -----------------
__global__ void layernorm_kernel(const float* __restrict__ x,
                                 const float* __restrict__ g,
                                 const float* __restrict__ bb,
                                 __half* __restrict__ out) {
    const float* xr = x + (size_t)blockIdx.x * Dsz;
    __half* orow = out + (size_t)blockIdx.x * Dsz;
    int tid = threadIdx.x;  // 256
    float2 v = *(const float2*)&xr[tid * 2];
    float s = v.x + v.y, ss = v.x * v.x + v.y * v.y;
    __shared__ float r1[8], r2[8];
    #pragma unroll
    for (int o = 16; o; o >>= 1) {
        s  += __shfl_xor_sync(0xffffffffu, s, o);
        ss += __shfl_xor_sync(0xffffffffu, ss, o);
    }
    if ((tid & 31) == 0) { r1[tid >> 5] = s; r2[tid >> 5] = ss; }
    __syncthreads();
    float S1 = 0.f, S2 = 0.f;
    #pragma unroll
    for (int i = 0; i < 8; i++) { S1 += r1[i]; S2 += r2[i]; }
    float mean = S1 * (1.0f / Dsz);
    float var  = S2 * (1.0f / Dsz) - mean * mean;
    float rs = rsqrtf(var + 1e-5f);
    float2 gg = *(const float2*)&g[tid * 2];
    float2 bv = *(const float2*)&bb[tid * 2];
    *(__half2*)&orow[tid * 2] = __floats2half2_rn(
        (v.x - mean) * rs * gg.x + bv.x,
        (v.y - mean) * rs * gg.y + bv.y);
}

// ---------------- fused LN1 + depthwise conv (K=3) + silu ----------------------
// One block per (b, 4 s-rows). Warps 0-5 LayerNorm rows s0-1..s0+4 into smem;
// phase 2: conv over smem, 4 outputs per thread.
__global__ void __launch_bounds__(256, 4) ln_dwconv_silu_kernel(
    const float* __restrict__ x,
    const float* __restrict__ g, const float* __restrict__ bb,
    const float* __restrict__ w, const float* __restrict__ bias,
    __half* __restrict__ out)
{
    __shared__ __half xs[6][Dsz];
    const int b = blockIdx.y;
    const int s0 = blockIdx.x * 4;
    const int tid = threadIdx.x, wd = tid >> 5, lane = tid & 31;

    if (wd < 6) {
        int s = s0 - 1 + wd;
        if (s >= 0 && s < Ssz) {
            const float* xr = x + ((size_t)b * Ssz + s) * Dsz;
            float v[16];
            float sum = 0.f, ssq = 0.f;
            #pragma unroll
            for (int i = 0; i < 16; i++) {
                v[i] = xr[lane + 32 * i];
                sum += v[i]; ssq += v[i] * v[i];
            }
            #pragma unroll
            for (int o = 16; o; o >>= 1) {
                sum += __shfl_xor_sync(0xffffffffu, sum, o);
                ssq += __shfl_xor_sync(0xffffffffu, ssq, o);
            }
            float mean = sum * (1.0f / Dsz);
            float var  = ssq * (1.0f / Dsz) - mean * mean;
            float rs = rsqrtf(var + 1e-5f);
            #pragma unroll
            for (int i = 0; i < 16; i++) {
                int d = lane + 32 * i;
                xs[wd][d] = __float2half((v[i] - mean) * rs * g[d] + bb[d]);
            }
        } else {
            #pragma unroll
            for (int i = 0; i < 16; i++)
                xs[wd][lane + 32 * i] = __float2half(0.f);
        }
    }
    __syncthreads();

    const int d2 = tid, d = d2 * 2;   // 256 threads cover all Dsz/2 pairs
    float2 wc0 = *(const float2*)&w[d*3];       // w[d][0], w[d][1]
    float  wc2 = w[d*3+2];
    float  w10 = w[d*3+3];
    float2 wc3 = *(const float2*)&w[d*3+4];     // w[d+1][1], w[d+1][2]
    float2 bv  = *(const float2*)&bias[d];

    float2 xv[6];
    #pragma unroll
    for (int r = 0; r < 6; r++)
        xv[r] = __half22float2(*(const __half2*)&xs[r][d]);

    __half2* orow = (__half2*)out + ((size_t)b * Ssz + s0) * (Dsz/2) + d2;
    #pragma unroll
    for (int t = 0; t < 4; t++) {
        float a0 = bv.x + xv[t].x * wc0.x + xv[t+1].x * wc0.y + xv[t+2].x * wc2;
        float a1 = bv.y + xv[t].y * w10   + xv[t+1].y * wc3.x + xv[t+2].y * wc3.y;
        orow[t * (Dsz/2)] = silu_h2(__floats2half2_rn(a0, a1));
    }
}

// ---------------- V transpose: [B,S,D] -> [B,D,S] (half2 both sides) -----------
__global__ void transpose_v_kernel(const __half* __restrict__ v, __half* __restrict__ vt) {
    __shared__ __half tile[64][66];
    int b = blockIdx.z;
    int s0 = blockIdx.x * 64, d0 = blockIdx.y * 64;
    int tx = threadIdx.x & 31, ty = threadIdx.x >> 5;   // 32 x 8
    #pragma unroll
    for (int j = 0; j < 64; j += 8) {
        __half2 hv = *(const __half2*)&v[((size_t)b * Ssz + s0 + ty + j) * Dsz + d0 + tx * 2];
        tile[ty + j][tx * 2]     = __low2half(hv);
        tile[ty + j][tx * 2 + 1] = __high2half(hv);
    }
    __syncthreads();
    #pragma unroll
    for (int j = 0; j < 64; j += 8) {
        int d = ty + j;
        __half2 hv = __halves2half2(tile[tx * 2][d], tile[tx * 2 + 1][d]);
        *(__half2*)&vt[((size_t)b * Dsz + d0 + d) * Ssz + s0 + tx * 2] = hv;
    }
}

// ---------------- mma.f16 + ldmatrix helpers -----------------------------------
__device__ __forceinline__ void mma_f16(float c[4], const uint32_t a[4], const uint32_t b[2]) {
    asm volatile(
        "mma.sync.aligned.m16n8k16.row.col.f32.f16.f16.f32 "
        "{%0,%1,%2,%3}, {%4,%5,%6,%7}, {%8,%9}, {%0,%1,%2,%3};"
        : "+f"(c[0]), "+f"(c[1]), "+f"(c[2]), "+f"(c[3])
        : "r"(a[0]), "r"(a[1]), "r"(a[2]), "r"(a[3]), "r"(b[0]), "r"(b[1]));
}

__device__ __forceinline__ void ldsm_x4(uint32_t r[4], uint32_t addr) {
    asm volatile("ldmatrix.sync.aligned.m8n8.x4.shared.b16 {%0,%1,%2,%3}, [%4];"
                 : "=r"(r[0]), "=r"(r[1]), "=r"(r[2]), "=r"(r[3]) : "r"(addr));
}

#define CP_ASYNC16(dst_u32, src_ptr) \
    asm volatile("cp.async.ca.shared.global [%0], [%1], 16;" :: "r"(dst_u32), "l"(src_ptr))
#define CP_COMMIT() asm volatile("cp.async.commit_group;")
#define CP_WAIT2()  asm volatile("cp.async.wait_group 2;")
#define CP_WAIT1()  asm volatile("cp.async.wait_group 1;")
#define CP_WAIT0()  asm volatile("cp.async.wait_group 0;")

// ---------------- fp16 tensor-core TN GEMM (128xCN tiles, K32 chunks) ----------
#define STRB 80
#define NSTAGE 4
#define GEMM_SMEMH(CNv) (NSTAGE * (128 + (CNv)) * STRB)

template<int CN, int EPI, int MODE, int OUTH>
__global__ void __launch_bounds__(256, 2) gemm_mma_kernel(
    const __half* __restrict__ A0, int lda,
    const __half* __restrict__ W0, int ldw,
    const float* __restrict__ bias0, const float* __restrict__ res,
    void* __restrict__ C0v, int ldc, int K,
    const __half* __restrict__ Wa, const __half* __restrict__ Wb2,
    const float* __restrict__ ba, const float* __restrict__ bb2,
    void* __restrict__ Cav, void* __restrict__ Cbv)
{
    constexpr int NWN = CN / 32;
    constexpr int NWM = 8 / NWN;
    constexpr int MT  = 8 / NWM;

    extern __shared__ char smem[];
    const uint32_t sb = (uint32_t)__cvta_generic_to_shared(smem);
    const uint32_t sA = sb;
    const uint32_t sW = sb + NSTAGE * 128 * STRB;

    const int tid  = threadIdx.x;
    const int wid  = tid >> 5, lane = tid & 31;
    const int g    = lane >> 2, tg = lane & 3;
    const int wm   = wid % NWM, wn = wid / NWM;

    const int z = blockIdx.z;
    const __half* A = A0; const __half* W = W0; void* Cv = C0v;
    const float* bias = bias0;
    if (MODE == 4) {
        W    = (z == 0) ? W0 : (z == 1 ? Wa : Wb2);
        bias = (z == 0) ? bias0 : (z == 1 ? ba : bb2);
        Cv   = (z == 0) ? C0v : (z == 1 ? Cav : Cbv);
    }

    const int m_cta = blockIdx.y * 128, n_cta = blockIdx.x * CN;

    auto fetch = [&](int t, int buf) {
        int k0 = t * 32;
        #pragma unroll
        for (int r = 0; r < 2; r++) {
            int id = tid + 256 * r;
            int row = id >> 2, ch = id & 3;
            CP_ASYNC16(sA + (uint32_t)(buf * 128 * STRB + row * STRB + ch * 16),
                       A + (size_t)(m_cta + row) * lda + k0 + ch * 8);
        }
        #pragma unroll
        for (int r = 0; r < CN / 64; r++) {
            int id = tid + 256 * r;
            int row = id >> 2, ch = id & 3;
            CP_ASYNC16(sW + (uint32_t)(buf * CN * STRB + row * STRB + ch * 16),
                       W + (size_t)(n_cta + row) * ldw + k0 + ch * 8);
        }
        CP_COMMIT();
    };

    const int lq = lane >> 3, lr = lane & 7;
    const int aoff = ((lq & 1) * 8 + lr) * STRB + (lq >> 1) * 16;
    const int boff = ((lq >> 1) * 8 + lr) * STRB + (lq & 1) * 16;

    float acc[MT][4][4] = {};

    const int T = K / 32;
    fetch(0, 0);
    fetch(1, 1);
    if (T > 2) fetch(2, 2);
    for (int it = 0; it < T; it++) {
        const int buf = it & (NSTAGE - 1);
        if (it < T - 2)       { CP_WAIT2(); }
        else if (it == T - 2) { CP_WAIT1(); }
        else                  { CP_WAIT0(); }
        __syncthreads();
        if (it + 3 < T) fetch(it + 3, (it + 3) & (NSTAGE - 1));

        const uint32_t bA = sA + (uint32_t)(buf * 128 * STRB);
        const uint32_t bW = sW + (uint32_t)(buf * CN  * STRB);
        #pragma unroll
        for (int ks = 0; ks < 2; ks++) {
            const int kb = ks * 32;
            uint32_t af[MT][4];
            #pragma unroll
            for (int im = 0; im < MT; im++)
                ldsm_x4(af[im], bA + (uint32_t)((wm * MT * 16 + im * 16) * STRB + aoff + kb));
            uint32_t bf[2][4];
            #pragma unroll
            for (int ip = 0; ip < 2; ip++)
                ldsm_x4(bf[ip], bW + (uint32_t)((wn * 32 + ip * 16) * STRB + boff + kb));
            #pragma unroll
            for (int im = 0; im < MT; im++)
                #pragma unroll
                for (int in = 0; in < 4; in++)
                    mma_f16(acc[im][in], af[im], &bf[in >> 1][(in & 1) * 2]);
        }
    }

    #pragma unroll
    for (int im = 0; im < MT; im++) {
        int mrow0 = m_cta + wm * MT * 16 + im * 16 + g;
        #pragma unroll
        for (int in = 0; in < 4; in++) {
            int ncol0 = n_cta + wn * 32 + in * 8 + tg * 2;
            float2 bv = make_float2(0.f, 0.f);
            if (EPI >= 1) bv = *(const float2*)&bias[ncol0];
            #pragma unroll
            for (int h = 0; h < 2; h++) {
                int m = mrow0 + h * 8;
                float v0 = acc[im][in][h * 2 + 0];
                float v1 = acc[im][in][h * 2 + 1];
                if (EPI >= 1) { v0 += bv.x; v1 += bv.y; }
                if (EPI == 2) {
                    float2 rv = *(const float2*)&res[(size_t)m * ldc + ncol0];
                    v0 += rv.x; v1 += rv.y;
                }
                if (OUTH) {
                    __half2 hv = __floats2half2_rn(v0, v1);
                    if (EPI == 3) hv = silu_h2(hv);
                    *(__half2*)&((__half*)Cv)[(size_t)m * ldc + ncol0] = hv;
                } else {
                    *(float2*)&((float*)Cv)[(size_t)m * ldc + ncol0] = make_float2(v0, v1);
                }
            }
        }
    }
}

// ---------------- fp16 mma GEMM for pos projections (N=64, K=64) ---------------
// Output pre-scaled by SCALE2F (folds softmax scale + log2e into the tables).
__global__ void __launch_bounds__(256, 2) gemm_pos_kernel(
    const __half* __restrict__ A0,
    const __half* __restrict__ W0,
    __half* __restrict__ C0,
    const __half* __restrict__ Aa, const __half* __restrict__ Wa,
    __half* __restrict__ Ca)
{
    extern __shared__ char smem[];
    const uint32_t sb = (uint32_t)__cvta_generic_to_shared(smem);
    const uint32_t sA = sb;
    const uint32_t sW = sb + NSTAGE * 128 * STRB;

    const int tid  = threadIdx.x;
    const int wid  = tid >> 5, lane = tid & 31;
    const int g    = lane >> 2, tg = lane & 3;
    const int wm   = wid & 3, wn = wid >> 2;

    int zz = blockIdx.z & 63, sel = blockIdx.z >> 6;
    int bb = zz >> 3, hh = zz & 7;
    const __half* A = (sel ? Aa : A0) + (size_t)bb * Ssz * Dsz + hh * DHsz;
    const __half* W = (sel ? Wa : W0) + hh * DHsz;
    __half* C = (sel ? Ca : C0) + (size_t)zz * Ssz * NPOS;

    const int m_cta = blockIdx.y * 128;

    auto fetch = [&](int t, int buf) {
        int k0 = t * 32;
        #pragma unroll
        for (int r = 0; r < 2; r++) {
            int id = tid + 256 * r;
            int row = id >> 2, ch = id & 3;
            CP_ASYNC16(sA + (uint32_t)(buf * 128 * STRB + row * STRB + ch * 16),
                       A + (size_t)(m_cta + row) * Dsz + k0 + ch * 8);
        }
        {
            int row = tid >> 2, ch = tid & 3;
            if (row < 64)
                CP_ASYNC16(sW + (uint32_t)(buf * 64 * STRB + row * STRB + ch * 16),
                           W + (size_t)row * Dsz + k0 + ch * 8);
        }
        CP_COMMIT();
    };

    const int lq = lane >> 3, lr = lane & 7;
    const int aoff = ((lq & 1) * 8 + lr) * STRB + (lq >> 1) * 16;
    const int boff = ((lq >> 1) * 8 + lr) * STRB + (lq & 1) * 16;

    float acc[2][4][4] = {};
    const int T = 2;   // K=64
    fetch(0, 0); fetch(1, 1);
    for (int it = 0; it < T; it++) {
        const int buf = it & (NSTAGE - 1);
        if (it == T - 2) { CP_WAIT1(); } else { CP_WAIT0(); }
        __syncthreads();

        const uint32_t bA = sA + (uint32_t)(buf * 128 * STRB);
        const uint32_t bW = sW + (uint32_t)(buf * 64  * STRB);
        #pragma unroll
        for (int ks = 0; ks < 2; ks++) {
            const int kb = ks * 32;
            uint32_t af[2][4];
            #pragma unroll
            for (int im = 0; im < 2; im++)
                ldsm_x4(af[im], bA + (uint32_t)((wm * 32 + im * 16) * STRB + aoff + kb));
            uint32_t bf[2][4];
            #pragma unroll
            for (int ip = 0; ip < 2; ip++)
                ldsm_x4(bf[ip], bW + (uint32_t)((wn * 32 + ip * 16) * STRB + boff + kb));
            #pragma unroll
            for (int im = 0; im < 2; im++)
                #pragma unroll
                for (int in = 0; in < 4; in++)
                    mma_f16(acc[im][in], af[im], &bf[in >> 1][(in & 1) * 2]);
        }
    }

    #pragma unroll
    for (int im = 0; im < 2; im++) {
        int mrow0 = m_cta + wm * 32 + im * 16 + g;
        #pragma unroll
        for (int in = 0; in < 4; in++) {
            int ncol0 = wn * 32 + in * 8 + tg * 2;
            #pragma unroll
            for (int h = 0; h < 2; h++) {
                int m = mrow0 + h * 8;
                *(__half2*)&C[(size_t)m * NPOS + ncol0] =
                    __floats2half2_rn(acc[im][in][h * 2] * SCALE2F,
                                      acc[im][in][h * 2 + 1] * SCALE2F);
            }
        }
    }
}

// ---------------- small SIMT GEMM (pos-emb projections, fp32 in, half out) -----
#define TK 16
#define TPAD 68
__global__ void gemm_tn_small_kernel(const float* __restrict__ A, int lda,
                                     const float* __restrict__ W0, int ldw,
                                     const float* __restrict__ b0,
                                     __half* __restrict__ C0,
                                     const float* __restrict__ W1,
                                     const float* __restrict__ b1,
                                     __half* __restrict__ C1, int ldc, int Kd) {
    const float* W   = blockIdx.z ? W1 : W0;
    const float* bias= blockIdx.z ? b1 : b0;
    __half* C        = blockIdx.z ? C1 : C0;
    int m0 = blockIdx.y * 64, n0 = blockIdx.x * 64;
    __shared__ float As[TK][TPAD];
    __shared__ float Ws2[TK][TPAD];
    const int tid = threadIdx.x;
    const int tx = tid & 15, ty = tid >> 4;
    const int lk = tid & 15, lm = tid >> 4;
    float acc[4][4] = {};
    for (int k0 = 0; k0 < Kd; k0 += TK) {
        #pragma unroll
        for (int r = 0; r < 4; r++) {
            As[lk][lm + 16 * r]  = A[(size_t)(m0 + lm + 16 * r) * lda + k0 + lk];
            Ws2[lk][lm + 16 * r] = W[(size_t)(n0 + lm + 16 * r) * ldw + k0 + lk];
        }
        __syncthreads();
        #pragma unroll
        for (int kk = 0; kk < TK; kk++) {
            float4 a = *(const float4*)&As[kk][ty * 4];
            float4 b = *(const float4*)&Ws2[kk][tx * 4];
            float av[4] = {a.x, a.y, a.z, a.w};
            float bv[4] = {b.x, b.y, b.z, b.w};
            #pragma unroll
            for (int i = 0; i < 4; i++)
                #pragma unroll
                for (int j = 0; j < 4; j++)
                    acc[i][j] += av[i] * bv[j];
        }
        __syncthreads();
    }
    #pragma unroll
    for (int i = 0; i < 4; i++) {
        int m = m0 + ty * 4 + i;
        #pragma unroll
        for (int j = 0; j < 4; j += 2) {
            int n = n0 + tx * 4 + j;
            *(__half2*)&C[(size_t)m * ldc + n] =
                __floats2half2_rn(acc[i][j] + bias[n], acc[i][j+1] + bias[n+1]);
        }
    }
}

// =========================== fused flash attention (fp16 mma) ==================
// smem gathers (half tables pre-scaled), half2 softmax arithmetic, register P.
#define STRF 144
#define FA_K(buf)   ((buf) * 64 * STRF)
#define FA_V(buf)   (2 * 64 * STRF + (buf) * 64 * STRF)
#define FA_Q        (4 * 64 * STRF)
#define FA_C2P      (FA_Q + 128 * STRF)
#define FA_P2C(buf) (FA_C2P + 16384 + (buf) * 8192)
#define FA_LUT      (FA_C2P + 16384 + 16384)
#define FA_SMEM     (FA_LUT + 2048 * 4)

__global__ void __launch_bounds__(256, 2) flash_attn_kernel(
    const __half* __restrict__ qg, const __half* __restrict__ kg,
    const __half* __restrict__ vt,
    const __half* __restrict__ c2p, const __half* __restrict__ p2c,
    const int* __restrict__ lut, __half* __restrict__ ctx)
{
    extern __shared__ char smc[];
    int* lut_s = (int*)(smc + FA_LUT);

    const int tid = threadIdx.x, w = tid >> 5, lane = tid & 31;
    const int g = lane >> 2, tg = lane & 3;
    const int z = blockIdx.z, bb = z >> 3, hh = z & 7;
    const int i0 = blockIdx.x * 128;

    const __half* c2pz = c2p + (size_t)z * Ssz * NPOS;
    const __half* p2cz = p2c + (size_t)z * Ssz * NPOS;

    const uint32_t sb = (uint32_t)__cvta_generic_to_shared(smc);

    #pragma unroll
    for (int t = 0; t < 8; t++) {
        int idx = tid + 256 * t;
        if (idx < 2 * Ssz - 1) lut_s[idx] = lut[idx];
    }

    auto loadKV = [&](int jt, int buf) {
        int j0 = jt * 64;
        #pragma unroll
        for (int c = 0; c < 2; c++) {
            int id = tid * 2 + c;
            int row = id >> 3, ch = id & 7;
            CP_ASYNC16(sb + (uint32_t)(FA_K(buf) + row * STRF + ch * 16),
                       kg + ((size_t)bb * Ssz + j0 + row) * Dsz + hh * DHsz + ch * 8);
        }
        #pragma unroll
        for (int c = 0; c < 2; c++) {
            int id = tid * 2 + c;
            int row = id >> 3, ch = id & 7;
            CP_ASYNC16(sb + (uint32_t)(FA_V(buf) + row * STRF + ch * 16),
                       vt + ((size_t)bb * Dsz + hh * DHsz + row) * Ssz + j0 + ch * 8);
        }
        #pragma unroll
        for (int c = 0; c < 2; c++) {
            int id = tid * 2 + c;
            int row = id >> 3, ch = id & 7;
            CP_ASYNC16(sb + (uint32_t)(FA_P2C(buf) + row * 128 + ch * 16),
                       p2cz + (size_t)(j0 + row) * NPOS + ch * 8);
        }
        CP_COMMIT();
    };

    #pragma unroll
    for (int c = 0; c < 4; c++) {
        int id = tid * 4 + c;
        int row = id >> 3, ch = id & 7;
        CP_ASYNC16(sb + (uint32_t)(FA_Q + row * STRF + ch * 16),
                   qg + ((size_t)bb * Ssz + i0 + row) * Dsz + hh * DHsz + ch * 8);
    }
    #pragma unroll
    for (int c = 0; c < 4; c++) {
        int id = tid * 4 + c;
        int row = id >> 3, ch = id & 7;
        CP_ASYNC16(sb + (uint32_t)(FA_C2P + row * 128 + ch * 16),
                   c2pz + (size_t)(i0 + row) * NPOS + ch * 8);
    }
    CP_COMMIT();
    loadKV(0, 0);

    CP_WAIT1();
    __syncthreads();

    const int lq = lane >> 3, lr = lane & 7;
    const int aoffF = ((lq & 1) * 8 + lr) * STRF + (lq >> 1) * 16;
    const int boffF = ((lq >> 1) * 8 + lr) * STRF + (lq & 1) * 16;

    uint32_t qf[4][4];
    #pragma unroll
    for (int kc = 0; kc < 4; kc++)
        ldsm_x4(qf[kc], sb + (uint32_t)(FA_Q + (w * 16) * STRF + aoffF + kc * 32));

    const __half* c2ps = (const __half*)(smc + FA_C2P);
    const int crow0 = (w * 16 + g) * 64;
    const int crow1 = crow0 + 8 * 64;

    float acc_o[8][4] = {};
    float m_r[2] = {-1e30f, -1e30f};
    float l_r[2] = {0.f, 0.f};
    const int mg0 = i0 + w * 16 + g;

    for (int jt = 0; jt < 16; jt++) {
        const int buf = jt & 1;
        const int j0 = jt * 64;
        CP_WAIT0();
        __syncthreads();
        if (jt < 15) loadKV(jt + 1, buf ^ 1);

        // ---- S = Q K^T (64 cols) ----
        float acc_s[8][4] = {};
        #pragma unroll
        for (int kc = 0; kc < 4; kc++) {
            #pragma unroll
            for (int ip = 0; ip < 4; ip++) {
                uint32_t bf[4];
                ldsm_x4(bf, sb + (uint32_t)(FA_K(buf) + (ip * 16) * STRF + boffF + kc * 32));
                mma_f16(acc_s[ip * 2],     qf[kc], &bf[0]);
                mma_f16(acc_s[ip * 2 + 1], qf[kc], &bf[2]);
            }
        }

        // ---- bias + softmax in half2 (tables pre-scaled by SCALE2F) ----
        const __half* p2cs = (const __half*)(smc + FA_P2C(buf));
        __half2 s01[8], s23[8];
        __half2 mx0h = __floats2half2_rn(-60000.f, -60000.f);
        __half2 mx1h = mx0h;
        #pragma unroll
        for (int in = 0; in < 8; in++) {
            int nloc = in * 8 + tg * 2;
            int dbase = mg0 - j0 - nloc + (Ssz - 1);
            int i00 = lut_s[dbase];
            int i01 = lut_s[dbase - 1];
            int i10 = lut_s[dbase + 8];
            int i11 = lut_s[dbase + 7];
            __half2 b01 = __hadd2(__halves2half2(c2ps[crow0 + i00], c2ps[crow0 + i01]),
                                  __halves2half2(p2cs[nloc * 64 + i00], p2cs[(nloc + 1) * 64 + i01]));
            __half2 b23 = __hadd2(__halves2half2(c2ps[crow1 + i10], c2ps[crow1 + i11]),
                                  __halves2half2(p2cs[nloc * 64 + i10], p2cs[(nloc + 1) * 64 + i11]));
            __half2 v01 = __hadd2(__floats2half2_rn(acc_s[in][0] * SCALE2F,
                                                    acc_s[in][1] * SCALE2F), b01);
            __half2 v23 = __hadd2(__floats2half2_rn(acc_s[in][2] * SCALE2F,
                                                    acc_s[in][3] * SCALE2F), b23);
            s01[in] = v01; s23[in] = v23;
            mx0h = __hmax2(mx0h, v01);
            mx1h = __hmax2(mx1h, v23);
        }
        float mx0 = fmaxf(__low2float(mx0h), __high2float(mx0h));
        float mx1 = fmaxf(__low2float(mx1h), __high2float(mx1h));
        mx0 = fmaxf(mx0, __shfl_xor_sync(0xffffffffu, mx0, 1));
        mx0 = fmaxf(mx0, __shfl_xor_sync(0xffffffffu, mx0, 2));
        mx1 = fmaxf(mx1, __shfl_xor_sync(0xffffffffu, mx1, 1));
        mx1 = fmaxf(mx1, __shfl_xor_sync(0xffffffffu, mx1, 2));
        float mn0 = fmaxf(m_r[0], mx0), mn1 = fmaxf(m_r[1], mx1);
        float al0 = exp2f(m_r[0] - mn0), al1 = exp2f(m_r[1] - mn1);
        __half2 mn0h = __float2half2_rn(mn0);
        __half2 mn1h = __float2half2_rn(mn1);
        float s0 = 0.f, s1 = 0.f;
        uint32_t u01[8], u23[8];
        #pragma unroll
        for (int in = 0; in < 8; in++) {
            __half2 e01 = h2exp2(__hsub2(s01[in], mn0h));
            __half2 e23 = h2exp2(__hsub2(s23[in], mn1h));
            u01[in] = *(uint32_t*)&e01;
            u23[in] = *(uint32_t*)&e23;
            float2 f01 = __half22float2(e01);
            float2 f23 = __half22float2(e23);
            s0 += f01.x + f01.y; s1 += f23.x + f23.y;
        }
        l_r[0] = l_r[0] * al0 + s0;
        l_r[1] = l_r[1] * al1 + s1;
        m_r[0] = mn0; m_r[1] = mn1;
        #pragma unroll
        for (int nf = 0; nf < 8; nf++) {
            acc_o[nf][0] *= al0; acc_o[nf][1] *= al0;
            acc_o[nf][2] *= al1; acc_o[nf][3] *= al1;
        }

        // ---- O += P V ----
        #pragma unroll
        for (int kc2 = 0; kc2 < 4; kc2++) {
            uint32_t af[4];
            af[0] = u01[kc2 * 2];
            af[1] = u23[kc2 * 2];
            af[2] = u01[kc2 * 2 + 1];
            af[3] = u23[kc2 * 2 + 1];
            #pragma unroll
            for (int ip = 0; ip < 4; ip++) {
                uint32_t bf[4];
                ldsm_x4(bf, sb + (uint32_t)(FA_V(buf) + (ip * 16) * STRF + boffF + kc2 * 32));
                mma_f16(acc_o[ip * 2],     af, &bf[0]);
                mma_f16(acc_o[ip * 2 + 1], af, &bf[2]);
            }
        }
    }

    float l0 = l_r[0];
    l0 += __shfl_xor_sync(0xffffffffu, l0, 1);
    l0 += __shfl_xor_sync(0xffffffffu, l0, 2);
    float l1 = l_r[1];
    l1 += __shfl_xor_sync(0xffffffffu, l1, 1);
    l1 += __shfl_xor_sync(0xffffffffu, l1, 2);
    float inv0 = 1.0f / l0, inv1 = 1.0f / l1;
    __half* c0 = ctx + ((size_t)bb * Ssz + mg0)     * Dsz + hh * DHsz;
    __half* c1 = ctx + ((size_t)bb * Ssz + mg0 + 8) * Dsz + hh * DHsz;
    #pragma unroll
    for (int nf = 0; nf < 8; nf++) {
        int col = nf * 8 + tg * 2;
        *(__half2*)&c0[col] = __floats2half2_rn(acc_o[nf][0] * inv0, acc_o[nf][1] * inv0);
        *(__half2*)&c1[col] = __floats2half2_rn(acc_o[nf][2] * inv1, acc_o[nf][3] * inv1);
    }
}

// =============================== launch ========================================
extern "C" void kernel_launch(void* const* d_in, const int* in_sizes, int n_in,
                              void* d_out, int out_size) {
    const float* x      = (const float*)d_in[0];
    const float* ln1g   = (const float*)d_in[1];
    const float* ln1b   = (const float*)d_in[2];
    const float* dww    = (const float*)d_in[3];
    const float* dwb    = (const float*)d_in[4];
    const float* pww    = (const float*)d_in[5];
    const float* pwb    = (const float*)d_in[6];
    const float* ln2g   = (const float*)d_in[7];
    const float* ln2b   = (const float*)d_in[8];
    const float* qw     = (const float*)d_in[9];
    const float* qb     = (const float*)d_in[10];
    const float* kw     = (const float*)d_in[11];
    const float* kb     = (const float*)d_in[12];
    const float* vw     = (const float*)d_in[13];
    const float* vb     = (const float*)d_in[14];
    const float* ow     = (const float*)d_in[15];
    const float* ob     = (const float*)d_in[16];
    const float* relemb = (const float*)d_in[17];
    const float* ln3g   = (const float*)d_in[18];
    const float* ln3b   = (const float*)d_in[19];
    const float* w1     = (const float*)d_in[20];
    const float* b1     = (const float*)d_in[21];
    const float* w2     = (const float*)d_in[22];
    const float* b2     = (const float*)d_in[23];
    float* out = (float*)d_out;

    float *x1, *x2; int* lut;
    __half *c2p, *p2c;
    __half *xnh, *convh, *qh, *kh, *vh, *vth, *ctxh, *ffh, *poskh, *posqh;
    __half *pwwh, *qwh, *kwh, *vwh, *owh, *w1h, *w2h;
    cudaGetSymbolAddress((void**)&x1,    g_x1);
    cudaGetSymbolAddress((void**)&x2,    g_x2);
    cudaGetSymbolAddress((void**)&c2p,   g_c2p);
    cudaGetSymbolAddress((void**)&p2c,   g_p2c);
    cudaGetSymbolAddress((void**)&lut,   g_lut);
    cudaGetSymbolAddress((void**)&xnh,   g_xnh);
    cudaGetSymbolAddress((void**)&convh, g_convh);
    cudaGetSymbolAddress((void**)&qh,    g_qh);
    cudaGetSymbolAddress((void**)&kh,    g_kh);
    cudaGetSymbolAddress((void**)&vh,    g_vh);
    cudaGetSymbolAddress((void**)&vth,   g_vth);
    cudaGetSymbolAddress((void**)&ctxh,  g_ctxh);
    cudaGetSymbolAddress((void**)&ffh,   g_ffh);
    cudaGetSymbolAddress((void**)&poskh, g_poskh);
    cudaGetSymbolAddress((void**)&posqh, g_posqh);
    cudaGetSymbolAddress((void**)&pwwh,  g_pwwh);
    cudaGetSymbolAddress((void**)&qwh,   g_qwh);
    cudaGetSymbolAddress((void**)&kwh,   g_kwh);
    cudaGetSymbolAddress((void**)&vwh,   g_vwh);
    cudaGetSymbolAddress((void**)&owh,   g_owh);
    cudaGetSymbolAddress((void**)&w1h,   g_w1h);
    cudaGetSymbolAddress((void**)&w2h,   g_w2h);

    static int attr_set = 0;
    if (!attr_set) {
        cudaFuncSetAttribute(flash_attn_kernel,
                             cudaFuncAttributeMaxDynamicSharedMemorySize, FA_SMEM);
        cudaFuncSetAttribute(gemm_mma_kernel<128,2,0,0>,
                             cudaFuncAttributeMaxDynamicSharedMemorySize, GEMM_SMEMH(128));
        cudaFuncSetAttribute(gemm_mma_kernel<128,1,4,1>,
                             cudaFuncAttributeMaxDynamicSharedMemorySize, GEMM_SMEMH(128));
        cudaFuncSetAttribute(gemm_mma_kernel<128,3,0,1>,
                             cudaFuncAttributeMaxDynamicSharedMemorySize, GEMM_SMEMH(128));
        cudaFuncSetAttribute(gemm_pos_kernel,
                             cudaFuncAttributeMaxDynamicSharedMemorySize, GEMM_SMEMH(64));
        attr_set = 1;
    }

    setup_kernel<<<dim3(256, 1, 8), 256>>>(pww, qw, kw, vw, ow, w1, w2,
                                           pwwh, qwh, kwh, vwh, owh, w1h, w2h, lut);

    // ---- conv block (fused LN1 + dwconv + silu) ----
    ln_dwconv_silu_kernel<<<dim3(Ssz/4, Bsz), 256>>>(x, ln1g, ln1b, dww, dwb, convh);
    gemm_mma_kernel<128,2,0,0><<<dim3(Dsz/128, NROWS/128, 1), 256, GEMM_SMEMH(128)>>>(
        convh, Dsz, pwwh, Dsz, pwb, x, x1, Dsz, Dsz,
        nullptr, nullptr, nullptr, nullptr, nullptr, nullptr);

    // ---- attention block ----
    layernorm_kernel<<<NROWS, 256>>>(x1, ln2g, ln2b, xnh);
    gemm_mma_kernel<128,1,4,1><<<dim3(Dsz/128, NROWS/128, 3), 256, GEMM_SMEMH(128)>>>(
        xnh, Dsz, qwh, Dsz, qb, nullptr, qh, Dsz, Dsz,
        kwh, vwh, kb, vb, kh, vh);
    transpose_v_kernel<<<dim3(Ssz/64, Dsz/64, Bsz), 256>>>(vh, vth);

    gemm_tn_small_kernel<<<dim3(Dsz/64, 1, 2), 256>>>(
        relemb, Dsz, kw, Dsz, kb, poskh, qw, qb, posqh, Dsz, Dsz);

    gemm_pos_kernel<<<dim3(1, Ssz/128, 2*Bsz*Hsz), 256, GEMM_SMEMH(64)>>>(
        qh, poskh, c2p, kh, posqh, p2c);

    flash_attn_kernel<<<dim3(Ssz/128, 1, Bsz*Hsz), 256, FA_SMEM>>>(
        qh, kh, vth, c2p, p2c, lut, ctxh);

    gemm_mma_kernel<128,2,0,0><<<dim3(Dsz/128, NROWS/128, 1), 256, GEMM_SMEMH(128)>>>(
        ctxh, Dsz, owh, Dsz, ob, x1, x2, Dsz, Dsz,
        nullptr, nullptr, nullptr, nullptr, nullptr, nullptr);

    // ---- FFN block ----
    layernorm_kernel<<<NROWS, 256>>>(x2, ln3g, ln3b, xnh);
    gemm_mma_kernel<128,3,0,1><<<dim3(FFsz/128, NROWS/128, 1), 256, GEMM_SMEMH(128)>>>(
        xnh, Dsz, w1h, Dsz, b1, nullptr, ffh, FFsz, Dsz,
        nullptr, nullptr, nullptr, nullptr, nullptr, nullptr);
    gemm_mma_kernel<128,2,0,0><<<dim3(Dsz/128, NROWS/128, 1), 256, GEMM_SMEMH(128)>>>(
        ffh, FFsz, w2h, FFsz, b2, x2, out, Dsz, FFsz,
        nullptr, nullptr, nullptr, nullptr, nullptr, nullptr);
}

// round 16
// speedup vs baseline: 1.6563x; 1.0166x over previous
#include <cuda_runtime.h>
#include <cuda_fp16.h>
#include <math.h>
#include <stdint.h>

#define Bsz 8
#define Ssz 1024
#define Dsz 512
#define Hsz 8
#define DHsz 64
#define FFsz 1024
#define NPOS 64          // 2*SPAN
#define NROWS (Bsz*Ssz)  // 8192

// ---------------- scratch (device globals; no allocation allowed) ------------
__device__ float  g_x1  [Bsz*Ssz*Dsz];
__device__ float  g_x2  [Bsz*Ssz*Dsz];
__device__ __half g_c2p [Bsz*Hsz*Ssz*NPOS];   // pre-scaled by SCALE*log2(e)
__device__ __half g_p2c [Bsz*Hsz*Ssz*NPOS];   // pre-scaled
__device__ int    g_lut [2*Ssz];
__device__ __half g_xnh  [Bsz*Ssz*Dsz];
__device__ __half g_convh[Bsz*Ssz*Dsz];
__device__ __half g_qh   [Bsz*Ssz*Dsz];
__device__ __half g_kh   [Bsz*Ssz*Dsz];
__device__ __half g_vh   [Bsz*Ssz*Dsz];
__device__ __half g_vth  [Bsz*Ssz*Dsz];   // [B, D, S]
__device__ __half g_ctxh [Bsz*Ssz*Dsz];
__device__ __half g_ffh  [Bsz*Ssz*FFsz];
__device__ __half g_poskh[NPOS*Dsz];
__device__ __half g_posqh[NPOS*Dsz];
__device__ __half g_pwwh[Dsz*Dsz];
__device__ __half g_qwh [Dsz*Dsz];
__device__ __half g_kwh [Dsz*Dsz];
__device__ __half g_vwh [Dsz*Dsz];
__device__ __half g_owh [Dsz*Dsz];
__device__ __half g_w1h [FFsz*Dsz];
__device__ __half g_w2h [FFsz*Dsz];

#define SCALE2F (0.07216878364870323f * 1.4426950408889634f)  // 1/sqrt(192)*log2(e)

// ---------------- half2 silu helper ---------------------------------------------
__device__ __forceinline__ __half2 silu_h2(__half2 hv) {
    const __half2 nl2e = __floats2half2_rn(-1.4426950408889634f, -1.4426950408889634f);
    const __half2 one2 = __floats2half2_rn(1.0f, 1.0f);
    return __hmul2(hv, h2rcp(__hadd2(one2, h2exp2(__hmul2(hv, nl2e)))));
}

// ---------------- setup: weights fp32->fp16 + rel-pos LUT (merged) -------------
__global__ void setup_kernel(const float* __restrict__ s0, const float* __restrict__ s1,
                             const float* __restrict__ s2, const float* __restrict__ s3,
                             const float* __restrict__ s4, const float* __restrict__ s5,
                             const float* __restrict__ s6,
                             __half* d0, __half* d1, __half* d2, __half* d3,
                             __half* d4, __half* d5, __half* d6, int* __restrict__ lut) {
    int z = blockIdx.z;
    if (z == 7) {   // LUT
        int t = blockIdx.x * blockDim.x + threadIdx.x;
        if (t >= 2*Ssz - 1) return;
        int rel = t - (Ssz - 1);
        const int mid = 16;
        int bucket;
        if (rel > -mid && rel < mid) {
            bucket = rel;
        } else {
            float absp = fabsf((float)rel);
            if (absp <= (float)mid) {
                bucket = rel;
            } else {
                float logp = ceilf(logf(absp / 16.0f) / logf(127.0f / 16.0f) * 15.0f) + 16.0f;
                bucket = (rel > 0 ? 1 : -1) * (int)logp;
            }
        }
        int idx = bucket + 32;
        lut[t] = min(max(idx, 0), 63);
        return;
    }
    const float* s; __half* d; int n;
    switch (z) {
        case 0: s = s0; d = d0; n = Dsz*Dsz;  break;
        case 1: s = s1; d = d1; n = Dsz*Dsz;  break;
        case 2: s = s2; d = d2; n = Dsz*Dsz;  break;
        case 3: s = s3; d = d3; n = Dsz*Dsz;  break;
        case 4: s = s4; d = d4; n = Dsz*Dsz;  break;
        case 5: s = s5; d = d5; n = FFsz*Dsz; break;
        default:s = s6; d = d6; n = FFsz*Dsz; break;
    }
    for (int i = blockIdx.x * blockDim.x + threadIdx.x; i * 2 < n; i += gridDim.x * blockDim.x) {
        float2 f = *(const float2*)&s[i * 2];
        *(__half2*)&d[i * 2] = __floats2half2_rn(f.x, f.y);
    }
}

// ---------------- LayerNorm (warp-per-row, no barriers) -> half ----------------
__global__ void __launch_bounds__(256, 6) layernorm_kernel(
    const float* __restrict__ x,
    const float* __restrict__ g,
    const float* __restrict__ bb,
    __half* __restrict__ out) {
    const int wd = threadIdx.x >> 5, lane = threadIdx.x & 31;
    const size_t row = (size_t)blockIdx.x * 8 + wd;
    const float* xr = x + row * Dsz;
    __half* orow = out + row * Dsz;

    float4 v[4];
    float sum = 0.f, ssq = 0.f;
    #pragma unroll
    for (int r = 0; r < 4; r++) {
        v[r] = *(const float4*)&xr[r * 128 + lane * 4];
        sum += v[r].x + v[r].y + v[r].z + v[r].w;
        ssq += v[r].x * v[r].x + v[r].y * v[r].y + v[r].z * v[r].z + v[r].w * v[r].w;
    }
    #pragma unroll
    for (int o = 16; o; o >>= 1) {
        sum += __shfl_xor_sync(0xffffffffu, sum, o);
        ssq += __shfl_xor_sync(0xffffffffu, ssq, o);
    }
    float mean = sum * (1.0f / Dsz);
    float var  = ssq * (1.0f / Dsz) - mean * mean;
    float rs = rsqrtf(var + 1e-5f);

    #pragma unroll
    for (int r = 0; r < 4; r++) {
        int c = r * 128 + lane * 4;
        float4 gg = *(const float4*)&g[c];
        float4 bv = *(const float4*)&bb[c];
        __half2 h0 = __floats2half2_rn((v[r].x - mean) * rs * gg.x + bv.x,
                                       (v[r].y - mean) * rs * gg.y + bv.y);
        __half2 h1 = __floats2half2_rn((v[r].z - mean) * rs * gg.z + bv.z,
                                       (v[r].w - mean) * rs * gg.w + bv.w);
        uint2 pk;
        pk.x = *(uint32_t*)&h0;
        pk.y = *(uint32_t*)&h1;
        *(uint2*)&orow[c] = pk;
    }
}

// ---------------- fused LN1 + depthwise conv (K=3) + silu ----------------------
__global__ void __launch_bounds__(256, 4) ln_dwconv_silu_kernel(
    const float* __restrict__ x,
    const float* __restrict__ g, const float* __restrict__ bb,
    const float* __restrict__ w, const float* __restrict__ bias,
    __half* __restrict__ out)
{
    __shared__ __half xs[6][Dsz];
    const int b = blockIdx.y;
    const int s0 = blockIdx.x * 4;
    const int tid = threadIdx.x, wd = tid >> 5, lane = tid & 31;

    if (wd < 6) {
        int s = s0 - 1 + wd;
        if (s >= 0 && s < Ssz) {
            const float* xr = x + ((size_t)b * Ssz + s) * Dsz;
            float v[16];
            float sum = 0.f, ssq = 0.f;
            #pragma unroll
            for (int i = 0; i < 16; i++) {
                v[i] = xr[lane + 32 * i];
                sum += v[i]; ssq += v[i] * v[i];
            }
            #pragma unroll
            for (int o = 16; o; o >>= 1) {
                sum += __shfl_xor_sync(0xffffffffu, sum, o);
                ssq += __shfl_xor_sync(0xffffffffu, ssq, o);
            }
            float mean = sum * (1.0f / Dsz);
            float var  = ssq * (1.0f / Dsz) - mean * mean;
            float rs = rsqrtf(var + 1e-5f);
            #pragma unroll
            for (int i = 0; i < 16; i++) {
                int d = lane + 32 * i;
                xs[wd][d] = __float2half((v[i] - mean) * rs * g[d] + bb[d]);
            }
        } else {
            #pragma unroll
            for (int i = 0; i < 16; i++)
                xs[wd][lane + 32 * i] = __float2half(0.f);
        }
    }
    __syncthreads();

    const int d2 = tid, d = d2 * 2;
    float2 wc0 = *(const float2*)&w[d*3];
    float  wc2 = w[d*3+2];
    float  w10 = w[d*3+3];
    float2 wc3 = *(const float2*)&w[d*3+4];
    float2 bv  = *(const float2*)&bias[d];

    float2 xv[6];
    #pragma unroll
    for (int r = 0; r < 6; r++)
        xv[r] = __half22float2(*(const __half2*)&xs[r][d]);

    __half2* orow = (__half2*)out + ((size_t)b * Ssz + s0) * (Dsz/2) + d2;
    #pragma unroll
    for (int t = 0; t < 4; t++) {
        float a0 = bv.x + xv[t].x * wc0.x + xv[t+1].x * wc0.y + xv[t+2].x * wc2;
        float a1 = bv.y + xv[t].y * w10   + xv[t+1].y * wc3.x + xv[t+2].y * wc3.y;
        orow[t * (Dsz/2)] = silu_h2(__floats2half2_rn(a0, a1));
    }
}

// ---------------- V transpose: [B,S,D] -> [B,D,S] (half2 both sides) -----------
__global__ void transpose_v_kernel(const __half* __restrict__ v, __half* __restrict__ vt) {
    __shared__ __half tile[64][66];
    int b = blockIdx.z;
    int s0 = blockIdx.x * 64, d0 = blockIdx.y * 64;
    int tx = threadIdx.x & 31, ty = threadIdx.x >> 5;   // 32 x 8
    #pragma unroll
    for (int j = 0; j < 64; j += 8) {
        __half2 hv = *(const __half2*)&v[((size_t)b * Ssz + s0 + ty + j) * Dsz + d0 + tx * 2];
        tile[ty + j][tx * 2]     = __low2half(hv);
        tile[ty + j][tx * 2 + 1] = __high2half(hv);
    }
    __syncthreads();
    #pragma unroll
    for (int j = 0; j < 64; j += 8) {
        int d = ty + j;
        __half2 hv = __halves2half2(tile[tx * 2][d], tile[tx * 2 + 1][d]);
        *(__half2*)&vt[((size_t)b * Dsz + d0 + d) * Ssz + s0 + tx * 2] = hv;
    }
}

// ---------------- mma.f16 + ldmatrix helpers -----------------------------------
__device__ __forceinline__ void mma_f16(float c[4], const uint32_t a[4], const uint32_t b[2]) {
    asm volatile(
        "mma.sync.aligned.m16n8k16.row.col.f32.f16.f16.f32 "
        "{%0,%1,%2,%3}, {%4,%5,%6,%7}, {%8,%9}, {%0,%1,%2,%3};"
        : "+f"(c[0]), "+f"(c[1]), "+f"(c[2]), "+f"(c[3])
        : "r"(a[0]), "r"(a[1]), "r"(a[2]), "r"(a[3]), "r"(b[0]), "r"(b[1]));
}

__device__ __forceinline__ void ldsm_x4(uint32_t r[4], uint32_t addr) {
    asm volatile("ldmatrix.sync.aligned.m8n8.x4.shared.b16 {%0,%1,%2,%3}, [%4];"
                 : "=r"(r[0]), "=r"(r[1]), "=r"(r[2]), "=r"(r[3]) : "r"(addr));
}

#define CP_ASYNC16(dst_u32, src_ptr) \
    asm volatile("cp.async.ca.shared.global [%0], [%1], 16;" :: "r"(dst_u32), "l"(src_ptr))
#define CP_COMMIT() asm volatile("cp.async.commit_group;")
#define CP_WAIT2()  asm volatile("cp.async.wait_group 2;")
#define CP_WAIT1()  asm volatile("cp.async.wait_group 1;")
#define CP_WAIT0()  asm volatile("cp.async.wait_group 0;")

// ---------------- fp16 tensor-core TN GEMM (128xCN tiles, K32 chunks) ----------
#define STRB 80
#define NSTAGE 4
#define GEMM_SMEMH(CNv) (NSTAGE * (128 + (CNv)) * STRB)

template<int CN, int EPI, int MODE, int OUTH>
__global__ void __launch_bounds__(256, 2) gemm_mma_kernel(
    const __half* __restrict__ A0, int lda,
    const __half* __restrict__ W0, int ldw,
    const float* __restrict__ bias0, const float* __restrict__ res,
    void* __restrict__ C0v, int ldc, int K,
    const __half* __restrict__ Wa, const __half* __restrict__ Wb2,
    const float* __restrict__ ba, const float* __restrict__ bb2,
    void* __restrict__ Cav, void* __restrict__ Cbv)
{
    constexpr int NWN = CN / 32;
    constexpr int NWM = 8 / NWN;
    constexpr int MT  = 8 / NWM;

    extern __shared__ char smem[];
    const uint32_t sb = (uint32_t)__cvta_generic_to_shared(smem);
    const uint32_t sA = sb;
    const uint32_t sW = sb + NSTAGE * 128 * STRB;

    const int tid  = threadIdx.x;
    const int wid  = tid >> 5, lane = tid & 31;
    const int g    = lane >> 2, tg = lane & 3;
    const int wm   = wid % NWM, wn = wid / NWM;

    const int z = blockIdx.z;
    const __half* A = A0; const __half* W = W0; void* Cv = C0v;
    const float* bias = bias0;
    if (MODE == 4) {
        W    = (z == 0) ? W0 : (z == 1 ? Wa : Wb2);
        bias = (z == 0) ? bias0 : (z == 1 ? ba : bb2);
        Cv   = (z == 0) ? C0v : (z == 1 ? Cav : Cbv);
    }

    const int m_cta = blockIdx.y * 128, n_cta = blockIdx.x * CN;

    auto fetch = [&](int t, int buf) {
        int k0 = t * 32;
        #pragma unroll
        for (int r = 0; r < 2; r++) {
            int id = tid + 256 * r;
            int row = id >> 2, ch = id & 3;
            CP_ASYNC16(sA + (uint32_t)(buf * 128 * STRB + row * STRB + ch * 16),
                       A + (size_t)(m_cta + row) * lda + k0 + ch * 8);
        }
        #pragma unroll
        for (int r = 0; r < CN / 64; r++) {
            int id = tid + 256 * r;
            int row = id >> 2, ch = id & 3;
            CP_ASYNC16(sW + (uint32_t)(buf * CN * STRB + row * STRB + ch * 16),
                       W + (size_t)(n_cta + row) * ldw + k0 + ch * 8);
        }
        CP_COMMIT();
    };

    const int lq = lane >> 3, lr = lane & 7;
    const int aoff = ((lq & 1) * 8 + lr) * STRB + (lq >> 1) * 16;
    const int boff = ((lq >> 1) * 8 + lr) * STRB + (lq & 1) * 16;

    float acc[MT][4][4] = {};

    const int T = K / 32;
    fetch(0, 0);
    fetch(1, 1);
    if (T > 2) fetch(2, 2);
    for (int it = 0; it < T; it++) {
        const int buf = it & (NSTAGE - 1);
        if (it < T - 2)       { CP_WAIT2(); }
        else if (it == T - 2) { CP_WAIT1(); }
        else                  { CP_WAIT0(); }
        __syncthreads();
        if (it + 3 < T) fetch(it + 3, (it + 3) & (NSTAGE - 1));

        const uint32_t bA = sA + (uint32_t)(buf * 128 * STRB);
        const uint32_t bW = sW + (uint32_t)(buf * CN  * STRB);
        #pragma unroll
        for (int ks = 0; ks < 2; ks++) {
            const int kb = ks * 32;
            uint32_t af[MT][4];
            #pragma unroll
            for (int im = 0; im < MT; im++)
                ldsm_x4(af[im], bA + (uint32_t)((wm * MT * 16 + im * 16) * STRB + aoff + kb));
            uint32_t bf[2][4];
            #pragma unroll
            for (int ip = 0; ip < 2; ip++)
                ldsm_x4(bf[ip], bW + (uint32_t)((wn * 32 + ip * 16) * STRB + boff + kb));
            #pragma unroll
            for (int im = 0; im < MT; im++)
                #pragma unroll
                for (int in = 0; in < 4; in++)
                    mma_f16(acc[im][in], af[im], &bf[in >> 1][(in & 1) * 2]);
        }
    }

    #pragma unroll
    for (int im = 0; im < MT; im++) {
        int mrow0 = m_cta + wm * MT * 16 + im * 16 + g;
        #pragma unroll
        for (int in = 0; in < 4; in++) {
            int ncol0 = n_cta + wn * 32 + in * 8 + tg * 2;
            float2 bv = make_float2(0.f, 0.f);
            if (EPI >= 1) bv = *(const float2*)&bias[ncol0];
            #pragma unroll
            for (int h = 0; h < 2; h++) {
                int m = mrow0 + h * 8;
                float v0 = acc[im][in][h * 2 + 0];
                float v1 = acc[im][in][h * 2 + 1];
                if (EPI >= 1) { v0 += bv.x; v1 += bv.y; }
                if (EPI == 2) {
                    float2 rv = *(const float2*)&res[(size_t)m * ldc + ncol0];
                    v0 += rv.x; v1 += rv.y;
                }
                if (OUTH) {
                    __half2 hv = __floats2half2_rn(v0, v1);
                    if (EPI == 3) hv = silu_h2(hv);
                    *(__half2*)&((__half*)Cv)[(size_t)m * ldc + ncol0] = hv;
                } else {
                    *(float2*)&((float*)Cv)[(size_t)m * ldc + ncol0] = make_float2(v0, v1);
                }
            }
        }
    }
}

// ---------------- fp16 mma GEMM for pos projections (N=64, K=64) ---------------
__global__ void __launch_bounds__(256, 2) gemm_pos_kernel(
    const __half* __restrict__ A0,
    const __half* __restrict__ W0,
    __half* __restrict__ C0,
    const __half* __restrict__ Aa, const __half* __restrict__ Wa,
    __half* __restrict__ Ca)
{
    extern __shared__ char smem[];
    const uint32_t sb = (uint32_t)__cvta_generic_to_shared(smem);
    const uint32_t sA = sb;
    const uint32_t sW = sb + NSTAGE * 128 * STRB;

    const int tid  = threadIdx.x;
    const int wid  = tid >> 5, lane = tid & 31;
    const int g    = lane >> 2, tg = lane & 3;
    const int wm   = wid & 3, wn = wid >> 2;

    int zz = blockIdx.z & 63, sel = blockIdx.z >> 6;
    int bb = zz >> 3, hh = zz & 7;
    const __half* A = (sel ? Aa : A0) + (size_t)bb * Ssz * Dsz + hh * DHsz;
    const __half* W = (sel ? Wa : W0) + hh * DHsz;
    __half* C = (sel ? Ca : C0) + (size_t)zz * Ssz * NPOS;

    const int m_cta = blockIdx.y * 128;

    auto fetch = [&](int t, int buf) {
        int k0 = t * 32;
        #pragma unroll
        for (int r = 0; r < 2; r++) {
            int id = tid + 256 * r;
            int row = id >> 2, ch = id & 3;
            CP_ASYNC16(sA + (uint32_t)(buf * 128 * STRB + row * STRB + ch * 16),
                       A + (size_t)(m_cta + row) * Dsz + k0 + ch * 8);
        }
        {
            int row = tid >> 2, ch = tid & 3;
            if (row < 64)
                CP_ASYNC16(sW + (uint32_t)(buf * 64 * STRB + row * STRB + ch * 16),
                           W + (size_t)row * Dsz + k0 + ch * 8);
        }
        CP_COMMIT();
    };

    const int lq = lane >> 3, lr = lane & 7;
    const int aoff = ((lq & 1) * 8 + lr) * STRB + (lq >> 1) * 16;
    const int boff = ((lq >> 1) * 8 + lr) * STRB + (lq & 1) * 16;

    float acc[2][4][4] = {};
    const int T = 2;   // K=64
    fetch(0, 0); fetch(1, 1);
    for (int it = 0; it < T; it++) {
        const int buf = it & (NSTAGE - 1);
        if (it == T - 2) { CP_WAIT1(); } else { CP_WAIT0(); }
        __syncthreads();

        const uint32_t bA = sA + (uint32_t)(buf * 128 * STRB);
        const uint32_t bW = sW + (uint32_t)(buf * 64  * STRB);
        #pragma unroll
        for (int ks = 0; ks < 2; ks++) {
            const int kb = ks * 32;
            uint32_t af[2][4];
            #pragma unroll
            for (int im = 0; im < 2; im++)
                ldsm_x4(af[im], bA + (uint32_t)((wm * 32 + im * 16) * STRB + aoff + kb));
            uint32_t bf[2][4];
            #pragma unroll
            for (int ip = 0; ip < 2; ip++)
                ldsm_x4(bf[ip], bW + (uint32_t)((wn * 32 + ip * 16) * STRB + boff + kb));
            #pragma unroll
            for (int im = 0; im < 2; im++)
                #pragma unroll
                for (int in = 0; in < 4; in++)
                    mma_f16(acc[im][in], af[im], &bf[in >> 1][(in & 1) * 2]);
        }
    }

    #pragma unroll
    for (int im = 0; im < 2; im++) {
        int mrow0 = m_cta + wm * 32 + im * 16 + g;
        #pragma unroll
        for (int in = 0; in < 4; in++) {
            int ncol0 = wn * 32 + in * 8 + tg * 2;
            #pragma unroll
            for (int h = 0; h < 2; h++) {
                int m = mrow0 + h * 8;
                *(__half2*)&C[(size_t)m * NPOS + ncol0] =
                    __floats2half2_rn(acc[im][in][h * 2] * SCALE2F,
                                      acc[im][in][h * 2 + 1] * SCALE2F);
            }
        }
    }
}

// ---------------- small SIMT GEMM (pos-emb projections, fp32 in, half out) -----
#define TK 16
#define TPAD 68
__global__ void gemm_tn_small_kernel(const float* __restrict__ A, int lda,
                                     const float* __restrict__ W0, int ldw,
                                     const float* __restrict__ b0,
                                     __half* __restrict__ C0,
                                     const float* __restrict__ W1,
                                     const float* __restrict__ b1,
                                     __half* __restrict__ C1, int ldc, int Kd) {
    const float* W   = blockIdx.z ? W1 : W0;
    const float* bias= blockIdx.z ? b1 : b0;
    __half* C        = blockIdx.z ? C1 : C0;
    int m0 = blockIdx.y * 64, n0 = blockIdx.x * 64;
    __shared__ float As[TK][TPAD];
    __shared__ float Ws2[TK][TPAD];
    const int tid = threadIdx.x;
    const int tx = tid & 15, ty = tid >> 4;
    const int lk = tid & 15, lm = tid >> 4;
    float acc[4][4] = {};
    for (int k0 = 0; k0 < Kd; k0 += TK) {
        #pragma unroll
        for (int r = 0; r < 4; r++) {
            As[lk][lm + 16 * r]  = A[(size_t)(m0 + lm + 16 * r) * lda + k0 + lk];
            Ws2[lk][lm + 16 * r] = W[(size_t)(n0 + lm + 16 * r) * ldw + k0 + lk];
        }
        __syncthreads();
        #pragma unroll
        for (int kk = 0; kk < TK; kk++) {
            float4 a = *(const float4*)&As[kk][ty * 4];
            float4 b = *(const float4*)&Ws2[kk][tx * 4];
            float av[4] = {a.x, a.y, a.z, a.w};
            float bv[4] = {b.x, b.y, b.z, b.w};
            #pragma unroll
            for (int i = 0; i < 4; i++)
                #pragma unroll
                for (int j = 0; j < 4; j++)
                    acc[i][j] += av[i] * bv[j];
        }
        __syncthreads();
    }
    #pragma unroll
    for (int i = 0; i < 4; i++) {
        int m = m0 + ty * 4 + i;
        #pragma unroll
        for (int j = 0; j < 4; j += 2) {
            int n = n0 + tx * 4 + j;
            *(__half2*)&C[(size_t)m * ldc + n] =
                __floats2half2_rn(acc[i][j] + bias[n], acc[i][j+1] + bias[n+1]);
        }
    }
}

// =========================== fused flash attention (fp16 mma) ==================
#define STRF 144
#define FA_K(buf)   ((buf) * 64 * STRF)
#define FA_V(buf)   (2 * 64 * STRF + (buf) * 64 * STRF)
#define FA_Q        (4 * 64 * STRF)
#define FA_C2P      (FA_Q + 128 * STRF)
#define FA_P2C(buf) (FA_C2P + 16384 + (buf) * 8192)
#define FA_LUT      (FA_C2P + 16384 + 16384)
#define FA_SMEM     (FA_LUT + 2048 * 4)

__global__ void __launch_bounds__(256, 2) flash_attn_kernel(
    const __half* __restrict__ qg, const __half* __restrict__ kg,
    const __half* __restrict__ vt,
    const __half* __restrict__ c2p, const __half* __restrict__ p2c,
    const int* __restrict__ lut, __half* __restrict__ ctx)
{
    extern __shared__ char smc[];
    int* lut_s = (int*)(smc + FA_LUT);

    const int tid = threadIdx.x, w = tid >> 5, lane = tid & 31;
    const int g = lane >> 2, tg = lane & 3;
    const int z = blockIdx.z, bb = z >> 3, hh = z & 7;
    const int i0 = blockIdx.x * 128;

    const __half* c2pz = c2p + (size_t)z * Ssz * NPOS;
    const __half* p2cz = p2c + (size_t)z * Ssz * NPOS;

    const uint32_t sb = (uint32_t)__cvta_generic_to_shared(smc);

    #pragma unroll
    for (int t = 0; t < 8; t++) {
        int idx = tid + 256 * t;
        if (idx < 2 * Ssz - 1) lut_s[idx] = lut[idx];
    }

    auto loadKV = [&](int jt, int buf) {
        int j0 = jt * 64;
        #pragma unroll
        for (int c = 0; c < 2; c++) {
            int id = tid * 2 + c;
            int row = id >> 3, ch = id & 7;
            CP_ASYNC16(sb + (uint32_t)(FA_K(buf) + row * STRF + ch * 16),
                       kg + ((size_t)bb * Ssz + j0 + row) * Dsz + hh * DHsz + ch * 8);
        }
        #pragma unroll
        for (int c = 0; c < 2; c++) {
            int id = tid * 2 + c;
            int row = id >> 3, ch = id & 7;
            CP_ASYNC16(sb + (uint32_t)(FA_V(buf) + row * STRF + ch * 16),
                       vt + ((size_t)bb * Dsz + hh * DHsz + row) * Ssz + j0 + ch * 8);
        }
        #pragma unroll
        for (int c = 0; c < 2; c++) {
            int id = tid * 2 + c;
            int row = id >> 3, ch = id & 7;
            CP_ASYNC16(sb + (uint32_t)(FA_P2C(buf) + row * 128 + ch * 16),
                       p2cz + (size_t)(j0 + row) * NPOS + ch * 8);
        }
        CP_COMMIT();
    };

    #pragma unroll
    for (int c = 0; c < 4; c++) {
        int id = tid * 4 + c;
        int row = id >> 3, ch = id & 7;
        CP_ASYNC16(sb + (uint32_t)(FA_Q + row * STRF + ch * 16),
                   qg + ((size_t)bb * Ssz + i0 + row) * Dsz + hh * DHsz + ch * 8);
    }
    #pragma unroll
    for (int c = 0; c < 4; c++) {
        int id = tid * 4 + c;
        int row = id >> 3, ch = id & 7;
        CP_ASYNC16(sb + (uint32_t)(FA_C2P + row * 128 + ch * 16),
                   c2pz + (size_t)(i0 + row) * NPOS + ch * 8);
    }
    CP_COMMIT();
    loadKV(0, 0);

    CP_WAIT1();
    __syncthreads();

    const int lq = lane >> 3, lr = lane & 7;
    const int aoffF = ((lq & 1) * 8 + lr) * STRF + (lq >> 1) * 16;
    const int boffF = ((lq >> 1) * 8 + lr) * STRF + (lq & 1) * 16;

    uint32_t qf[4][4];
    #pragma unroll
    for (int kc = 0; kc < 4; kc++)
        ldsm_x4(qf[kc], sb + (uint32_t)(FA_Q + (w * 16) * STRF + aoffF + kc * 32));

    const __half* c2ps = (const __half*)(smc + FA_C2P);
    const int crow0 = (w * 16 + g) * 64;
    const int crow1 = crow0 + 8 * 64;

    float acc_o[8][4] = {};
    float m_r[2] = {-1e30f, -1e30f};
    float l_r[2] = {0.f, 0.f};
    const int mg0 = i0 + w * 16 + g;

    for (int jt = 0; jt < 16; jt++) {
        const int buf = jt & 1;
        const int j0 = jt * 64;
        CP_WAIT0();
        __syncthreads();
        if (jt < 15) loadKV(jt + 1, buf ^ 1);

        float acc_s[8][4] = {};
        #pragma unroll
        for (int kc = 0; kc < 4; kc++) {
            #pragma unroll
            for (int ip = 0; ip < 4; ip++) {
                uint32_t bf[4];
                ldsm_x4(bf, sb + (uint32_t)(FA_K(buf) + (ip * 16) * STRF + boffF + kc * 32));
                mma_f16(acc_s[ip * 2],     qf[kc], &bf[0]);
                mma_f16(acc_s[ip * 2 + 1], qf[kc], &bf[2]);
            }
        }

        const __half* p2cs = (const __half*)(smc + FA_P2C(buf));
        __half2 s01[8], s23[8];
        __half2 mx0h = __floats2half2_rn(-60000.f, -60000.f);
        __half2 mx1h = mx0h;
        #pragma unroll
        for (int in = 0; in < 8; in++) {
            int nloc = in * 8 + tg * 2;
            int dbase = mg0 - j0 - nloc + (Ssz - 1);
            int i00 = lut_s[dbase];
            int i01 = lut_s[dbase - 1];
            int i10 = lut_s[dbase + 8];
            int i11 = lut_s[dbase + 7];
            __half2 b01 = __hadd2(__halves2half2(c2ps[crow0 + i00], c2ps[crow0 + i01]),
                                  __halves2half2(p2cs[nloc * 64 + i00], p2cs[(nloc + 1) * 64 + i01]));
            __half2 b23 = __hadd2(__halves2half2(c2ps[crow1 + i10], c2ps[crow1 + i11]),
                                  __halves2half2(p2cs[nloc * 64 + i10], p2cs[(nloc + 1) * 64 + i11]));
            __half2 v01 = __hadd2(__floats2half2_rn(acc_s[in][0] * SCALE2F,
                                                    acc_s[in][1] * SCALE2F), b01);
            __half2 v23 = __hadd2(__floats2half2_rn(acc_s[in][2] * SCALE2F,
                                                    acc_s[in][3] * SCALE2F), b23);
            s01[in] = v01; s23[in] = v23;
            mx0h = __hmax2(mx0h, v01);
            mx1h = __hmax2(mx1h, v23);
        }
        float mx0 = fmaxf(__low2float(mx0h), __high2float(mx0h));
        float mx1 = fmaxf(__low2float(mx1h), __high2float(mx1h));
        mx0 = fmaxf(mx0, __shfl_xor_sync(0xffffffffu, mx0, 1));
        mx0 = fmaxf(mx0, __shfl_xor_sync(0xffffffffu, mx0, 2));
        mx1 = fmaxf(mx1, __shfl_xor_sync(0xffffffffu, mx1, 1));
        mx1 = fmaxf(mx1, __shfl_xor_sync(0xffffffffu, mx1, 2));
        float mn0 = fmaxf(m_r[0], mx0), mn1 = fmaxf(m_r[1], mx1);
        float al0 = exp2f(m_r[0] - mn0), al1 = exp2f(m_r[1] - mn1);
        __half2 mn0h = __float2half2_rn(mn0);
        __half2 mn1h = __float2half2_rn(mn1);
        float s0 = 0.f, s1 = 0.f;
        uint32_t u01[8], u23[8];
        #pragma unroll
        for (int in = 0; in < 8; in++) {
            __half2 e01 = h2exp2(__hsub2(s01[in], mn0h));
            __half2 e23 = h2exp2(__hsub2(s23[in], mn1h));
            u01[in] = *(uint32_t*)&e01;
            u23[in] = *(uint32_t*)&e23;
            float2 f01 = __half22float2(e01);
            float2 f23 = __half22float2(e23);
            s0 += f01.x + f01.y; s1 += f23.x + f23.y;
        }
        l_r[0] = l_r[0] * al0 + s0;
        l_r[1] = l_r[1] * al1 + s1;
        m_r[0] = mn0; m_r[1] = mn1;
        #pragma unroll
        for (int nf = 0; nf < 8; nf++) {
            acc_o[nf][0] *= al0; acc_o[nf][1] *= al0;
            acc_o[nf][2] *= al1; acc_o[nf][3] *= al1;
        }

        #pragma unroll
        for (int kc2 = 0; kc2 < 4; kc2++) {
            uint32_t af[4];
            af[0] = u01[kc2 * 2];
            af[1] = u23[kc2 * 2];
            af[2] = u01[kc2 * 2 + 1];
            af[3] = u23[kc2 * 2 + 1];
            #pragma unroll
            for (int ip = 0; ip < 4; ip++) {
                uint32_t bf[4];
                ldsm_x4(bf, sb + (uint32_t)(FA_V(buf) + (ip * 16) * STRF + boffF + kc2 * 32));
                mma_f16(acc_o[ip * 2],     af, &bf[0]);
                mma_f16(acc_o[ip * 2 + 1], af, &bf[2]);
            }
        }
    }

    float l0 = l_r[0];
    l0 += __shfl_xor_sync(0xffffffffu, l0, 1);
    l0 += __shfl_xor_sync(0xffffffffu, l0, 2);
    float l1 = l_r[1];
    l1 += __shfl_xor_sync(0xffffffffu, l1, 1);
    l1 += __shfl_xor_sync(0xffffffffu, l1, 2);
    float inv0 = 1.0f / l0, inv1 = 1.0f / l1;
    __half* c0 = ctx + ((size_t)bb * Ssz + mg0)     * Dsz + hh * DHsz;
    __half* c1 = ctx + ((size_t)bb * Ssz + mg0 + 8) * Dsz + hh * DHsz;
    #pragma unroll
    for (int nf = 0; nf < 8; nf++) {
        int col = nf * 8 + tg * 2;
        *(__half2*)&c0[col] = __floats2half2_rn(acc_o[nf][0] * inv0, acc_o[nf][1] * inv0);
        *(__half2*)&c1[col] = __floats2half2_rn(acc_o[nf][2] * inv1, acc_o[nf][3] * inv1);
    }
}

// =============================== launch ========================================
extern "C" void kernel_launch(void* const* d_in, const int* in_sizes, int n_in,
                              void* d_out, int out_size) {
    const float* x      = (const float*)d_in[0];
    const float* ln1g   = (const float*)d_in[1];
    const float* ln1b   = (const float*)d_in[2];
    const float* dww    = (const float*)d_in[3];
    const float* dwb    = (const float*)d_in[4];
    const float* pww    = (const float*)d_in[5];
    const float* pwb    = (const float*)d_in[6];
    const float* ln2g   = (const float*)d_in[7];
    const float* ln2b   = (const float*)d_in[8];
    const float* qw     = (const float*)d_in[9];
    const float* qb     = (const float*)d_in[10];
    const float* kw     = (const float*)d_in[11];
    const float* kb     = (const float*)d_in[12];
    const float* vw     = (const float*)d_in[13];
    const float* vb     = (const float*)d_in[14];
    const float* ow     = (const float*)d_in[15];
    const float* ob     = (const float*)d_in[16];
    const float* relemb = (const float*)d_in[17];
    const float* ln3g   = (const float*)d_in[18];
    const float* ln3b   = (const float*)d_in[19];
    const float* w1     = (const float*)d_in[20];
    const float* b1     = (const float*)d_in[21];
    const float* w2     = (const float*)d_in[22];
    const float* b2     = (const float*)d_in[23];
    float* out = (float*)d_out;

    float *x1, *x2; int* lut;
    __half *c2p, *p2c;
    __half *xnh, *convh, *qh, *kh, *vh, *vth, *ctxh, *ffh, *poskh, *posqh;
    __half *pwwh, *qwh, *kwh, *vwh, *owh, *w1h, *w2h;
    cudaGetSymbolAddress((void**)&x1,    g_x1);
    cudaGetSymbolAddress((void**)&x2,    g_x2);
    cudaGetSymbolAddress((void**)&c2p,   g_c2p);
    cudaGetSymbolAddress((void**)&p2c,   g_p2c);
    cudaGetSymbolAddress((void**)&lut,   g_lut);
    cudaGetSymbolAddress((void**)&xnh,   g_xnh);
    cudaGetSymbolAddress((void**)&convh, g_convh);
    cudaGetSymbolAddress((void**)&qh,    g_qh);
    cudaGetSymbolAddress((void**)&kh,    g_kh);
    cudaGetSymbolAddress((void**)&vh,    g_vh);
    cudaGetSymbolAddress((void**)&vth,   g_vth);
    cudaGetSymbolAddress((void**)&ctxh,  g_ctxh);
    cudaGetSymbolAddress((void**)&ffh,   g_ffh);
    cudaGetSymbolAddress((void**)&poskh, g_poskh);
    cudaGetSymbolAddress((void**)&posqh, g_posqh);
    cudaGetSymbolAddress((void**)&pwwh,  g_pwwh);
    cudaGetSymbolAddress((void**)&qwh,   g_qwh);
    cudaGetSymbolAddress((void**)&kwh,   g_kwh);
    cudaGetSymbolAddress((void**)&vwh,   g_vwh);
    cudaGetSymbolAddress((void**)&owh,   g_owh);
    cudaGetSymbolAddress((void**)&w1h,   g_w1h);
    cudaGetSymbolAddress((void**)&w2h,   g_w2h);

    static int attr_set = 0;
    if (!attr_set) {
        cudaFuncSetAttribute(flash_attn_kernel,
                             cudaFuncAttributeMaxDynamicSharedMemorySize, FA_SMEM);
        cudaFuncSetAttribute(gemm_mma_kernel<128,2,0,0>,
                             cudaFuncAttributeMaxDynamicSharedMemorySize, GEMM_SMEMH(128));
        cudaFuncSetAttribute(gemm_mma_kernel<128,1,4,1>,
                             cudaFuncAttributeMaxDynamicSharedMemorySize, GEMM_SMEMH(128));
        cudaFuncSetAttribute(gemm_mma_kernel<128,3,0,1>,
                             cudaFuncAttributeMaxDynamicSharedMemorySize, GEMM_SMEMH(128));
        cudaFuncSetAttribute(gemm_pos_kernel,
                             cudaFuncAttributeMaxDynamicSharedMemorySize, GEMM_SMEMH(64));
        attr_set = 1;
    }

    setup_kernel<<<dim3(256, 1, 8), 256>>>(pww, qw, kw, vw, ow, w1, w2,
                                           pwwh, qwh, kwh, vwh, owh, w1h, w2h, lut);

    // ---- conv block (fused LN1 + dwconv + silu) ----
    ln_dwconv_silu_kernel<<<dim3(Ssz/4, Bsz), 256>>>(x, ln1g, ln1b, dww, dwb, convh);
    gemm_mma_kernel<128,2,0,0><<<dim3(Dsz/128, NROWS/128, 1), 256, GEMM_SMEMH(128)>>>(
        convh, Dsz, pwwh, Dsz, pwb, x, x1, Dsz, Dsz,
        nullptr, nullptr, nullptr, nullptr, nullptr, nullptr);

    // ---- attention block ----
    layernorm_kernel<<<NROWS/8, 256>>>(x1, ln2g, ln2b, xnh);
    gemm_mma_kernel<128,1,4,1><<<dim3(Dsz/128, NROWS/128, 3), 256, GEMM_SMEMH(128)>>>(
        xnh, Dsz, qwh, Dsz, qb, nullptr, qh, Dsz, Dsz,
        kwh, vwh, kb, vb, kh, vh);
    transpose_v_kernel<<<dim3(Ssz/64, Dsz/64, Bsz), 256>>>(vh, vth);

    gemm_tn_small_kernel<<<dim3(Dsz/64, 1, 2), 256>>>(
        relemb, Dsz, kw, Dsz, kb, poskh, qw, qb, posqh, Dsz, Dsz);

    gemm_pos_kernel<<<dim3(1, Ssz/128, 2*Bsz*Hsz), 256, GEMM_SMEMH(64)>>>(
        qh, poskh, c2p, kh, posqh, p2c);

    flash_attn_kernel<<<dim3(Ssz/128, 1, Bsz*Hsz), 256, FA_SMEM>>>(
        qh, kh, vth, c2p, p2c, lut, ctxh);

    gemm_mma_kernel<128,2,0,0><<<dim3(Dsz/128, NROWS/128, 1), 256, GEMM_SMEMH(128)>>>(
        ctxh, Dsz, owh, Dsz, ob, x1, x2, Dsz, Dsz,
        nullptr, nullptr, nullptr, nullptr, nullptr, nullptr);

    // ---- FFN block ----
    layernorm_kernel<<<NROWS/8, 256>>>(x2, ln3g, ln3b, xnh);
    gemm_mma_kernel<128,3,0,1><<<dim3(FFsz/128, NROWS/128, 1), 256, GEMM_SMEMH(128)>>>(
        xnh, Dsz, w1h, Dsz, b1, nullptr, ffh, FFsz, Dsz,
        nullptr, nullptr, nullptr, nullptr, nullptr, nullptr);
    gemm_mma_kernel<128,2,0,0><<<dim3(Dsz/128, NROWS/128, 1), 256, GEMM_SMEMH(128)>>>(
        ffh, FFsz, w2h, FFsz, b2, x2, out, Dsz, FFsz,
        nullptr, nullptr, nullptr, nullptr, nullptr, nullptr);
}

// round 17
// speedup vs baseline: 1.6656x; 1.0056x over previous
#include <cuda_runtime.h>
#include <cuda_fp16.h>
#include <math.h>
#include <stdint.h>

#define Bsz 8
#define Ssz 1024
#define Dsz 512
#define Hsz 8
#define DHsz 64
#define FFsz 1024
#define NPOS 64          // 2*SPAN
#define NROWS (Bsz*Ssz)  // 8192

// ---------------- scratch (device globals; no allocation allowed) ------------
__device__ float  g_x1  [Bsz*Ssz*Dsz];
__device__ float  g_x2  [Bsz*Ssz*Dsz];
__device__ __half g_c2p [Bsz*Hsz*Ssz*NPOS];   // pre-scaled by SCALE*log2(e)
__device__ __half g_p2c [Bsz*Hsz*Ssz*NPOS];   // pre-scaled
__device__ int    g_lut [2*Ssz];
__device__ __half g_xnh  [Bsz*Ssz*Dsz];
__device__ __half g_convh[Bsz*Ssz*Dsz];
__device__ __half g_qh   [Bsz*Ssz*Dsz];
__device__ __half g_kh   [Bsz*Ssz*Dsz];
__device__ __half g_vh   [Bsz*Ssz*Dsz];
__device__ __half g_ctxh [Bsz*Ssz*Dsz];
__device__ __half g_ffh  [Bsz*Ssz*FFsz];
__device__ __half g_poskh[NPOS*Dsz];
__device__ __half g_posqh[NPOS*Dsz];
__device__ __half g_pwwh[Dsz*Dsz];
__device__ __half g_qwh [Dsz*Dsz];
__device__ __half g_kwh [Dsz*Dsz];
__device__ __half g_vwh [Dsz*Dsz];
__device__ __half g_owh [Dsz*Dsz];
__device__ __half g_w1h [FFsz*Dsz];
__device__ __half g_w2h [FFsz*Dsz];

#define SCALE2F (0.07216878364870323f * 1.4426950408889634f)  // 1/sqrt(192)*log2(e)

// ---------------- half2 silu helper ---------------------------------------------
__device__ __forceinline__ __half2 silu_h2(__half2 hv) {
    const __half2 nl2e = __floats2half2_rn(-1.4426950408889634f, -1.4426950408889634f);
    const __half2 one2 = __floats2half2_rn(1.0f, 1.0f);
    return __hmul2(hv, h2rcp(__hadd2(one2, h2exp2(__hmul2(hv, nl2e)))));
}

// ---------------- setup: weights fp32->fp16 + rel-pos LUT (merged) -------------
__global__ void setup_kernel(const float* __restrict__ s0, const float* __restrict__ s1,
                             const float* __restrict__ s2, const float* __restrict__ s3,
                             const float* __restrict__ s4, const float* __restrict__ s5,
                             const float* __restrict__ s6,
                             __half* d0, __half* d1, __half* d2, __half* d3,
                             __half* d4, __half* d5, __half* d6, int* __restrict__ lut) {
    int z = blockIdx.z;
    if (z == 7) {   // LUT
        int t = blockIdx.x * blockDim.x + threadIdx.x;
        if (t >= 2*Ssz - 1) return;
        int rel = t - (Ssz - 1);
        const int mid = 16;
        int bucket;
        if (rel > -mid && rel < mid) {
            bucket = rel;
        } else {
            float absp = fabsf((float)rel);
            if (absp <= (float)mid) {
                bucket = rel;
            } else {
                float logp = ceilf(logf(absp / 16.0f) / logf(127.0f / 16.0f) * 15.0f) + 16.0f;
                bucket = (rel > 0 ? 1 : -1) * (int)logp;
            }
        }
        int idx = bucket + 32;
        lut[t] = min(max(idx, 0), 63);
        return;
    }
    const float* s; __half* d; int n;
    switch (z) {
        case 0: s = s0; d = d0; n = Dsz*Dsz;  break;
        case 1: s = s1; d = d1; n = Dsz*Dsz;  break;
        case 2: s = s2; d = d2; n = Dsz*Dsz;  break;
        case 3: s = s3; d = d3; n = Dsz*Dsz;  break;
        case 4: s = s4; d = d4; n = Dsz*Dsz;  break;
        case 5: s = s5; d = d5; n = FFsz*Dsz; break;
        default:s = s6; d = d6; n = FFsz*Dsz; break;
    }
    for (int i = blockIdx.x * blockDim.x + threadIdx.x; i * 2 < n; i += gridDim.x * blockDim.x) {
        float2 f = *(const float2*)&s[i * 2];
        *(__half2*)&d[i * 2] = __floats2half2_rn(f.x, f.y);
    }
}

// ---------------- LayerNorm (warp per 2 rows, no barriers) -> half -------------
__global__ void __launch_bounds__(256, 6) layernorm_kernel(
    const float* __restrict__ x,
    const float* __restrict__ g,
    const float* __restrict__ bb,
    __half* __restrict__ out) {
    const int wd = threadIdx.x >> 5, lane = threadIdx.x & 31;
    const size_t row0 = (size_t)blockIdx.x * 16 + wd * 2;

    float4 v[2][4];
    float sum[2] = {0.f, 0.f}, ssq[2] = {0.f, 0.f};
    #pragma unroll
    for (int q = 0; q < 2; q++) {
        const float* xr = x + (row0 + q) * Dsz;
        #pragma unroll
        for (int r = 0; r < 4; r++) {
            v[q][r] = *(const float4*)&xr[r * 128 + lane * 4];
            sum[q] += v[q][r].x + v[q][r].y + v[q][r].z + v[q][r].w;
            ssq[q] += v[q][r].x * v[q][r].x + v[q][r].y * v[q][r].y
                    + v[q][r].z * v[q][r].z + v[q][r].w * v[q][r].w;
        }
    }
    #pragma unroll
    for (int o = 16; o; o >>= 1) {
        sum[0] += __shfl_xor_sync(0xffffffffu, sum[0], o);
        ssq[0] += __shfl_xor_sync(0xffffffffu, ssq[0], o);
        sum[1] += __shfl_xor_sync(0xffffffffu, sum[1], o);
        ssq[1] += __shfl_xor_sync(0xffffffffu, ssq[1], o);
    }
    #pragma unroll
    for (int q = 0; q < 2; q++) {
        float mean = sum[q] * (1.0f / Dsz);
        float var  = ssq[q] * (1.0f / Dsz) - mean * mean;
        float rs = rsqrtf(var + 1e-5f);
        __half* orow = out + (row0 + q) * Dsz;
        #pragma unroll
        for (int r = 0; r < 4; r++) {
            int c = r * 128 + lane * 4;
            float4 gg = *(const float4*)&g[c];
            float4 bv = *(const float4*)&bb[c];
            __half2 h0 = __floats2half2_rn((v[q][r].x - mean) * rs * gg.x + bv.x,
                                           (v[q][r].y - mean) * rs * gg.y + bv.y);
            __half2 h1 = __floats2half2_rn((v[q][r].z - mean) * rs * gg.z + bv.z,
                                           (v[q][r].w - mean) * rs * gg.w + bv.w);
            uint2 pk;
            pk.x = *(uint32_t*)&h0;
            pk.y = *(uint32_t*)&h1;
            *(uint2*)&orow[c] = pk;
        }
    }
}

// ---------------- fused LN1 + depthwise conv (K=3) + silu ----------------------
__global__ void __launch_bounds__(256, 4) ln_dwconv_silu_kernel(
    const float* __restrict__ x,
    const float* __restrict__ g, const float* __restrict__ bb,
    const float* __restrict__ w, const float* __restrict__ bias,
    __half* __restrict__ out)
{
    __shared__ __half xs[6][Dsz];
    const int b = blockIdx.y;
    const int s0 = blockIdx.x * 4;
    const int tid = threadIdx.x, wd = tid >> 5, lane = tid & 31;

    if (wd < 6) {
        int s = s0 - 1 + wd;
        if (s >= 0 && s < Ssz) {
            const float* xr = x + ((size_t)b * Ssz + s) * Dsz;
            float v[16];
            float sum = 0.f, ssq = 0.f;
            #pragma unroll
            for (int i = 0; i < 16; i++) {
                v[i] = xr[lane + 32 * i];
                sum += v[i]; ssq += v[i] * v[i];
            }
            #pragma unroll
            for (int o = 16; o; o >>= 1) {
                sum += __shfl_xor_sync(0xffffffffu, sum, o);
                ssq += __shfl_xor_sync(0xffffffffu, ssq, o);
            }
            float mean = sum * (1.0f / Dsz);
            float var  = ssq * (1.0f / Dsz) - mean * mean;
            float rs = rsqrtf(var + 1e-5f);
            #pragma unroll
            for (int i = 0; i < 16; i++) {
                int d = lane + 32 * i;
                xs[wd][d] = __float2half((v[i] - mean) * rs * g[d] + bb[d]);
            }
        } else {
            #pragma unroll
            for (int i = 0; i < 16; i++)
                xs[wd][lane + 32 * i] = __float2half(0.f);
        }
    }
    __syncthreads();

    const int d2 = tid, d = d2 * 2;
    float2 wc0 = *(const float2*)&w[d*3];
    float  wc2 = w[d*3+2];
    float  w10 = w[d*3+3];
    float2 wc3 = *(const float2*)&w[d*3+4];
    float2 bv  = *(const float2*)&bias[d];

    float2 xv[6];
    #pragma unroll
    for (int r = 0; r < 6; r++)
        xv[r] = __half22float2(*(const __half2*)&xs[r][d]);

    __half2* orow = (__half2*)out + ((size_t)b * Ssz + s0) * (Dsz/2) + d2;
    #pragma unroll
    for (int t = 0; t < 4; t++) {
        float a0 = bv.x + xv[t].x * wc0.x + xv[t+1].x * wc0.y + xv[t+2].x * wc2;
        float a1 = bv.y + xv[t].y * w10   + xv[t+1].y * wc3.x + xv[t+2].y * wc3.y;
        orow[t * (Dsz/2)] = silu_h2(__floats2half2_rn(a0, a1));
    }
}

// ---------------- mma.f16 + ldmatrix helpers -----------------------------------
__device__ __forceinline__ void mma_f16(float c[4], const uint32_t a[4], const uint32_t b[2]) {
    asm volatile(
        "mma.sync.aligned.m16n8k16.row.col.f32.f16.f16.f32 "
        "{%0,%1,%2,%3}, {%4,%5,%6,%7}, {%8,%9}, {%0,%1,%2,%3};"
        : "+f"(c[0]), "+f"(c[1]), "+f"(c[2]), "+f"(c[3])
        : "r"(a[0]), "r"(a[1]), "r"(a[2]), "r"(a[3]), "r"(b[0]), "r"(b[1]));
}

__device__ __forceinline__ void ldsm_x4(uint32_t r[4], uint32_t addr) {
    asm volatile("ldmatrix.sync.aligned.m8n8.x4.shared.b16 {%0,%1,%2,%3}, [%4];"
                 : "=r"(r[0]), "=r"(r[1]), "=r"(r[2]), "=r"(r[3]) : "r"(addr));
}

__device__ __forceinline__ void ldsm_x4_trans(uint32_t r[4], uint32_t addr) {
    asm volatile("ldmatrix.sync.aligned.m8n8.x4.trans.shared.b16 {%0,%1,%2,%3}, [%4];"
                 : "=r"(r[0]), "=r"(r[1]), "=r"(r[2]), "=r"(r[3]) : "r"(addr));
}

#define CP_ASYNC16(dst_u32, src_ptr) \
    asm volatile("cp.async.ca.shared.global [%0], [%1], 16;" :: "r"(dst_u32), "l"(src_ptr))
#define CP_COMMIT() asm volatile("cp.async.commit_group;")
#define CP_WAIT2()  asm volatile("cp.async.wait_group 2;")
#define CP_WAIT1()  asm volatile("cp.async.wait_group 1;")
#define CP_WAIT0()  asm volatile("cp.async.wait_group 0;")

// ---------------- fp16 tensor-core TN GEMM (128xCN tiles, K32 chunks) ----------
#define STRB 80
#define NSTAGE 4
#define GEMM_SMEMH(CNv) (NSTAGE * (128 + (CNv)) * STRB)

template<int CN, int EPI, int MODE, int OUTH>
__global__ void __launch_bounds__(256, 2) gemm_mma_kernel(
    const __half* __restrict__ A0, int lda,
    const __half* __restrict__ W0, int ldw,
    const float* __restrict__ bias0, const float* __restrict__ res,
    void* __restrict__ C0v, int ldc, int K,
    const __half* __restrict__ Wa, const __half* __restrict__ Wb2,
    const float* __restrict__ ba, const float* __restrict__ bb2,
    void* __restrict__ Cav, void* __restrict__ Cbv)
{
    constexpr int NWN = CN / 32;
    constexpr int NWM = 8 / NWN;
    constexpr int MT  = 8 / NWM;

    extern __shared__ char smem[];
    const uint32_t sb = (uint32_t)__cvta_generic_to_shared(smem);
    const uint32_t sA = sb;
    const uint32_t sW = sb + NSTAGE * 128 * STRB;

    const int tid  = threadIdx.x;
    const int wid  = tid >> 5, lane = tid & 31;
    const int g    = lane >> 2, tg = lane & 3;
    const int wm   = wid % NWM, wn = wid / NWM;

    const int z = blockIdx.z;
    const __half* A = A0; const __half* W = W0; void* Cv = C0v;
    const float* bias = bias0;
    if (MODE == 4) {
        W    = (z == 0) ? W0 : (z == 1 ? Wa : Wb2);
        bias = (z == 0) ? bias0 : (z == 1 ? ba : bb2);
        Cv   = (z == 0) ? C0v : (z == 1 ? Cav : Cbv);
    }

    const int m_cta = blockIdx.y * 128, n_cta = blockIdx.x * CN;

    auto fetch = [&](int t, int buf) {
        int k0 = t * 32;
        #pragma unroll
        for (int r = 0; r < 2; r++) {
            int id = tid + 256 * r;
            int row = id >> 2, ch = id & 3;
            CP_ASYNC16(sA + (uint32_t)(buf * 128 * STRB + row * STRB + ch * 16),
                       A + (size_t)(m_cta + row) * lda + k0 + ch * 8);
        }
        #pragma unroll
        for (int r = 0; r < CN / 64; r++) {
            int id = tid + 256 * r;
            int row = id >> 2, ch = id & 3;
            CP_ASYNC16(sW + (uint32_t)(buf * CN * STRB + row * STRB + ch * 16),
                       W + (size_t)(n_cta + row) * ldw + k0 + ch * 8);
        }
        CP_COMMIT();
    };

    const int lq = lane >> 3, lr = lane & 7;
    const int aoff = ((lq & 1) * 8 + lr) * STRB + (lq >> 1) * 16;
    const int boff = ((lq >> 1) * 8 + lr) * STRB + (lq & 1) * 16;

    float acc[MT][4][4] = {};

    const int T = K / 32;
    fetch(0, 0);
    fetch(1, 1);
    if (T > 2) fetch(2, 2);
    for (int it = 0; it < T; it++) {
        const int buf = it & (NSTAGE - 1);
        if (it < T - 2)       { CP_WAIT2(); }
        else if (it == T - 2) { CP_WAIT1(); }
        else                  { CP_WAIT0(); }
        __syncthreads();
        if (it + 3 < T) fetch(it + 3, (it + 3) & (NSTAGE - 1));

        const uint32_t bA = sA + (uint32_t)(buf * 128 * STRB);
        const uint32_t bW = sW + (uint32_t)(buf * CN  * STRB);
        #pragma unroll
        for (int ks = 0; ks < 2; ks++) {
            const int kb = ks * 32;
            uint32_t af[MT][4];
            #pragma unroll
            for (int im = 0; im < MT; im++)
                ldsm_x4(af[im], bA + (uint32_t)((wm * MT * 16 + im * 16) * STRB + aoff + kb));
            uint32_t bf[2][4];
            #pragma unroll
            for (int ip = 0; ip < 2; ip++)
                ldsm_x4(bf[ip], bW + (uint32_t)((wn * 32 + ip * 16) * STRB + boff + kb));
            #pragma unroll
            for (int im = 0; im < MT; im++)
                #pragma unroll
                for (int in = 0; in < 4; in++)
                    mma_f16(acc[im][in], af[im], &bf[in >> 1][(in & 1) * 2]);
        }
    }

    #pragma unroll
    for (int im = 0; im < MT; im++) {
        int mrow0 = m_cta + wm * MT * 16 + im * 16 + g;
        #pragma unroll
        for (int in = 0; in < 4; in++) {
            int ncol0 = n_cta + wn * 32 + in * 8 + tg * 2;
            float2 bv = make_float2(0.f, 0.f);
            if (EPI >= 1) bv = *(const float2*)&bias[ncol0];
            #pragma unroll
            for (int h = 0; h < 2; h++) {
                int m = mrow0 + h * 8;
                float v0 = acc[im][in][h * 2 + 0];
                float v1 = acc[im][in][h * 2 + 1];
                if (EPI >= 1) { v0 += bv.x; v1 += bv.y; }
                if (EPI == 2) {
                    float2 rv = *(const float2*)&res[(size_t)m * ldc + ncol0];
                    v0 += rv.x; v1 += rv.y;
                }
                if (OUTH) {
                    __half2 hv = __floats2half2_rn(v0, v1);
                    if (EPI == 3) hv = silu_h2(hv);
                    *(__half2*)&((__half*)Cv)[(size_t)m * ldc + ncol0] = hv;
                } else {
                    *(float2*)&((float*)Cv)[(size_t)m * ldc + ncol0] = make_float2(v0, v1);
                }
            }
        }
    }
}

// ---------------- fp16 mma GEMM for pos projections (N=64, K=64) ---------------
__global__ void __launch_bounds__(256, 2) gemm_pos_kernel(
    const __half* __restrict__ A0,
    const __half* __restrict__ W0,
    __half* __restrict__ C0,
    const __half* __restrict__ Aa, const __half* __restrict__ Wa,
    __half* __restrict__ Ca)
{
    extern __shared__ char smem[];
    const uint32_t sb = (uint32_t)__cvta_generic_to_shared(smem);
    const uint32_t sA = sb;
    const uint32_t sW = sb + NSTAGE * 128 * STRB;

    const int tid  = threadIdx.x;
    const int wid  = tid >> 5, lane = tid & 31;
    const int g    = lane >> 2, tg = lane & 3;
    const int wm   = wid & 3, wn = wid >> 2;

    int zz = blockIdx.z & 63, sel = blockIdx.z >> 6;
    int bb = zz >> 3, hh = zz & 7;
    const __half* A = (sel ? Aa : A0) + (size_t)bb * Ssz * Dsz + hh * DHsz;
    const __half* W = (sel ? Wa : W0) + hh * DHsz;
    __half* C = (sel ? Ca : C0) + (size_t)zz * Ssz * NPOS;

    const int m_cta = blockIdx.y * 128;

    auto fetch = [&](int t, int buf) {
        int k0 = t * 32;
        #pragma unroll
        for (int r = 0; r < 2; r++) {
            int id = tid + 256 * r;
            int row = id >> 2, ch = id & 3;
            CP_ASYNC16(sA + (uint32_t)(buf * 128 * STRB + row * STRB + ch * 16),
                       A + (size_t)(m_cta + row) * Dsz + k0 + ch * 8);
        }
        {
            int row = tid >> 2, ch = tid & 3;
            if (row < 64)
                CP_ASYNC16(sW + (uint32_t)(buf * 64 * STRB + row * STRB + ch * 16),
                           W + (size_t)row * Dsz + k0 + ch * 8);
        }
        CP_COMMIT();
    };

    const int lq = lane >> 3, lr = lane & 7;
    const int aoff = ((lq & 1) * 8 + lr) * STRB + (lq >> 1) * 16;
    const int boff = ((lq >> 1) * 8 + lr) * STRB + (lq & 1) * 16;

    float acc[2][4][4] = {};
    const int T = 2;   // K=64
    fetch(0, 0); fetch(1, 1);
    for (int it = 0; it < T; it++) {
        const int buf = it & (NSTAGE - 1);
        if (it == T - 2) { CP_WAIT1(); } else { CP_WAIT0(); }
        __syncthreads();

        const uint32_t bA = sA + (uint32_t)(buf * 128 * STRB);
        const uint32_t bW = sW + (uint32_t)(buf * 64  * STRB);
        #pragma unroll
        for (int ks = 0; ks < 2; ks++) {
            const int kb = ks * 32;
            uint32_t af[2][4];
            #pragma unroll
            for (int im = 0; im < 2; im++)
                ldsm_x4(af[im], bA + (uint32_t)((wm * 32 + im * 16) * STRB + aoff + kb));
            uint32_t bf[2][4];
            #pragma unroll
            for (int ip = 0; ip < 2; ip++)
                ldsm_x4(bf[ip], bW + (uint32_t)((wn * 32 + ip * 16) * STRB + boff + kb));
            #pragma unroll
            for (int im = 0; im < 2; im++)
                #pragma unroll
                for (int in = 0; in < 4; in++)
                    mma_f16(acc[im][in], af[im], &bf[in >> 1][(in & 1) * 2]);
        }
    }

    #pragma unroll
    for (int im = 0; im < 2; im++) {
        int mrow0 = m_cta + wm * 32 + im * 16 + g;
        #pragma unroll
        for (int in = 0; in < 4; in++) {
            int ncol0 = wn * 32 + in * 8 + tg * 2;
            #pragma unroll
            for (int h = 0; h < 2; h++) {
                int m = mrow0 + h * 8;
                *(__half2*)&C[(size_t)m * NPOS + ncol0] =
                    __floats2half2_rn(acc[im][in][h * 2] * SCALE2F,
                                      acc[im][in][h * 2 + 1] * SCALE2F);
            }
        }
    }
}

// ---------------- small SIMT GEMM (pos-emb projections, fp32 in, half out) -----
#define TK 16
#define TPAD 68
__global__ void gemm_tn_small_kernel(const float* __restrict__ A, int lda,
                                     const float* __restrict__ W0, int ldw,
                                     const float* __restrict__ b0,
                                     __half* __restrict__ C0,
                                     const float* __restrict__ W1,
                                     const float* __restrict__ b1,
                                     __half* __restrict__ C1, int ldc, int Kd) {
    const float* W   = blockIdx.z ? W1 : W0;
    const float* bias= blockIdx.z ? b1 : b0;
    __half* C        = blockIdx.z ? C1 : C0;
    int m0 = blockIdx.y * 64, n0 = blockIdx.x * 64;
    __shared__ float As[TK][TPAD];
    __shared__ float Ws2[TK][TPAD];
    const int tid = threadIdx.x;
    const int tx = tid & 15, ty = tid >> 4;
    const int lk = tid & 15, lm = tid >> 4;
    float acc[4][4] = {};
    for (int k0 = 0; k0 < Kd; k0 += TK) {
        #pragma unroll
        for (int r = 0; r < 4; r++) {
            As[lk][lm + 16 * r]  = A[(size_t)(m0 + lm + 16 * r) * lda + k0 + lk];
            Ws2[lk][lm + 16 * r] = W[(size_t)(n0 + lm + 16 * r) * ldw + k0 + lk];
        }
        __syncthreads();
        #pragma unroll
        for (int kk = 0; kk < TK; kk++) {
            float4 a = *(const float4*)&As[kk][ty * 4];
            float4 b = *(const float4*)&Ws2[kk][tx * 4];
            float av[4] = {a.x, a.y, a.z, a.w};
            float bv[4] = {b.x, b.y, b.z, b.w};
            #pragma unroll
            for (int i = 0; i < 4; i++)
                #pragma unroll
                for (int j = 0; j < 4; j++)
                    acc[i][j] += av[i] * bv[j];
        }
        __syncthreads();
    }
    #pragma unroll
    for (int i = 0; i < 4; i++) {
        int m = m0 + ty * 4 + i;
        #pragma unroll
        for (int j = 0; j < 4; j += 2) {
            int n = n0 + tx * 4 + j;
            *(__half2*)&C[(size_t)m * ldc + n] =
                __floats2half2_rn(acc[i][j] + bias[n], acc[i][j+1] + bias[n+1]);
        }
    }
}

// =========================== fused flash attention (fp16 mma) ==================
// V loaded untransposed [j][d]; P.V B-fragments via ldmatrix.trans.
#define STRF 144
#define FA_K(buf)   ((buf) * 64 * STRF)
#define FA_V(buf)   (2 * 64 * STRF + (buf) * 64 * STRF)
#define FA_Q        (4 * 64 * STRF)
#define FA_C2P      (FA_Q + 128 * STRF)
#define FA_P2C(buf) (FA_C2P + 16384 + (buf) * 8192)
#define FA_LUT      (FA_C2P + 16384 + 16384)
#define FA_SMEM     (FA_LUT + 2048 * 4)

__global__ void __launch_bounds__(256, 2) flash_attn_kernel(
    const __half* __restrict__ qg, const __half* __restrict__ kg,
    const __half* __restrict__ vg,
    const __half* __restrict__ c2p, const __half* __restrict__ p2c,
    const int* __restrict__ lut, __half* __restrict__ ctx)
{
    extern __shared__ char smc[];
    int* lut_s = (int*)(smc + FA_LUT);

    const int tid = threadIdx.x, w = tid >> 5, lane = tid & 31;
    const int g = lane >> 2, tg = lane & 3;
    const int z = blockIdx.z, bb = z >> 3, hh = z & 7;
    const int i0 = blockIdx.x * 128;

    const __half* c2pz = c2p + (size_t)z * Ssz * NPOS;
    const __half* p2cz = p2c + (size_t)z * Ssz * NPOS;

    const uint32_t sb = (uint32_t)__cvta_generic_to_shared(smc);

    #pragma unroll
    for (int t = 0; t < 8; t++) {
        int idx = tid + 256 * t;
        if (idx < 2 * Ssz - 1) lut_s[idx] = lut[idx];
    }

    auto loadKV = [&](int jt, int buf) {
        int j0 = jt * 64;
        #pragma unroll
        for (int c = 0; c < 2; c++) {       // K: rows j x cols d
            int id = tid * 2 + c;
            int row = id >> 3, ch = id & 7;
            CP_ASYNC16(sb + (uint32_t)(FA_K(buf) + row * STRF + ch * 16),
                       kg + ((size_t)bb * Ssz + j0 + row) * Dsz + hh * DHsz + ch * 8);
        }
        #pragma unroll
        for (int c = 0; c < 2; c++) {       // V: rows j x cols d (untransposed)
            int id = tid * 2 + c;
            int row = id >> 3, ch = id & 7;
            CP_ASYNC16(sb + (uint32_t)(FA_V(buf) + row * STRF + ch * 16),
                       vg + ((size_t)bb * Ssz + j0 + row) * Dsz + hh * DHsz + ch * 8);
        }
        #pragma unroll
        for (int c = 0; c < 2; c++) {       // p2c rows for this j-tile
            int id = tid * 2 + c;
            int row = id >> 3, ch = id & 7;
            CP_ASYNC16(sb + (uint32_t)(FA_P2C(buf) + row * 128 + ch * 16),
                       p2cz + (size_t)(j0 + row) * NPOS + ch * 8);
        }
        CP_COMMIT();
    };

    #pragma unroll
    for (int c = 0; c < 4; c++) {
        int id = tid * 4 + c;
        int row = id >> 3, ch = id & 7;
        CP_ASYNC16(sb + (uint32_t)(FA_Q + row * STRF + ch * 16),
                   qg + ((size_t)bb * Ssz + i0 + row) * Dsz + hh * DHsz + ch * 8);
    }
    #pragma unroll
    for (int c = 0; c < 4; c++) {
        int id = tid * 4 + c;
        int row = id >> 3, ch = id & 7;
        CP_ASYNC16(sb + (uint32_t)(FA_C2P + row * 128 + ch * 16),
                   c2pz + (size_t)(i0 + row) * NPOS + ch * 8);
    }
    CP_COMMIT();
    loadKV(0, 0);

    CP_WAIT1();
    __syncthreads();

    const int lq = lane >> 3, lr = lane & 7;
    const int aoffF = ((lq & 1) * 8 + lr) * STRF + (lq >> 1) * 16;
    const int boffF = ((lq >> 1) * 8 + lr) * STRF + (lq & 1) * 16;
    // trans-V: matrices (n0-7,k0-7),(n0-7,k8-15),(n8-15,k0-7),(n8-15,k8-15)
    // stored rows = k (j), cols = n (d): row = (lq&1)*8+lr, col-off = (lq>>1)*16B
    const int boffT = ((lq & 1) * 8 + lr) * STRF + (lq >> 1) * 16;

    uint32_t qf[4][4];
    #pragma unroll
    for (int kc = 0; kc < 4; kc++)
        ldsm_x4(qf[kc], sb + (uint32_t)(FA_Q + (w * 16) * STRF + aoffF + kc * 32));

    const __half* c2ps = (const __half*)(smc + FA_C2P);
    const int crow0 = (w * 16 + g) * 64;
    const int crow1 = crow0 + 8 * 64;

    float acc_o[8][4] = {};
    float m_r[2] = {-1e30f, -1e30f};
    float l_r[2] = {0.f, 0.f};
    const int mg0 = i0 + w * 16 + g;

    for (int jt = 0; jt < 16; jt++) {
        const int buf = jt & 1;
        const int j0 = jt * 64;
        CP_WAIT0();
        __syncthreads();
        if (jt < 15) loadKV(jt + 1, buf ^ 1);

        float acc_s[8][4] = {};
        #pragma unroll
        for (int kc = 0; kc < 4; kc++) {
            #pragma unroll
            for (int ip = 0; ip < 4; ip++) {
                uint32_t bf[4];
                ldsm_x4(bf, sb + (uint32_t)(FA_K(buf) + (ip * 16) * STRF + boffF + kc * 32));
                mma_f16(acc_s[ip * 2],     qf[kc], &bf[0]);
                mma_f16(acc_s[ip * 2 + 1], qf[kc], &bf[2]);
            }
        }

        const __half* p2cs = (const __half*)(smc + FA_P2C(buf));
        __half2 s01[8], s23[8];
        __half2 mx0h = __floats2half2_rn(-60000.f, -60000.f);
        __half2 mx1h = mx0h;
        #pragma unroll
        for (int in = 0; in < 8; in++) {
            int nloc = in * 8 + tg * 2;
            int dbase = mg0 - j0 - nloc + (Ssz - 1);
            int i00 = lut_s[dbase];
            int i01 = lut_s[dbase - 1];
            int i10 = lut_s[dbase + 8];
            int i11 = lut_s[dbase + 7];
            __half2 b01 = __hadd2(__halves2half2(c2ps[crow0 + i00], c2ps[crow0 + i01]),
                                  __halves2half2(p2cs[nloc * 64 + i00], p2cs[(nloc + 1) * 64 + i01]));
            __half2 b23 = __hadd2(__halves2half2(c2ps[crow1 + i10], c2ps[crow1 + i11]),
                                  __halves2half2(p2cs[nloc * 64 + i10], p2cs[(nloc + 1) * 64 + i11]));
            __half2 v01 = __hadd2(__floats2half2_rn(acc_s[in][0] * SCALE2F,
                                                    acc_s[in][1] * SCALE2F), b01);
            __half2 v23 = __hadd2(__floats2half2_rn(acc_s[in][2] * SCALE2F,
                                                    acc_s[in][3] * SCALE2F), b23);
            s01[in] = v01; s23[in] = v23;
            mx0h = __hmax2(mx0h, v01);
            mx1h = __hmax2(mx1h, v23);
        }
        float mx0 = fmaxf(__low2float(mx0h), __high2float(mx0h));
        float mx1 = fmaxf(__low2float(mx1h), __high2float(mx1h));
        mx0 = fmaxf(mx0, __shfl_xor_sync(0xffffffffu, mx0, 1));
        mx0 = fmaxf(mx0, __shfl_xor_sync(0xffffffffu, mx0, 2));
        mx1 = fmaxf(mx1, __shfl_xor_sync(0xffffffffu, mx1, 1));
        mx1 = fmaxf(mx1, __shfl_xor_sync(0xffffffffu, mx1, 2));
        float mn0 = fmaxf(m_r[0], mx0), mn1 = fmaxf(m_r[1], mx1);
        float al0 = exp2f(m_r[0] - mn0), al1 = exp2f(m_r[1] - mn1);
        __half2 mn0h = __float2half2_rn(mn0);
        __half2 mn1h = __float2half2_rn(mn1);
        float s0 = 0.f, s1 = 0.f;
        uint32_t u01[8], u23[8];
        #pragma unroll
        for (int in = 0; in < 8; in++) {
            __half2 e01 = h2exp2(__hsub2(s01[in], mn0h));
            __half2 e23 = h2exp2(__hsub2(s23[in], mn1h));
            u01[in] = *(uint32_t*)&e01;
            u23[in] = *(uint32_t*)&e23;
            float2 f01 = __half22float2(e01);
            float2 f23 = __half22float2(e23);
            s0 += f01.x + f01.y; s1 += f23.x + f23.y;
        }
        l_r[0] = l_r[0] * al0 + s0;
        l_r[1] = l_r[1] * al1 + s1;
        m_r[0] = mn0; m_r[1] = mn1;
        #pragma unroll
        for (int nf = 0; nf < 8; nf++) {
            acc_o[nf][0] *= al0; acc_o[nf][1] *= al0;
            acc_o[nf][2] *= al1; acc_o[nf][3] *= al1;
        }

        // ---- O += P V : V via ldmatrix.trans from [j][d] layout ----
        #pragma unroll
        for (int kc2 = 0; kc2 < 4; kc2++) {
            uint32_t af[4];
            af[0] = u01[kc2 * 2];
            af[1] = u23[kc2 * 2];
            af[2] = u01[kc2 * 2 + 1];
            af[3] = u23[kc2 * 2 + 1];
            #pragma unroll
            for (int ip = 0; ip < 4; ip++) {
                uint32_t bf[4];
                ldsm_x4_trans(bf, sb + (uint32_t)(FA_V(buf) + (kc2 * 16) * STRF + boffT + ip * 32));
                mma_f16(acc_o[ip * 2],     af, &bf[0]);
                mma_f16(acc_o[ip * 2 + 1], af, &bf[2]);
            }
        }
    }

    float l0 = l_r[0];
    l0 += __shfl_xor_sync(0xffffffffu, l0, 1);
    l0 += __shfl_xor_sync(0xffffffffu, l0, 2);
    float l1 = l_r[1];
    l1 += __shfl_xor_sync(0xffffffffu, l1, 1);
    l1 += __shfl_xor_sync(0xffffffffu, l1, 2);
    float inv0 = 1.0f / l0, inv1 = 1.0f / l1;
    __half* c0 = ctx + ((size_t)bb * Ssz + mg0)     * Dsz + hh * DHsz;
    __half* c1 = ctx + ((size_t)bb * Ssz + mg0 + 8) * Dsz + hh * DHsz;
    #pragma unroll
    for (int nf = 0; nf < 8; nf++) {
        int col = nf * 8 + tg * 2;
        *(__half2*)&c0[col] = __floats2half2_rn(acc_o[nf][0] * inv0, acc_o[nf][1] * inv0);
        *(__half2*)&c1[col] = __floats2half2_rn(acc_o[nf][2] * inv1, acc_o[nf][3] * inv1);
    }
}

// =============================== launch ========================================
extern "C" void kernel_launch(void* const* d_in, const int* in_sizes, int n_in,
                              void* d_out, int out_size) {
    const float* x      = (const float*)d_in[0];
    const float* ln1g   = (const float*)d_in[1];
    const float* ln1b   = (const float*)d_in[2];
    const float* dww    = (const float*)d_in[3];
    const float* dwb    = (const float*)d_in[4];
    const float* pww    = (const float*)d_in[5];
    const float* pwb    = (const float*)d_in[6];
    const float* ln2g   = (const float*)d_in[7];
    const float* ln2b   = (const float*)d_in[8];
    const float* qw     = (const float*)d_in[9];
    const float* qb     = (const float*)d_in[10];
    const float* kw     = (const float*)d_in[11];
    const float* kb     = (const float*)d_in[12];
    const float* vw     = (const float*)d_in[13];
    const float* vb     = (const float*)d_in[14];
    const float* ow     = (const float*)d_in[15];
    const float* ob     = (const float*)d_in[16];
    const float* relemb = (const float*)d_in[17];
    const float* ln3g   = (const float*)d_in[18];
    const float* ln3b   = (const float*)d_in[19];
    const float* w1     = (const float*)d_in[20];
    const float* b1     = (const float*)d_in[21];
    const float* w2     = (const float*)d_in[22];
    const float* b2     = (const float*)d_in[23];
    float* out = (float*)d_out;

    float *x1, *x2; int* lut;
    __half *c2p, *p2c;
    __half *xnh, *convh, *qh, *kh, *vh, *ctxh, *ffh, *poskh, *posqh;
    __half *pwwh, *qwh, *kwh, *vwh, *owh, *w1h, *w2h;
    cudaGetSymbolAddress((void**)&x1,    g_x1);
    cudaGetSymbolAddress((void**)&x2,    g_x2);
    cudaGetSymbolAddress((void**)&c2p,   g_c2p);
    cudaGetSymbolAddress((void**)&p2c,   g_p2c);
    cudaGetSymbolAddress((void**)&lut,   g_lut);
    cudaGetSymbolAddress((void**)&xnh,   g_xnh);
    cudaGetSymbolAddress((void**)&convh, g_convh);
    cudaGetSymbolAddress((void**)&qh,    g_qh);
    cudaGetSymbolAddress((void**)&kh,    g_kh);
    cudaGetSymbolAddress((void**)&vh,    g_vh);
    cudaGetSymbolAddress((void**)&ctxh,  g_ctxh);
    cudaGetSymbolAddress((void**)&ffh,   g_ffh);
    cudaGetSymbolAddress((void**)&poskh, g_poskh);
    cudaGetSymbolAddress((void**)&posqh, g_posqh);
    cudaGetSymbolAddress((void**)&pwwh,  g_pwwh);
    cudaGetSymbolAddress((void**)&qwh,   g_qwh);
    cudaGetSymbolAddress((void**)&kwh,   g_kwh);
    cudaGetSymbolAddress((void**)&vwh,   g_vwh);
    cudaGetSymbolAddress((void**)&owh,   g_owh);
    cudaGetSymbolAddress((void**)&w1h,   g_w1h);
    cudaGetSymbolAddress((void**)&w2h,   g_w2h);

    static int attr_set = 0;
    if (!attr_set) {
        cudaFuncSetAttribute(flash_attn_kernel,
                             cudaFuncAttributeMaxDynamicSharedMemorySize, FA_SMEM);
        cudaFuncSetAttribute(gemm_mma_kernel<128,2,0,0>,
                             cudaFuncAttributeMaxDynamicSharedMemorySize, GEMM_SMEMH(128));
        cudaFuncSetAttribute(gemm_mma_kernel<128,1,4,1>,
                             cudaFuncAttributeMaxDynamicSharedMemorySize, GEMM_SMEMH(128));
        cudaFuncSetAttribute(gemm_mma_kernel<128,3,0,1>,
                             cudaFuncAttributeMaxDynamicSharedMemorySize, GEMM_SMEMH(128));
        cudaFuncSetAttribute(gemm_pos_kernel,
                             cudaFuncAttributeMaxDynamicSharedMemorySize, GEMM_SMEMH(64));
        attr_set = 1;
    }

    setup_kernel<<<dim3(256, 1, 8), 256>>>(pww, qw, kw, vw, ow, w1, w2,
                                           pwwh, qwh, kwh, vwh, owh, w1h, w2h, lut);

    // ---- conv block (fused LN1 + dwconv + silu) ----
    ln_dwconv_silu_kernel<<<dim3(Ssz/4, Bsz), 256>>>(x, ln1g, ln1b, dww, dwb, convh);
    gemm_mma_kernel<128,2,0,0><<<dim3(Dsz/128, NROWS/128, 1), 256, GEMM_SMEMH(128)>>>(
        convh, Dsz, pwwh, Dsz, pwb, x, x1, Dsz, Dsz,
        nullptr, nullptr, nullptr, nullptr, nullptr, nullptr);

    // ---- attention block ----
    layernorm_kernel<<<NROWS/16, 256>>>(x1, ln2g, ln2b, xnh);
    gemm_mma_kernel<128,1,4,1><<<dim3(Dsz/128, NROWS/128, 3), 256, GEMM_SMEMH(128)>>>(
        xnh, Dsz, qwh, Dsz, qb, nullptr, qh, Dsz, Dsz,
        kwh, vwh, kb, vb, kh, vh);

    gemm_tn_small_kernel<<<dim3(Dsz/64, 1, 2), 256>>>(
        relemb, Dsz, kw, Dsz, kb, poskh, qw, qb, posqh, Dsz, Dsz);

    gemm_pos_kernel<<<dim3(1, Ssz/128, 2*Bsz*Hsz), 256, GEMM_SMEMH(64)>>>(
        qh, poskh, c2p, kh, posqh, p2c);

    flash_attn_kernel<<<dim3(Ssz/128, 1, Bsz*Hsz), 256, FA_SMEM>>>(
        qh, kh, vh, c2p, p2c, lut, ctxh);

    gemm_mma_kernel<128,2,0,0><<<dim3(Dsz/128, NROWS/128, 1), 256, GEMM_SMEMH(128)>>>(
        ctxh, Dsz, owh, Dsz, ob, x1, x2, Dsz, Dsz,
        nullptr, nullptr, nullptr, nullptr, nullptr, nullptr);

    // ---- FFN block ----
    layernorm_kernel<<<NROWS/16, 256>>>(x2, ln3g, ln3b, xnh);
    gemm_mma_kernel<128,3,0,1><<<dim3(FFsz/128, NROWS/128, 1), 256, GEMM_SMEMH(128)>>>(
        xnh, Dsz, w1h, Dsz, b1, nullptr, ffh, FFsz, Dsz,
        nullptr, nullptr, nullptr, nullptr, nullptr, nullptr);
    gemm_mma_kernel<128,2,0,0><<<dim3(Dsz/128, NROWS/128, 1), 256, GEMM_SMEMH(128)>>>(
        ffh, FFsz, w2h, FFsz, b2, x2, out, Dsz, FFsz,
        nullptr, nullptr, nullptr, nullptr, nullptr, nullptr);
}